// round 1
// baseline (speedup 1.0000x reference)
#include <cuda_runtime.h>
#include <math.h>

// ---------------- problem constants ----------------
#define DD     1024
#define LL     2048
#define BB     4
#define NH     16
#define DH     64
#define SSEL   5
#define WWIN   128
#define BKBLK  32
#define NB     64          // L / BK
#define NTOK   8192        // B*L
#define MKV    2560        // B*S*W
#define DFFN   4096

// ---------------- scratch (device globals; no allocations allowed) --------
__device__ float g_h   [NTOK * DD];
__device__ float g_kv  [MKV  * DD];
__device__ float g_q   [NTOK * DD];
__device__ float g_k   [MKV  * DD];
__device__ float g_v   [MKV  * DD];
__device__ float g_att [NTOK * DD];
__device__ float g_x2  [NTOK * DD];
__device__ float g_h2  [NTOK * DD];
__device__ float g_ff  [NTOK * DFFN];
__device__ float g_logits[BB * NB];
__device__ int   g_start [SSEL * BB];
__device__ float g_scale [SSEL * BB];

// ---------------- LayerNorm: one block per token ----------------
__global__ void ln_kernel(const float* __restrict__ x,
                          const float* __restrict__ gam,
                          const float* __restrict__ bet,
                          float* __restrict__ out) {
    __shared__ float red[8];
    const int row = blockIdx.x;
    const int t = threadIdx.x;  // 256 threads, each handles 4 floats
    const float4* xr = reinterpret_cast<const float4*>(x) + (size_t)row * (DD / 4);
    float4 v = xr[t];

    float s = v.x + v.y + v.z + v.w;
    #pragma unroll
    for (int o = 16; o; o >>= 1) s += __shfl_down_sync(0xffffffffu, s, o);
    if ((t & 31) == 0) red[t >> 5] = s;
    __syncthreads();
    float tot = red[0] + red[1] + red[2] + red[3] + red[4] + red[5] + red[6] + red[7];
    const float mean = tot * (1.0f / DD);
    __syncthreads();

    float dx = v.x - mean, dy = v.y - mean, dz = v.z - mean, dw = v.w - mean;
    float sq = dx * dx + dy * dy + dz * dz + dw * dw;
    #pragma unroll
    for (int o = 16; o; o >>= 1) sq += __shfl_down_sync(0xffffffffu, sq, o);
    if ((t & 31) == 0) red[t >> 5] = sq;
    __syncthreads();
    float var = (red[0] + red[1] + red[2] + red[3] + red[4] + red[5] + red[6] + red[7]) * (1.0f / DD);
    const float r = rsqrtf(var + 1e-5f);

    const float4 gg = reinterpret_cast<const float4*>(gam)[t];
    const float4 bb = reinterpret_cast<const float4*>(bet)[t];
    float4 o4;
    o4.x = dx * r * gg.x + bb.x;
    o4.y = dy * r * gg.y + bb.y;
    o4.z = dz * r * gg.z + bb.z;
    o4.w = dw * r * gg.w + bb.w;
    reinterpret_cast<float4*>(out)[(size_t)row * (DD / 4) + t] = o4;
}

// ---------------- block saliency logits: one block per (b,nb) -------------
__global__ void logits_kernel(const float* __restrict__ h,
                              const float* __restrict__ w_sal,
                              const float* __restrict__ b_sal,
                              float* __restrict__ logits) {
    __shared__ float red[8];
    const int t = threadIdx.x;  // 256
    const float4 w = reinterpret_cast<const float4*>(w_sal)[t];
    const float* base = h + (size_t)blockIdx.x * BKBLK * DD;  // (b*64+nb)*32 tokens
    float acc = 0.0f;
    for (int tok = 0; tok < BKBLK; tok++) {
        float4 hv = reinterpret_cast<const float4*>(base + (size_t)tok * DD)[t];
        acc += hv.x * w.x + hv.y * w.y + hv.z * w.z + hv.w * w.w;
    }
    #pragma unroll
    for (int o = 16; o; o >>= 1) acc += __shfl_down_sync(0xffffffffu, acc, o);
    if ((t & 31) == 0) red[t >> 5] = acc;
    __syncthreads();
    if (t == 0) {
        float tot = red[0] + red[1] + red[2] + red[3] + red[4] + red[5] + red[6] + red[7];
        logits[blockIdx.x] = tot * (1.0f / BKBLK) + b_sal[0];
    }
}

// ---------------- gumbel selection: one warp block per (s,b) --------------
__global__ void select_kernel(const float* __restrict__ logits,
                              const float* __restrict__ gu,
                              int* __restrict__ starts,
                              float* __restrict__ scales) {
    const int sb = blockIdx.x;           // s*B + b
    const int b = sb % BB;
    const int lane = threadIdx.x;        // 32

    float u0 = gu[sb * NB + lane];
    float u1 = gu[sb * NB + 32 + lane];
    float g0 = -logf(-logf(u0 + 1e-9f) + 1e-9f);
    float g1 = -logf(-logf(u1 + 1e-9f) + 1e-9f);
    float p0 = logits[b * NB + lane] + g0;       // TAU = 1
    float p1 = logits[b * NB + 32 + lane] + g1;

    float m = p0; int idx = lane;
    if (p1 > m) { m = p1; idx = lane + 32; }
    #pragma unroll
    for (int o = 16; o; o >>= 1) {
        float om = __shfl_down_sync(0xffffffffu, m, o);
        int   oi = __shfl_down_sync(0xffffffffu, idx, o);
        if (om > m || (om == m && oi < idx)) { m = om; idx = oi; }
    }
    m   = __shfl_sync(0xffffffffu, m, 0);
    idx = __shfl_sync(0xffffffffu, idx, 0);

    float se = expf(p0 - m) + expf(p1 - m);
    #pragma unroll
    for (int o = 16; o; o >>= 1) se += __shfl_down_sync(0xffffffffu, se, o);
    if (lane == 0) {
        float w = 1.0f / se;               // p at argmax
        float scale = (1.0f + w) - w;      // forward value of straight-through scale
        int start = idx * BKBLK + BKBLK / 2 - WWIN / 2;
        if (start < 0) start = 0;
        if (start > LL - WWIN) start = LL - WWIN;
        starts[sb] = start;
        scales[sb] = scale;
    }
}

// ---------------- window gather into kv ----------------
__global__ void gather_kernel(const float* __restrict__ h,
                              const int* __restrict__ starts,
                              const float* __restrict__ scales,
                              float* __restrict__ kv) {
    const int row = blockIdx.x;          // b*640 + s*128 + w
    const int b = row / (SSEL * WWIN);
    const int r = row % (SSEL * WWIN);
    const int s = r / WWIN;
    const int w = r % WWIN;
    const int sb = s * BB + b;
    const int src = b * LL + starts[sb] + w;
    const float sc = scales[sb];
    const int t = threadIdx.x;           // 256
    float4 v = reinterpret_cast<const float4*>(h)[(size_t)src * (DD / 4) + t];
    v.x *= sc; v.y *= sc; v.z *= sc; v.w *= sc;
    reinterpret_cast<float4*>(kv)[(size_t)row * (DD / 4) + t] = v;
}

// ---------------- tiled fp32 GEMM ----------------
// C[M,N] = A[M,K] @ op(B) + bias (+gelu) (+res)
// BT=true:  B is [N,K] row-major (C = A B^T)
// BT=false: B is [K,N] row-major (C = A B)
template<bool BT, bool GELU, bool RES>
__global__ void gemm_kernel(const float* __restrict__ A,
                            const float* __restrict__ B,
                            const float* __restrict__ bias,
                            const float* __restrict__ res,
                            float* __restrict__ C,
                            int M, int N, int K) {
    __shared__ float As[16][68];
    __shared__ float Bs[16][68];

    const int tid = threadIdx.x;         // 256
    const int tx = tid & 15, ty = tid >> 4;
    const int m0 = blockIdx.y * 64, n0 = blockIdx.x * 64;

    float acc[4][4];
    #pragma unroll
    for (int i = 0; i < 4; i++)
        #pragma unroll
        for (int j = 0; j < 4; j++) acc[i][j] = 0.0f;

    const int am = tid >> 2, ak = (tid & 3) * 4;   // A loader mapping
    const int bk_nn = tid >> 4, bn_nn = (tid & 15) * 4;

    for (int k0 = 0; k0 < K; k0 += 16) {
        // load A tile (64x16), stored transposed As[k][m]
        {
            float4 a = *reinterpret_cast<const float4*>(A + (size_t)(m0 + am) * K + k0 + ak);
            As[ak + 0][am] = a.x; As[ak + 1][am] = a.y;
            As[ak + 2][am] = a.z; As[ak + 3][am] = a.w;
        }
        // load B tile, stored Bs[k][n]
        if (BT) {
            float4 bv = *reinterpret_cast<const float4*>(B + (size_t)(n0 + am) * K + k0 + ak);
            Bs[ak + 0][am] = bv.x; Bs[ak + 1][am] = bv.y;
            Bs[ak + 2][am] = bv.z; Bs[ak + 3][am] = bv.w;
        } else {
            float4 bv = *reinterpret_cast<const float4*>(B + (size_t)(k0 + bk_nn) * N + n0 + bn_nn);
            *reinterpret_cast<float4*>(&Bs[bk_nn][bn_nn]) = bv;
        }
        __syncthreads();

        #pragma unroll
        for (int kk = 0; kk < 16; kk++) {
            float4 a = *reinterpret_cast<const float4*>(&As[kk][ty * 4]);
            float4 bq = *reinterpret_cast<const float4*>(&Bs[kk][tx * 4]);
            acc[0][0] += a.x * bq.x; acc[0][1] += a.x * bq.y; acc[0][2] += a.x * bq.z; acc[0][3] += a.x * bq.w;
            acc[1][0] += a.y * bq.x; acc[1][1] += a.y * bq.y; acc[1][2] += a.y * bq.z; acc[1][3] += a.y * bq.w;
            acc[2][0] += a.z * bq.x; acc[2][1] += a.z * bq.y; acc[2][2] += a.z * bq.z; acc[2][3] += a.z * bq.w;
            acc[3][0] += a.w * bq.x; acc[3][1] += a.w * bq.y; acc[3][2] += a.w * bq.z; acc[3][3] += a.w * bq.w;
        }
        __syncthreads();
    }

    // epilogue
    const float4 bia = *reinterpret_cast<const float4*>(bias + n0 + tx * 4);
    #pragma unroll
    for (int i = 0; i < 4; i++) {
        const int m = m0 + ty * 4 + i;
        float4 o;
        o.x = acc[i][0] + bia.x; o.y = acc[i][1] + bia.y;
        o.z = acc[i][2] + bia.z; o.w = acc[i][3] + bia.w;
        if (GELU) {
            #pragma unroll
            for (int j = 0; j < 4; j++) {
                float v = (&o.x)[j];
                float u = 0.7978845608028654f * (v + 0.044715f * v * v * v);
                (&o.x)[j] = 0.5f * v * (1.0f + tanhf(u));
            }
        }
        if (RES) {
            float4 r = *reinterpret_cast<const float4*>(res + (size_t)m * N + n0 + tx * 4);
            o.x += r.x; o.y += r.y; o.z += r.z; o.w += r.w;
        }
        *reinterpret_cast<float4*>(C + (size_t)m * N + n0 + tx * 4) = o;
    }
}

// ---------------- attention: one block = 64 queries of one (b,head) -------
__global__ void attn_kernel(const float* __restrict__ q,
                            const float* __restrict__ k,
                            const float* __restrict__ v,
                            float* __restrict__ o) {
    __shared__ float Ks[64][64];
    __shared__ float Vs[64][64];
    const int bh = blockIdx.y;
    const int b = bh >> 4, hh = bh & 15;
    const int t = threadIdx.x;          // 64 threads, one query each
    const int l = blockIdx.x * 64 + t;

    const float* qp = q + ((size_t)(b * LL + l) * DD) + hh * DH;
    float qr[DH];
    #pragma unroll
    for (int d = 0; d < DH; d += 4) {
        float4 x = *reinterpret_cast<const float4*>(qp + d);
        qr[d] = x.x * 0.125f; qr[d + 1] = x.y * 0.125f;
        qr[d + 2] = x.z * 0.125f; qr[d + 3] = x.w * 0.125f;
    }

    float m = -1e30f, lsum = 0.0f;
    float acc[DH];
    #pragma unroll
    for (int d = 0; d < DH; d++) acc[d] = 0.0f;

    const float* kbase = k + ((size_t)b * (SSEL * WWIN)) * DD + hh * DH;
    const float* vbase = v + ((size_t)b * (SSEL * WWIN)) * DD + hh * DH;
    const int tr = t >> 4, tc = (t & 15) * 4;

    for (int kt = 0; kt < (SSEL * WWIN) / 64; kt++) {
        #pragma unroll
        for (int r4 = 0; r4 < 16; r4++) {
            const int row = r4 * 4 + tr;
            const size_t gm = (size_t)(kt * 64 + row) * DD;
            *reinterpret_cast<float4*>(&Ks[row][tc]) = *reinterpret_cast<const float4*>(kbase + gm + tc);
            *reinterpret_cast<float4*>(&Vs[row][tc]) = *reinterpret_cast<const float4*>(vbase + gm + tc);
        }
        __syncthreads();
        #pragma unroll 1
        for (int j = 0; j < 64; j++) {
            float s = 0.0f;
            #pragma unroll
            for (int d = 0; d < DH; d += 4) {
                float4 kk4 = *reinterpret_cast<const float4*>(&Ks[j][d]);
                s += qr[d] * kk4.x + qr[d + 1] * kk4.y + qr[d + 2] * kk4.z + qr[d + 3] * kk4.w;
            }
            if (s <= m) {
                float p = __expf(s - m);
                lsum += p;
                #pragma unroll
                for (int d = 0; d < DH; d++) acc[d] += p * Vs[j][d];
            } else {
                float c = __expf(m - s);
                lsum = lsum * c + 1.0f;
                #pragma unroll
                for (int d = 0; d < DH; d++) acc[d] = acc[d] * c + Vs[j][d];
                m = s;
            }
        }
        __syncthreads();
    }

    const float inv = 1.0f / lsum;
    float* op = o + ((size_t)(b * LL + l) * DD) + hh * DH;
    #pragma unroll
    for (int d = 0; d < DH; d += 4) {
        float4 x;
        x.x = acc[d] * inv; x.y = acc[d + 1] * inv;
        x.z = acc[d + 2] * inv; x.w = acc[d + 3] * inv;
        *reinterpret_cast<float4*>(op + d) = x;
    }
}

// ---------------- driver ----------------
extern "C" void kernel_launch(void* const* d_in, const int* in_sizes, int n_in,
                              void* d_out, int out_size) {
    const float* x        = (const float*)d_in[0];
    const float* gumbel_u = (const float*)d_in[1];
    const float* ln1_g    = (const float*)d_in[2];
    const float* ln1_b    = (const float*)d_in[3];
    const float* ln2_g    = (const float*)d_in[4];
    const float* ln2_b    = (const float*)d_in[5];
    const float* w_sal    = (const float*)d_in[6];
    const float* b_sal    = (const float*)d_in[7];
    const float* ipw      = (const float*)d_in[8];
    const float* ipb      = (const float*)d_in[9];
    const float* opw      = (const float*)d_in[10];
    const float* opb      = (const float*)d_in[11];
    const float* w_fc     = (const float*)d_in[12];
    const float* b_fc     = (const float*)d_in[13];
    const float* w_proj   = (const float*)d_in[14];
    const float* b_proj   = (const float*)d_in[15];
    float* out = (float*)d_out;

    void* p;
    cudaGetSymbolAddress(&p, g_h);      float* h    = (float*)p;
    cudaGetSymbolAddress(&p, g_kv);     float* kv   = (float*)p;
    cudaGetSymbolAddress(&p, g_q);      float* qb   = (float*)p;
    cudaGetSymbolAddress(&p, g_k);      float* kb   = (float*)p;
    cudaGetSymbolAddress(&p, g_v);      float* vb   = (float*)p;
    cudaGetSymbolAddress(&p, g_att);    float* att  = (float*)p;
    cudaGetSymbolAddress(&p, g_x2);     float* x2   = (float*)p;
    cudaGetSymbolAddress(&p, g_h2);     float* h2   = (float*)p;
    cudaGetSymbolAddress(&p, g_ff);     float* ff   = (float*)p;
    cudaGetSymbolAddress(&p, g_logits); float* logi = (float*)p;
    cudaGetSymbolAddress(&p, g_start);  int*   st   = (int*)p;
    cudaGetSymbolAddress(&p, g_scale);  float* sc   = (float*)p;

    // 1. LN1
    ln_kernel<<<NTOK, 256>>>(x, ln1_g, ln1_b, h);
    // 2. saliency logits
    logits_kernel<<<BB * NB, 256>>>(h, w_sal, b_sal, logi);
    // 3. gumbel window selection
    select_kernel<<<SSEL * BB, 32>>>(logi, gumbel_u, st, sc);
    // 4. gather windows -> kv
    gather_kernel<<<MKV, 256>>>(h, st, sc, kv);
    // 5. Q/K/V projections (NT)
    gemm_kernel<true, false, false><<<dim3(DD / 64, NTOK / 64), 256>>>(
        h, ipw, ipb, nullptr, qb, NTOK, DD, DD);
    gemm_kernel<true, false, false><<<dim3(DD / 64, MKV / 64), 256>>>(
        kv, ipw + (size_t)DD * DD, ipb + DD, nullptr, kb, MKV, DD, DD);
    gemm_kernel<true, false, false><<<dim3(DD / 64, MKV / 64), 256>>>(
        kv, ipw + 2 * (size_t)DD * DD, ipb + 2 * DD, nullptr, vb, MKV, DD, DD);
    // 6. attention
    attn_kernel<<<dim3(LL / 64, BB * NH), 64>>>(qb, kb, vb, att);
    // 7. out proj + residual
    gemm_kernel<true, false, true><<<dim3(DD / 64, NTOK / 64), 256>>>(
        att, opw, opb, x, x2, NTOK, DD, DD);
    // 8. LN2
    ln_kernel<<<NTOK, 256>>>(x2, ln2_g, ln2_b, h2);
    // 9. FFN up + gelu (NN)
    gemm_kernel<false, true, false><<<dim3(DFFN / 64, NTOK / 64), 256>>>(
        h2, w_fc, b_fc, nullptr, ff, NTOK, DFFN, DD);
    // 10. FFN down + residual (NN) -> out
    gemm_kernel<false, false, true><<<dim3(DD / 64, NTOK / 64), 256>>>(
        ff, w_proj, b_proj, x2, out, NTOK, DD, DFFN);
}

// round 2
// speedup vs baseline: 2.7310x; 2.7310x over previous
#include <cuda_runtime.h>
#include <math.h>
#include <stdint.h>

// ---------------- problem constants ----------------
#define DD     1024
#define LL     2048
#define BB     4
#define NH     16
#define DH     64
#define SSEL   5
#define WWIN   128
#define BKBLK  32
#define NB     64          // L / BK
#define NTOK   8192        // B*L
#define MKV    2560        // B*S*W
#define DFFN   4096

// ---------------- scratch (device globals; no allocations allowed) --------
__device__ float g_h   [NTOK * DD];
__device__ float g_kv  [MKV  * DD];
__device__ float g_q   [NTOK * DD];
__device__ float g_k   [MKV  * DD];
__device__ float g_v   [MKV  * DD];
__device__ float g_att [NTOK * DD];
__device__ float g_x2  [NTOK * DD];
__device__ float g_h2  [NTOK * DD];
__device__ float g_ff  [NTOK * DFFN];
__device__ float g_logits[BB * NB];
__device__ int   g_start [SSEL * BB];
__device__ float g_scale [SSEL * BB];

// ---------------- LayerNorm: one block per token ----------------
__global__ void ln_kernel(const float* __restrict__ x,
                          const float* __restrict__ gam,
                          const float* __restrict__ bet,
                          float* __restrict__ out) {
    __shared__ float red[8];
    const int row = blockIdx.x;
    const int t = threadIdx.x;  // 256 threads, each handles 4 floats
    const float4* xr = reinterpret_cast<const float4*>(x) + (size_t)row * (DD / 4);
    float4 v = xr[t];

    float s = v.x + v.y + v.z + v.w;
    #pragma unroll
    for (int o = 16; o; o >>= 1) s += __shfl_down_sync(0xffffffffu, s, o);
    if ((t & 31) == 0) red[t >> 5] = s;
    __syncthreads();
    float tot = red[0] + red[1] + red[2] + red[3] + red[4] + red[5] + red[6] + red[7];
    const float mean = tot * (1.0f / DD);
    __syncthreads();

    float dx = v.x - mean, dy = v.y - mean, dz = v.z - mean, dw = v.w - mean;
    float sq = dx * dx + dy * dy + dz * dz + dw * dw;
    #pragma unroll
    for (int o = 16; o; o >>= 1) sq += __shfl_down_sync(0xffffffffu, sq, o);
    if ((t & 31) == 0) red[t >> 5] = sq;
    __syncthreads();
    float var = (red[0] + red[1] + red[2] + red[3] + red[4] + red[5] + red[6] + red[7]) * (1.0f / DD);
    const float r = rsqrtf(var + 1e-5f);

    const float4 gg = reinterpret_cast<const float4*>(gam)[t];
    const float4 bb = reinterpret_cast<const float4*>(bet)[t];
    float4 o4;
    o4.x = dx * r * gg.x + bb.x;
    o4.y = dy * r * gg.y + bb.y;
    o4.z = dz * r * gg.z + bb.z;
    o4.w = dw * r * gg.w + bb.w;
    reinterpret_cast<float4*>(out)[(size_t)row * (DD / 4) + t] = o4;
}

// ---------------- block saliency logits: one block per (b,nb) -------------
__global__ void logits_kernel(const float* __restrict__ h,
                              const float* __restrict__ w_sal,
                              const float* __restrict__ b_sal,
                              float* __restrict__ logits) {
    __shared__ float red[8];
    const int t = threadIdx.x;  // 256
    const float4 w = reinterpret_cast<const float4*>(w_sal)[t];
    const float* base = h + (size_t)blockIdx.x * BKBLK * DD;
    float acc = 0.0f;
    for (int tok = 0; tok < BKBLK; tok++) {
        float4 hv = reinterpret_cast<const float4*>(base + (size_t)tok * DD)[t];
        acc += hv.x * w.x + hv.y * w.y + hv.z * w.z + hv.w * w.w;
    }
    #pragma unroll
    for (int o = 16; o; o >>= 1) acc += __shfl_down_sync(0xffffffffu, acc, o);
    if ((t & 31) == 0) red[t >> 5] = acc;
    __syncthreads();
    if (t == 0) {
        float tot = red[0] + red[1] + red[2] + red[3] + red[4] + red[5] + red[6] + red[7];
        logits[blockIdx.x] = tot * (1.0f / BKBLK) + b_sal[0];
    }
}

// ---------------- gumbel selection: one warp block per (s,b) --------------
__global__ void select_kernel(const float* __restrict__ logits,
                              const float* __restrict__ gu,
                              int* __restrict__ starts,
                              float* __restrict__ scales) {
    const int sb = blockIdx.x;           // s*B + b
    const int b = sb % BB;
    const int lane = threadIdx.x;        // 32

    float u0 = gu[sb * NB + lane];
    float u1 = gu[sb * NB + 32 + lane];
    float g0 = -logf(-logf(u0 + 1e-9f) + 1e-9f);
    float g1 = -logf(-logf(u1 + 1e-9f) + 1e-9f);
    float p0 = logits[b * NB + lane] + g0;       // TAU = 1
    float p1 = logits[b * NB + 32 + lane] + g1;

    float m = p0; int idx = lane;
    if (p1 > m) { m = p1; idx = lane + 32; }
    #pragma unroll
    for (int o = 16; o; o >>= 1) {
        float om = __shfl_down_sync(0xffffffffu, m, o);
        int   oi = __shfl_down_sync(0xffffffffu, idx, o);
        if (om > m || (om == m && oi < idx)) { m = om; idx = oi; }
    }
    m   = __shfl_sync(0xffffffffu, m, 0);
    idx = __shfl_sync(0xffffffffu, idx, 0);

    float se = expf(p0 - m) + expf(p1 - m);
    #pragma unroll
    for (int o = 16; o; o >>= 1) se += __shfl_down_sync(0xffffffffu, se, o);
    if (lane == 0) {
        float w = 1.0f / se;
        float scale = (1.0f + w) - w;
        int start = idx * BKBLK + BKBLK / 2 - WWIN / 2;
        if (start < 0) start = 0;
        if (start > LL - WWIN) start = LL - WWIN;
        starts[sb] = start;
        scales[sb] = scale;
    }
}

// ---------------- window gather into kv ----------------
__global__ void gather_kernel(const float* __restrict__ h,
                              const int* __restrict__ starts,
                              const float* __restrict__ scales,
                              float* __restrict__ kv) {
    const int row = blockIdx.x;          // b*640 + s*128 + w
    const int b = row / (SSEL * WWIN);
    const int r = row % (SSEL * WWIN);
    const int s = r / WWIN;
    const int w = r % WWIN;
    const int sb = s * BB + b;
    const int src = b * LL + starts[sb] + w;
    const float sc = scales[sb];
    const int t = threadIdx.x;           // 256
    float4 v = reinterpret_cast<const float4*>(h)[(size_t)src * (DD / 4) + t];
    v.x *= sc; v.y *= sc; v.z *= sc; v.w *= sc;
    reinterpret_cast<float4*>(kv)[(size_t)row * (DD / 4) + t] = v;
}

// ================= TF32 tensor-core GEMM =================
// C[M,N] = A[M,K] @ op(B) + bias (+gelu) (+res)
// BT=true:  B is [N,K] row-major (C = A B^T)
// BT=false: B is [K,N] row-major (C = A B)
// Block tile 128x128x32, 8 warps, warp tile 64x32, mma m16n8k8 tf32.

#define SA_STRIDE 36    // A smem row stride: bank = 4*g + k (conflict-free)
#define SB_NN_STRIDE 136 // NN B smem row stride: bank = 8*k + n (conflict-free)
#define SBUF 4608       // floats per buffer (128*36 = 4608 >= 32*136 = 4352)

__device__ __forceinline__ void cp16(float* s, const float* g) {
    unsigned sa = (unsigned)__cvta_generic_to_shared(s);
    asm volatile("cp.async.cg.shared.global [%0], [%1], 16;\n" :: "r"(sa), "l"(g));
}
__device__ __forceinline__ void cp_commit() { asm volatile("cp.async.commit_group;\n"); }
__device__ __forceinline__ void cp_wait0()  { asm volatile("cp.async.wait_group 0;\n"); }

__device__ __forceinline__ void mma_tf32(float* d, const uint32_t* a, const uint32_t* b) {
    asm volatile(
        "mma.sync.aligned.m16n8k8.row.col.f32.tf32.tf32.f32 "
        "{%0,%1,%2,%3}, {%4,%5,%6,%7}, {%8,%9}, {%0,%1,%2,%3};\n"
        : "+f"(d[0]), "+f"(d[1]), "+f"(d[2]), "+f"(d[3])
        : "r"(a[0]), "r"(a[1]), "r"(a[2]), "r"(a[3]), "r"(b[0]), "r"(b[1]));
}

template<bool BT, bool GELU, bool RES>
__global__ __launch_bounds__(256, 2)
void mma_gemm(const float* __restrict__ A,
              const float* __restrict__ B,
              const float* __restrict__ bias,
              const float* __restrict__ res,
              float* __restrict__ C,
              int M, int N, int K) {
    extern __shared__ float smem[];
    float* As = smem;               // 2 * SBUF
    float* Bs = smem + 2 * SBUF;    // 2 * SBUF

    const int tid  = threadIdx.x;
    const int lane = tid & 31;
    const int wid  = tid >> 5;
    const int wm = (wid & 1) * 64;
    const int wn = (wid >> 1) * 32;
    const int lm = lane >> 2;   // group id 0..7
    const int lk = lane & 3;    // thread in group 0..3
    const int m0 = blockIdx.y * 128;
    const int n0 = blockIdx.x * 128;

    float acc[4][4][4];
    #pragma unroll
    for (int i = 0; i < 4; i++)
        #pragma unroll
        for (int j = 0; j < 4; j++)
            #pragma unroll
            for (int f = 0; f < 4; f++) acc[i][j][f] = 0.0f;

    auto issue = [&](int k0, int buf) {
        #pragma unroll
        for (int j = 0; j < 4; j++) {
            int idx = tid + j * 256;
            int r = idx >> 3, c = (idx & 7) * 4;
            cp16(&As[buf * SBUF + r * SA_STRIDE + c],
                 A + (size_t)(m0 + r) * K + k0 + c);
        }
        #pragma unroll
        for (int j = 0; j < 4; j++) {
            int idx = tid + j * 256;
            if (BT) {
                int r = idx >> 3, c = (idx & 7) * 4;
                cp16(&Bs[buf * SBUF + r * SA_STRIDE + c],
                     B + (size_t)(n0 + r) * K + k0 + c);
            } else {
                int r = idx >> 5, c = (idx & 31) * 4;
                cp16(&Bs[buf * SBUF + r * SB_NN_STRIDE + c],
                     B + (size_t)(k0 + r) * N + n0 + c);
            }
        }
    };

    issue(0, 0);
    cp_commit();
    cp_wait0();
    __syncthreads();

    const int T = K >> 5;  // K / 32
    for (int t = 0; t < T; t++) {
        const int buf = t & 1;
        if (t + 1 < T) { issue((t + 1) << 5, buf ^ 1); cp_commit(); }

        // compute on buf
        #pragma unroll
        for (int kk = 0; kk < 4; kk++) {
            uint32_t af[4][4];
            #pragma unroll
            for (int mi = 0; mi < 4; mi++) {
                const float* ap = &As[buf * SBUF + (wm + mi * 16 + lm) * SA_STRIDE + kk * 8 + lk];
                af[mi][0] = __float_as_uint(ap[0]);
                af[mi][1] = __float_as_uint(ap[8 * SA_STRIDE]);
                af[mi][2] = __float_as_uint(ap[4]);
                af[mi][3] = __float_as_uint(ap[8 * SA_STRIDE + 4]);
            }
            uint32_t bf[4][2];
            #pragma unroll
            for (int ni = 0; ni < 4; ni++) {
                if (BT) {
                    const float* bp = &Bs[buf * SBUF + (wn + ni * 8 + lm) * SA_STRIDE + kk * 8 + lk];
                    bf[ni][0] = __float_as_uint(bp[0]);
                    bf[ni][1] = __float_as_uint(bp[4]);
                } else {
                    const float* bp = &Bs[buf * SBUF + (kk * 8 + lk) * SB_NN_STRIDE + wn + ni * 8 + lm];
                    bf[ni][0] = __float_as_uint(bp[0]);
                    bf[ni][1] = __float_as_uint(bp[4 * SB_NN_STRIDE]);
                }
            }
            #pragma unroll
            for (int mi = 0; mi < 4; mi++)
                #pragma unroll
                for (int ni = 0; ni < 4; ni++)
                    mma_tf32(acc[mi][ni], af[mi], bf[ni]);
        }

        if (t + 1 < T) { cp_wait0(); __syncthreads(); }
    }

    // epilogue
    #pragma unroll
    for (int ni = 0; ni < 4; ni++) {
        const int cn = n0 + wn + ni * 8 + lk * 2;
        const float bx = bias[cn], by = bias[cn + 1];
        #pragma unroll
        for (int mi = 0; mi < 4; mi++) {
            const int rm = m0 + wm + mi * 16 + lm;
            float v0 = acc[mi][ni][0] + bx;
            float v1 = acc[mi][ni][1] + by;
            float v2 = acc[mi][ni][2] + bx;
            float v3 = acc[mi][ni][3] + by;
            if (GELU) {
                float vv[4] = {v0, v1, v2, v3};
                #pragma unroll
                for (int j = 0; j < 4; j++) {
                    float v = vv[j];
                    float u = 0.7978845608028654f * (v + 0.044715f * v * v * v);
                    vv[j] = 0.5f * v * (1.0f + tanhf(u));
                }
                v0 = vv[0]; v1 = vv[1]; v2 = vv[2]; v3 = vv[3];
            }
            if (RES) {
                float2 r0 = *reinterpret_cast<const float2*>(res + (size_t)rm * N + cn);
                float2 r1 = *reinterpret_cast<const float2*>(res + (size_t)(rm + 8) * N + cn);
                v0 += r0.x; v1 += r0.y; v2 += r1.x; v3 += r1.y;
            }
            float2 o0 = {v0, v1}, o1 = {v2, v3};
            *reinterpret_cast<float2*>(C + (size_t)rm * N + cn) = o0;
            *reinterpret_cast<float2*>(C + (size_t)(rm + 8) * N + cn) = o1;
        }
    }
}

// ---------------- attention: one block = 64 queries of one (b,head) -------
__global__ void attn_kernel(const float* __restrict__ q,
                            const float* __restrict__ k,
                            const float* __restrict__ v,
                            float* __restrict__ o) {
    __shared__ float Ks[64][64];
    __shared__ float Vs[64][64];
    const int bh = blockIdx.y;
    const int b = bh >> 4, hh = bh & 15;
    const int t = threadIdx.x;          // 64 threads, one query each
    const int l = blockIdx.x * 64 + t;

    const float* qp = q + ((size_t)(b * LL + l) * DD) + hh * DH;
    float qr[DH];
    #pragma unroll
    for (int d = 0; d < DH; d += 4) {
        float4 x = *reinterpret_cast<const float4*>(qp + d);
        qr[d] = x.x * 0.125f; qr[d + 1] = x.y * 0.125f;
        qr[d + 2] = x.z * 0.125f; qr[d + 3] = x.w * 0.125f;
    }

    float m = -1e30f, lsum = 0.0f;
    float acc[DH];
    #pragma unroll
    for (int d = 0; d < DH; d++) acc[d] = 0.0f;

    const float* kbase = k + ((size_t)b * (SSEL * WWIN)) * DD + hh * DH;
    const float* vbase = v + ((size_t)b * (SSEL * WWIN)) * DD + hh * DH;
    const int tr = t >> 4, tc = (t & 15) * 4;

    for (int kt = 0; kt < (SSEL * WWIN) / 64; kt++) {
        #pragma unroll
        for (int r4 = 0; r4 < 16; r4++) {
            const int row = r4 * 4 + tr;
            const size_t gm = (size_t)(kt * 64 + row) * DD;
            *reinterpret_cast<float4*>(&Ks[row][tc]) = *reinterpret_cast<const float4*>(kbase + gm + tc);
            *reinterpret_cast<float4*>(&Vs[row][tc]) = *reinterpret_cast<const float4*>(vbase + gm + tc);
        }
        __syncthreads();
        #pragma unroll 1
        for (int j = 0; j < 64; j++) {
            float s = 0.0f;
            #pragma unroll
            for (int d = 0; d < DH; d += 4) {
                float4 kk4 = *reinterpret_cast<const float4*>(&Ks[j][d]);
                s += qr[d] * kk4.x + qr[d + 1] * kk4.y + qr[d + 2] * kk4.z + qr[d + 3] * kk4.w;
            }
            if (s <= m) {
                float p = __expf(s - m);
                lsum += p;
                #pragma unroll
                for (int d = 0; d < DH; d++) acc[d] += p * Vs[j][d];
            } else {
                float c = __expf(m - s);
                lsum = lsum * c + 1.0f;
                #pragma unroll
                for (int d = 0; d < DH; d++) acc[d] = acc[d] * c + Vs[j][d];
                m = s;
            }
        }
        __syncthreads();
    }

    const float inv = 1.0f / lsum;
    float* op = o + ((size_t)(b * LL + l) * DD) + hh * DH;
    #pragma unroll
    for (int d = 0; d < DH; d += 4) {
        float4 x;
        x.x = acc[d] * inv; x.y = acc[d + 1] * inv;
        x.z = acc[d + 2] * inv; x.w = acc[d + 3] * inv;
        *reinterpret_cast<float4*>(op + d) = x;
    }
}

// ---------------- driver ----------------
extern "C" void kernel_launch(void* const* d_in, const int* in_sizes, int n_in,
                              void* d_out, int out_size) {
    const float* x        = (const float*)d_in[0];
    const float* gumbel_u = (const float*)d_in[1];
    const float* ln1_g    = (const float*)d_in[2];
    const float* ln1_b    = (const float*)d_in[3];
    const float* ln2_g    = (const float*)d_in[4];
    const float* ln2_b    = (const float*)d_in[5];
    const float* w_sal    = (const float*)d_in[6];
    const float* b_sal    = (const float*)d_in[7];
    const float* ipw      = (const float*)d_in[8];
    const float* ipb      = (const float*)d_in[9];
    const float* opw      = (const float*)d_in[10];
    const float* opb      = (const float*)d_in[11];
    const float* w_fc     = (const float*)d_in[12];
    const float* b_fc     = (const float*)d_in[13];
    const float* w_proj   = (const float*)d_in[14];
    const float* b_proj   = (const float*)d_in[15];
    float* out = (float*)d_out;

    void* p;
    cudaGetSymbolAddress(&p, g_h);      float* h    = (float*)p;
    cudaGetSymbolAddress(&p, g_kv);     float* kv   = (float*)p;
    cudaGetSymbolAddress(&p, g_q);      float* qb   = (float*)p;
    cudaGetSymbolAddress(&p, g_k);      float* kb   = (float*)p;
    cudaGetSymbolAddress(&p, g_v);      float* vb   = (float*)p;
    cudaGetSymbolAddress(&p, g_att);    float* att  = (float*)p;
    cudaGetSymbolAddress(&p, g_x2);     float* x2   = (float*)p;
    cudaGetSymbolAddress(&p, g_h2);     float* h2   = (float*)p;
    cudaGetSymbolAddress(&p, g_ff);     float* ff   = (float*)p;
    cudaGetSymbolAddress(&p, g_logits); float* logi = (float*)p;
    cudaGetSymbolAddress(&p, g_start);  int*   st   = (int*)p;
    cudaGetSymbolAddress(&p, g_scale);  float* sc   = (float*)p;

    const int SMEM_BYTES = 4 * SBUF * 4;  // 73728
    cudaFuncSetAttribute(mma_gemm<true,  false, false>, cudaFuncAttributeMaxDynamicSharedMemorySize, SMEM_BYTES);
    cudaFuncSetAttribute(mma_gemm<true,  false, true >, cudaFuncAttributeMaxDynamicSharedMemorySize, SMEM_BYTES);
    cudaFuncSetAttribute(mma_gemm<false, true,  false>, cudaFuncAttributeMaxDynamicSharedMemorySize, SMEM_BYTES);
    cudaFuncSetAttribute(mma_gemm<false, false, true >, cudaFuncAttributeMaxDynamicSharedMemorySize, SMEM_BYTES);

    // 1. LN1
    ln_kernel<<<NTOK, 256>>>(x, ln1_g, ln1_b, h);
    // 2. saliency logits
    logits_kernel<<<BB * NB, 256>>>(h, w_sal, b_sal, logi);
    // 3. gumbel window selection
    select_kernel<<<SSEL * BB, 32>>>(logi, gumbel_u, st, sc);
    // 4. gather windows -> kv
    gather_kernel<<<MKV, 256>>>(h, st, sc, kv);
    // 5. Q/K/V projections (NT)
    mma_gemm<true, false, false><<<dim3(DD / 128, NTOK / 128), 256, SMEM_BYTES>>>(
        h, ipw, ipb, nullptr, qb, NTOK, DD, DD);
    mma_gemm<true, false, false><<<dim3(DD / 128, MKV / 128), 256, SMEM_BYTES>>>(
        kv, ipw + (size_t)DD * DD, ipb + DD, nullptr, kb, MKV, DD, DD);
    mma_gemm<true, false, false><<<dim3(DD / 128, MKV / 128), 256, SMEM_BYTES>>>(
        kv, ipw + 2 * (size_t)DD * DD, ipb + 2 * DD, nullptr, vb, MKV, DD, DD);
    // 6. attention
    attn_kernel<<<dim3(LL / 64, BB * NH), 64>>>(qb, kb, vb, att);
    // 7. out proj + residual
    mma_gemm<true, false, true><<<dim3(DD / 128, NTOK / 128), 256, SMEM_BYTES>>>(
        att, opw, opb, x, x2, NTOK, DD, DD);
    // 8. LN2
    ln_kernel<<<NTOK, 256>>>(x2, ln2_g, ln2_b, h2);
    // 9. FFN up + gelu (NN)
    mma_gemm<false, true, false><<<dim3(DFFN / 128, NTOK / 128), 256, SMEM_BYTES>>>(
        h2, w_fc, b_fc, nullptr, ff, NTOK, DFFN, DD);
    // 10. FFN down + residual (NN) -> out
    mma_gemm<false, false, true><<<dim3(DD / 128, NTOK / 128), 256, SMEM_BYTES>>>(
        ff, w_proj, b_proj, x2, out, NTOK, DD, DFFN);
}

// round 3
// speedup vs baseline: 3.5661x; 1.3058x over previous
#include <cuda_runtime.h>
#include <math.h>
#include <stdint.h>

// ---------------- problem constants ----------------
#define DD     1024
#define LL     2048
#define BB     4
#define NH     16
#define DH     64
#define SSEL   5
#define WWIN   128
#define BKBLK  32
#define NB     64          // L / BK
#define NTOK   8192        // B*L
#define MKV    2560        // B*S*W
#define NKEY   640         // S*W keys per batch
#define DFFN   4096

// ---------------- scratch (device globals; no allocations allowed) --------
__device__ float g_h   [NTOK * DD];
__device__ float g_kv  [MKV  * DD];
__device__ float g_q   [NTOK * DD];
__device__ float g_k   [MKV  * DD];
__device__ float g_v   [MKV  * DD];
__device__ float g_vt  [BB * DD * NKEY];
__device__ float g_att [NTOK * DD];
__device__ float g_x2  [NTOK * DD];
__device__ float g_h2  [NTOK * DD];
__device__ float g_ff  [NTOK * DFFN];
__device__ float g_logits[BB * NB];
__device__ int   g_start [SSEL * BB];
__device__ float g_scale [SSEL * BB];

// ---------------- helpers ----------------
__device__ __forceinline__ uint32_t f2t(float f) {
    uint32_t u;
    asm("cvt.rna.tf32.f32 %0, %1;" : "=r"(u) : "f"(f));
    return u;
}

__device__ __forceinline__ void mma_tf32(float* d, const uint32_t* a, const uint32_t* b) {
    asm volatile(
        "mma.sync.aligned.m16n8k8.row.col.f32.tf32.tf32.f32 "
        "{%0,%1,%2,%3}, {%4,%5,%6,%7}, {%8,%9}, {%0,%1,%2,%3};\n"
        : "+f"(d[0]), "+f"(d[1]), "+f"(d[2]), "+f"(d[3])
        : "r"(a[0]), "r"(a[1]), "r"(a[2]), "r"(a[3]), "r"(b[0]), "r"(b[1]));
}

__device__ __forceinline__ void cp16(float* s, const float* g) {
    unsigned sa = (unsigned)__cvta_generic_to_shared(s);
    asm volatile("cp.async.cg.shared.global [%0], [%1], 16;\n" :: "r"(sa), "l"(g));
}
__device__ __forceinline__ void cp_commit() { asm volatile("cp.async.commit_group;\n"); }
__device__ __forceinline__ void cp_wait0()  { asm volatile("cp.async.wait_group 0;\n"); }

// ---------------- LayerNorm: one block per token ----------------
__global__ void ln_kernel(const float* __restrict__ x,
                          const float* __restrict__ gam,
                          const float* __restrict__ bet,
                          float* __restrict__ out) {
    __shared__ float red[8];
    const int row = blockIdx.x;
    const int t = threadIdx.x;  // 256 threads, each handles 4 floats
    const float4* xr = reinterpret_cast<const float4*>(x) + (size_t)row * (DD / 4);
    float4 v = xr[t];

    float s = v.x + v.y + v.z + v.w;
    #pragma unroll
    for (int o = 16; o; o >>= 1) s += __shfl_down_sync(0xffffffffu, s, o);
    if ((t & 31) == 0) red[t >> 5] = s;
    __syncthreads();
    float tot = red[0] + red[1] + red[2] + red[3] + red[4] + red[5] + red[6] + red[7];
    const float mean = tot * (1.0f / DD);
    __syncthreads();

    float dx = v.x - mean, dy = v.y - mean, dz = v.z - mean, dw = v.w - mean;
    float sq = dx * dx + dy * dy + dz * dz + dw * dw;
    #pragma unroll
    for (int o = 16; o; o >>= 1) sq += __shfl_down_sync(0xffffffffu, sq, o);
    if ((t & 31) == 0) red[t >> 5] = sq;
    __syncthreads();
    float var = (red[0] + red[1] + red[2] + red[3] + red[4] + red[5] + red[6] + red[7]) * (1.0f / DD);
    const float r = rsqrtf(var + 1e-5f);

    const float4 gg = reinterpret_cast<const float4*>(gam)[t];
    const float4 bb = reinterpret_cast<const float4*>(bet)[t];
    float4 o4;
    o4.x = dx * r * gg.x + bb.x;
    o4.y = dy * r * gg.y + bb.y;
    o4.z = dz * r * gg.z + bb.z;
    o4.w = dw * r * gg.w + bb.w;
    reinterpret_cast<float4*>(out)[(size_t)row * (DD / 4) + t] = o4;
}

// ---------------- block saliency logits ----------------
__global__ void logits_kernel(const float* __restrict__ h,
                              const float* __restrict__ w_sal,
                              const float* __restrict__ b_sal,
                              float* __restrict__ logits) {
    __shared__ float red[8];
    const int t = threadIdx.x;  // 256
    const float4 w = reinterpret_cast<const float4*>(w_sal)[t];
    const float* base = h + (size_t)blockIdx.x * BKBLK * DD;
    float acc = 0.0f;
    for (int tok = 0; tok < BKBLK; tok++) {
        float4 hv = reinterpret_cast<const float4*>(base + (size_t)tok * DD)[t];
        acc += hv.x * w.x + hv.y * w.y + hv.z * w.z + hv.w * w.w;
    }
    #pragma unroll
    for (int o = 16; o; o >>= 1) acc += __shfl_down_sync(0xffffffffu, acc, o);
    if ((t & 31) == 0) red[t >> 5] = acc;
    __syncthreads();
    if (t == 0) {
        float tot = red[0] + red[1] + red[2] + red[3] + red[4] + red[5] + red[6] + red[7];
        logits[blockIdx.x] = tot * (1.0f / BKBLK) + b_sal[0];
    }
}

// ---------------- gumbel selection ----------------
__global__ void select_kernel(const float* __restrict__ logits,
                              const float* __restrict__ gu,
                              int* __restrict__ starts,
                              float* __restrict__ scales) {
    const int sb = blockIdx.x;           // s*B + b
    const int b = sb % BB;
    const int lane = threadIdx.x;        // 32

    float u0 = gu[sb * NB + lane];
    float u1 = gu[sb * NB + 32 + lane];
    float g0 = -logf(-logf(u0 + 1e-9f) + 1e-9f);
    float g1 = -logf(-logf(u1 + 1e-9f) + 1e-9f);
    float p0 = logits[b * NB + lane] + g0;       // TAU = 1
    float p1 = logits[b * NB + 32 + lane] + g1;

    float m = p0; int idx = lane;
    if (p1 > m) { m = p1; idx = lane + 32; }
    #pragma unroll
    for (int o = 16; o; o >>= 1) {
        float om = __shfl_down_sync(0xffffffffu, m, o);
        int   oi = __shfl_down_sync(0xffffffffu, idx, o);
        if (om > m || (om == m && oi < idx)) { m = om; idx = oi; }
    }
    m   = __shfl_sync(0xffffffffu, m, 0);
    idx = __shfl_sync(0xffffffffu, idx, 0);

    float se = expf(p0 - m) + expf(p1 - m);
    #pragma unroll
    for (int o = 16; o; o >>= 1) se += __shfl_down_sync(0xffffffffu, se, o);
    if (lane == 0) {
        float w = 1.0f / se;
        float scale = (1.0f + w) - w;
        int start = idx * BKBLK + BKBLK / 2 - WWIN / 2;
        if (start < 0) start = 0;
        if (start > LL - WWIN) start = LL - WWIN;
        starts[sb] = start;
        scales[sb] = scale;
    }
}

// ---------------- window gather into kv ----------------
__global__ void gather_kernel(const float* __restrict__ h,
                              const int* __restrict__ starts,
                              const float* __restrict__ scales,
                              float* __restrict__ kv) {
    const int row = blockIdx.x;          // b*640 + s*128 + w
    const int b = row / (SSEL * WWIN);
    const int r = row % (SSEL * WWIN);
    const int s = r / WWIN;
    const int w = r % WWIN;
    const int sb = s * BB + b;
    const int src = b * LL + starts[sb] + w;
    const float sc = scales[sb];
    const int t = threadIdx.x;           // 256
    float4 v = reinterpret_cast<const float4*>(h)[(size_t)src * (DD / 4) + t];
    v.x *= sc; v.y *= sc; v.z *= sc; v.w *= sc;
    reinterpret_cast<float4*>(kv)[(size_t)row * (DD / 4) + t] = v;
}

// ---------------- V transpose: v[b*640+j][c] -> vt[b*1024+c][j] ----------
__global__ void vtrans_kernel(const float* __restrict__ v, float* __restrict__ vt) {
    __shared__ float t[32][33];
    const int b = blockIdx.z;
    const int j0 = blockIdx.x * 32, c0 = blockIdx.y * 32;
    const int tx = threadIdx.x, ty = threadIdx.y;  // 32 x 8
    #pragma unroll
    for (int i = 0; i < 32; i += 8)
        t[ty + i][tx] = v[((size_t)(b * NKEY + j0 + ty + i)) * DD + c0 + tx];
    __syncthreads();
    #pragma unroll
    for (int i = 0; i < 32; i += 8)
        vt[((size_t)(b * DD + c0 + ty + i)) * NKEY + j0 + tx] = t[tx][ty + i];
}

// ================= TF32 tensor-core GEMM =================
#define SA_STRIDE 36     // A smem row stride: bank = 4*g + k (conflict-free)
#define SB_NN_STRIDE 136 // NN B smem row stride: bank = 8*k + n (conflict-free)
#define SBUF 4608        // floats per buffer

template<bool BT, bool GELU, bool RES>
__global__ __launch_bounds__(256, 2)
void mma_gemm(const float* __restrict__ A,
              const float* __restrict__ B,
              const float* __restrict__ bias,
              const float* __restrict__ res,
              float* __restrict__ C,
              int M, int N, int K) {
    extern __shared__ float smem[];
    float* As = smem;               // 2 * SBUF
    float* Bs = smem + 2 * SBUF;    // 2 * SBUF

    const int tid  = threadIdx.x;
    const int lane = tid & 31;
    const int wid  = tid >> 5;
    const int wm = (wid & 1) * 64;
    const int wn = (wid >> 1) * 32;
    const int lm = lane >> 2;   // group id 0..7
    const int lk = lane & 3;    // thread in group 0..3
    const int m0 = blockIdx.y * 128;
    const int n0 = blockIdx.x * 128;

    float acc[4][4][4];
    #pragma unroll
    for (int i = 0; i < 4; i++)
        #pragma unroll
        for (int j = 0; j < 4; j++)
            #pragma unroll
            for (int f = 0; f < 4; f++) acc[i][j][f] = 0.0f;

    auto issue = [&](int k0, int buf) {
        #pragma unroll
        for (int j = 0; j < 4; j++) {
            int idx = tid + j * 256;
            int r = idx >> 3, c = (idx & 7) * 4;
            cp16(&As[buf * SBUF + r * SA_STRIDE + c],
                 A + (size_t)(m0 + r) * K + k0 + c);
        }
        #pragma unroll
        for (int j = 0; j < 4; j++) {
            int idx = tid + j * 256;
            if (BT) {
                int r = idx >> 3, c = (idx & 7) * 4;
                cp16(&Bs[buf * SBUF + r * SA_STRIDE + c],
                     B + (size_t)(n0 + r) * K + k0 + c);
            } else {
                int r = idx >> 5, c = (idx & 31) * 4;
                cp16(&Bs[buf * SBUF + r * SB_NN_STRIDE + c],
                     B + (size_t)(k0 + r) * N + n0 + c);
            }
        }
    };

    issue(0, 0);
    cp_commit();
    cp_wait0();
    __syncthreads();

    const int T = K >> 5;  // K / 32
    for (int t = 0; t < T; t++) {
        const int buf = t & 1;
        if (t + 1 < T) { issue((t + 1) << 5, buf ^ 1); cp_commit(); }

        #pragma unroll
        for (int kk = 0; kk < 4; kk++) {
            uint32_t af[4][4];
            #pragma unroll
            for (int mi = 0; mi < 4; mi++) {
                const float* ap = &As[buf * SBUF + (wm + mi * 16 + lm) * SA_STRIDE + kk * 8 + lk];
                af[mi][0] = f2t(ap[0]);
                af[mi][1] = f2t(ap[8 * SA_STRIDE]);
                af[mi][2] = f2t(ap[4]);
                af[mi][3] = f2t(ap[8 * SA_STRIDE + 4]);
            }
            uint32_t bf[4][2];
            #pragma unroll
            for (int ni = 0; ni < 4; ni++) {
                if (BT) {
                    const float* bp = &Bs[buf * SBUF + (wn + ni * 8 + lm) * SA_STRIDE + kk * 8 + lk];
                    bf[ni][0] = f2t(bp[0]);
                    bf[ni][1] = f2t(bp[4]);
                } else {
                    const float* bp = &Bs[buf * SBUF + (kk * 8 + lk) * SB_NN_STRIDE + wn + ni * 8 + lm];
                    bf[ni][0] = f2t(bp[0]);
                    bf[ni][1] = f2t(bp[4 * SB_NN_STRIDE]);
                }
            }
            #pragma unroll
            for (int mi = 0; mi < 4; mi++)
                #pragma unroll
                for (int ni = 0; ni < 4; ni++)
                    mma_tf32(acc[mi][ni], af[mi], bf[ni]);
        }

        if (t + 1 < T) { cp_wait0(); __syncthreads(); }
    }

    // epilogue
    #pragma unroll
    for (int ni = 0; ni < 4; ni++) {
        const int cn = n0 + wn + ni * 8 + lk * 2;
        const float bx = bias[cn], by = bias[cn + 1];
        #pragma unroll
        for (int mi = 0; mi < 4; mi++) {
            const int rm = m0 + wm + mi * 16 + lm;
            float v0 = acc[mi][ni][0] + bx;
            float v1 = acc[mi][ni][1] + by;
            float v2 = acc[mi][ni][2] + bx;
            float v3 = acc[mi][ni][3] + by;
            if (GELU) {
                float vv[4] = {v0, v1, v2, v3};
                #pragma unroll
                for (int j = 0; j < 4; j++) {
                    float v = vv[j];
                    float u = 0.7978845608028654f * (v + 0.044715f * v * v * v);
                    vv[j] = 0.5f * v * (1.0f + tanhf(u));
                }
                v0 = vv[0]; v1 = vv[1]; v2 = vv[2]; v3 = vv[3];
            }
            if (RES) {
                float2 r0 = *reinterpret_cast<const float2*>(res + (size_t)rm * N + cn);
                float2 r1 = *reinterpret_cast<const float2*>(res + (size_t)(rm + 8) * N + cn);
                v0 += r0.x; v1 += r0.y; v2 += r1.x; v3 += r1.y;
            }
            float2 o0 = {v0, v1}, o1 = {v2, v3};
            *reinterpret_cast<float2*>(C + (size_t)rm * N + cn) = o0;
            *reinterpret_cast<float2*>(C + (size_t)(rm + 8) * N + cn) = o1;
        }
    }
}

// ================= flash attention (TF32 mma) =================
// grid (L/64, B*H), 128 threads (4 warps). Each block: 64 queries of one (b,h).
#define AT_STRIDE 68
#define AT_TILE (64 * AT_STRIDE)

__global__ __launch_bounds__(128)
void fattn_kernel(const float* __restrict__ q,
                  const float* __restrict__ k,
                  const float* __restrict__ vt,
                  float* __restrict__ o) {
    extern __shared__ float sm[];
    float* Qs = sm;                 // [m][d]
    float* Ks = sm + AT_TILE;       // [j][d]
    float* Vs = sm + 2 * AT_TILE;   // [d][j]  (transposed V)
    float* Ps = sm + 3 * AT_TILE;   // [m][j]

    const int bh = blockIdx.y;
    const int b = bh >> 4, hh = bh & 15;
    const int q0 = blockIdx.x * 64;
    const int tid = threadIdx.x, lane = tid & 31, wid = tid >> 5;
    const int lm = lane >> 2, lk = lane & 3;
    const int wm = wid * 16;

    // load Q tile (scaled by 1/8)
    {
        const float* qg = q + ((size_t)(b * LL + q0)) * DD + hh * DH;
        #pragma unroll
        for (int it = 0; it < 8; it++) {
            int idx = tid + it * 128;
            int r = idx >> 4, c = (idx & 15) * 4;
            float4 x = *reinterpret_cast<const float4*>(qg + (size_t)r * DD + c);
            x.x *= 0.125f; x.y *= 0.125f; x.z *= 0.125f; x.w *= 0.125f;
            *reinterpret_cast<float4*>(&Qs[r * AT_STRIDE + c]) = x;
        }
    }

    float mrow0 = -1e30f, mrow1 = -1e30f, lrow0 = 0.0f, lrow1 = 0.0f;
    float oacc[8][4];
    #pragma unroll
    for (int ni = 0; ni < 8; ni++)
        #pragma unroll
        for (int f = 0; f < 4; f++) oacc[ni][f] = 0.0f;

    const float* kg = k + ((size_t)(b * NKEY)) * DD + hh * DH;
    const float* vg = vt + ((size_t)(b * DD + hh * DH)) * NKEY;

    for (int kt = 0; kt < NKEY / 64; kt++) {
        __syncthreads();
        #pragma unroll
        for (int it = 0; it < 8; it++) {
            int idx = tid + it * 128;
            int r = idx >> 4, c = (idx & 15) * 4;
            *reinterpret_cast<float4*>(&Ks[r * AT_STRIDE + c]) =
                *reinterpret_cast<const float4*>(kg + (size_t)(kt * 64 + r) * DD + c);
            *reinterpret_cast<float4*>(&Vs[r * AT_STRIDE + c]) =
                *reinterpret_cast<const float4*>(vg + (size_t)r * NKEY + kt * 64 + c);
        }
        __syncthreads();

        // S = Q @ K^T (warp rows wm..wm+15, all 64 cols)
        float s[8][4];
        #pragma unroll
        for (int ni = 0; ni < 8; ni++)
            #pragma unroll
            for (int f = 0; f < 4; f++) s[ni][f] = 0.0f;

        #pragma unroll
        for (int kk = 0; kk < 8; kk++) {
            uint32_t a[4];
            const float* ap = &Qs[(wm + lm) * AT_STRIDE + kk * 8 + lk];
            a[0] = __float_as_uint(ap[0]);
            a[1] = __float_as_uint(ap[8 * AT_STRIDE]);
            a[2] = __float_as_uint(ap[4]);
            a[3] = __float_as_uint(ap[8 * AT_STRIDE + 4]);
            #pragma unroll
            for (int ni = 0; ni < 8; ni++) {
                uint32_t bfr[2];
                const float* bp = &Ks[(ni * 8 + lm) * AT_STRIDE + kk * 8 + lk];
                bfr[0] = __float_as_uint(bp[0]);
                bfr[1] = __float_as_uint(bp[4]);
                mma_tf32(s[ni], a, bfr);
            }
        }

        // online softmax (rows lm and lm+8 within warp tile)
        float rm0 = -1e30f, rm1 = -1e30f;
        #pragma unroll
        for (int ni = 0; ni < 8; ni++) {
            rm0 = fmaxf(rm0, fmaxf(s[ni][0], s[ni][1]));
            rm1 = fmaxf(rm1, fmaxf(s[ni][2], s[ni][3]));
        }
        rm0 = fmaxf(rm0, __shfl_xor_sync(0xffffffffu, rm0, 1));
        rm0 = fmaxf(rm0, __shfl_xor_sync(0xffffffffu, rm0, 2));
        rm1 = fmaxf(rm1, __shfl_xor_sync(0xffffffffu, rm1, 1));
        rm1 = fmaxf(rm1, __shfl_xor_sync(0xffffffffu, rm1, 2));

        float nm0 = fmaxf(mrow0, rm0), nm1 = fmaxf(mrow1, rm1);
        float al0 = __expf(mrow0 - nm0), al1 = __expf(mrow1 - nm1);
        mrow0 = nm0; mrow1 = nm1;

        float rs0 = 0.0f, rs1 = 0.0f;
        #pragma unroll
        for (int ni = 0; ni < 8; ni++) {
            s[ni][0] = __expf(s[ni][0] - nm0);
            s[ni][1] = __expf(s[ni][1] - nm0);
            s[ni][2] = __expf(s[ni][2] - nm1);
            s[ni][3] = __expf(s[ni][3] - nm1);
            rs0 += s[ni][0] + s[ni][1];
            rs1 += s[ni][2] + s[ni][3];
        }
        rs0 += __shfl_xor_sync(0xffffffffu, rs0, 1);
        rs0 += __shfl_xor_sync(0xffffffffu, rs0, 2);
        rs1 += __shfl_xor_sync(0xffffffffu, rs1, 1);
        rs1 += __shfl_xor_sync(0xffffffffu, rs1, 2);

        lrow0 = lrow0 * al0 + rs0;
        lrow1 = lrow1 * al1 + rs1;

        #pragma unroll
        for (int ni = 0; ni < 8; ni++) {
            oacc[ni][0] *= al0; oacc[ni][1] *= al0;
            oacc[ni][2] *= al1; oacc[ni][3] *= al1;
        }

        // write P to smem (own warp rows only)
        #pragma unroll
        for (int ni = 0; ni < 8; ni++) {
            float* pp = &Ps[(wm + lm) * AT_STRIDE + ni * 8 + 2 * lk];
            pp[0] = s[ni][0];
            pp[1] = s[ni][1];
            pp[8 * AT_STRIDE] = s[ni][2];
            pp[8 * AT_STRIDE + 1] = s[ni][3];
        }
        __syncwarp();

        // O += P @ V  (A = Ps rows, B = Vs[d][j])
        #pragma unroll
        for (int kk = 0; kk < 8; kk++) {
            uint32_t a[4];
            const float* ap = &Ps[(wm + lm) * AT_STRIDE + kk * 8 + lk];
            a[0] = __float_as_uint(ap[0]);
            a[1] = __float_as_uint(ap[8 * AT_STRIDE]);
            a[2] = __float_as_uint(ap[4]);
            a[3] = __float_as_uint(ap[8 * AT_STRIDE + 4]);
            #pragma unroll
            for (int ni = 0; ni < 8; ni++) {
                uint32_t bfr[2];
                const float* bp = &Vs[(ni * 8 + lm) * AT_STRIDE + kk * 8 + lk];
                bfr[0] = __float_as_uint(bp[0]);
                bfr[1] = __float_as_uint(bp[4]);
                mma_tf32(oacc[ni], a, bfr);
            }
        }
    }

    // epilogue: divide by l and store
    const float inv0 = 1.0f / lrow0, inv1 = 1.0f / lrow1;
    float* og = o + ((size_t)(b * LL + q0 + wm + lm)) * DD + hh * DH;
    #pragma unroll
    for (int ni = 0; ni < 8; ni++) {
        const int cc = ni * 8 + 2 * lk;
        float2 o0 = {oacc[ni][0] * inv0, oacc[ni][1] * inv0};
        float2 o1 = {oacc[ni][2] * inv1, oacc[ni][3] * inv1};
        *reinterpret_cast<float2*>(og + cc) = o0;
        *reinterpret_cast<float2*>(og + (size_t)8 * DD + cc) = o1;
    }
}

// ---------------- driver ----------------
extern "C" void kernel_launch(void* const* d_in, const int* in_sizes, int n_in,
                              void* d_out, int out_size) {
    const float* x        = (const float*)d_in[0];
    const float* gumbel_u = (const float*)d_in[1];
    const float* ln1_g    = (const float*)d_in[2];
    const float* ln1_b    = (const float*)d_in[3];
    const float* ln2_g    = (const float*)d_in[4];
    const float* ln2_b    = (const float*)d_in[5];
    const float* w_sal    = (const float*)d_in[6];
    const float* b_sal    = (const float*)d_in[7];
    const float* ipw      = (const float*)d_in[8];
    const float* ipb      = (const float*)d_in[9];
    const float* opw      = (const float*)d_in[10];
    const float* opb      = (const float*)d_in[11];
    const float* w_fc     = (const float*)d_in[12];
    const float* b_fc     = (const float*)d_in[13];
    const float* w_proj   = (const float*)d_in[14];
    const float* b_proj   = (const float*)d_in[15];
    float* out = (float*)d_out;

    void* p;
    cudaGetSymbolAddress(&p, g_h);      float* h    = (float*)p;
    cudaGetSymbolAddress(&p, g_kv);     float* kv   = (float*)p;
    cudaGetSymbolAddress(&p, g_q);      float* qb   = (float*)p;
    cudaGetSymbolAddress(&p, g_k);      float* kb   = (float*)p;
    cudaGetSymbolAddress(&p, g_v);      float* vb   = (float*)p;
    cudaGetSymbolAddress(&p, g_vt);     float* vtb  = (float*)p;
    cudaGetSymbolAddress(&p, g_att);    float* att  = (float*)p;
    cudaGetSymbolAddress(&p, g_x2);     float* x2   = (float*)p;
    cudaGetSymbolAddress(&p, g_h2);     float* h2   = (float*)p;
    cudaGetSymbolAddress(&p, g_ff);     float* ff   = (float*)p;
    cudaGetSymbolAddress(&p, g_logits); float* logi = (float*)p;
    cudaGetSymbolAddress(&p, g_start);  int*   st   = (int*)p;
    cudaGetSymbolAddress(&p, g_scale);  float* sc   = (float*)p;

    const int SMEM_BYTES = 4 * SBUF * 4;       // 73728
    const int ATTN_SMEM  = 4 * AT_TILE * 4;    // 69632
    cudaFuncSetAttribute(mma_gemm<true,  false, false>, cudaFuncAttributeMaxDynamicSharedMemorySize, SMEM_BYTES);
    cudaFuncSetAttribute(mma_gemm<true,  false, true >, cudaFuncAttributeMaxDynamicSharedMemorySize, SMEM_BYTES);
    cudaFuncSetAttribute(mma_gemm<false, true,  false>, cudaFuncAttributeMaxDynamicSharedMemorySize, SMEM_BYTES);
    cudaFuncSetAttribute(mma_gemm<false, false, true >, cudaFuncAttributeMaxDynamicSharedMemorySize, SMEM_BYTES);
    cudaFuncSetAttribute(fattn_kernel, cudaFuncAttributeMaxDynamicSharedMemorySize, ATTN_SMEM);

    // 1. LN1
    ln_kernel<<<NTOK, 256>>>(x, ln1_g, ln1_b, h);
    // 2. saliency logits
    logits_kernel<<<BB * NB, 256>>>(h, w_sal, b_sal, logi);
    // 3. gumbel window selection
    select_kernel<<<SSEL * BB, 32>>>(logi, gumbel_u, st, sc);
    // 4. gather windows -> kv
    gather_kernel<<<MKV, 256>>>(h, st, sc, kv);
    // 5. Q/K/V projections (NT)
    mma_gemm<true, false, false><<<dim3(DD / 128, NTOK / 128), 256, SMEM_BYTES>>>(
        h, ipw, ipb, nullptr, qb, NTOK, DD, DD);
    mma_gemm<true, false, false><<<dim3(DD / 128, MKV / 128), 256, SMEM_BYTES>>>(
        kv, ipw + (size_t)DD * DD, ipb + DD, nullptr, kb, MKV, DD, DD);
    mma_gemm<true, false, false><<<dim3(DD / 128, MKV / 128), 256, SMEM_BYTES>>>(
        kv, ipw + 2 * (size_t)DD * DD, ipb + 2 * DD, nullptr, vb, MKV, DD, DD);
    // 5b. transpose V for flash attention
    vtrans_kernel<<<dim3(NKEY / 32, DD / 32, BB), dim3(32, 8)>>>(vb, vtb);
    // 6. attention (tensor-core flash)
    fattn_kernel<<<dim3(LL / 64, BB * NH), 128, ATTN_SMEM>>>(qb, kb, vtb, att);
    // 7. out proj + residual
    mma_gemm<true, false, true><<<dim3(DD / 128, NTOK / 128), 256, SMEM_BYTES>>>(
        att, opw, opb, x, x2, NTOK, DD, DD);
    // 8. LN2
    ln_kernel<<<NTOK, 256>>>(x2, ln2_g, ln2_b, h2);
    // 9. FFN up + gelu (NN)
    mma_gemm<false, true, false><<<dim3(DFFN / 128, NTOK / 128), 256, SMEM_BYTES>>>(
        h2, w_fc, b_fc, nullptr, ff, NTOK, DFFN, DD);
    // 10. FFN down + residual (NN) -> out
    mma_gemm<false, false, true><<<dim3(DD / 128, NTOK / 128), 256, SMEM_BYTES>>>(
        ff, w_proj, b_proj, x2, out, NTOK, DD, DFFN);
}

// round 4
// speedup vs baseline: 5.7415x; 1.6100x over previous
#include <cuda_runtime.h>
#include <cuda_fp16.h>
#include <math.h>
#include <stdint.h>

// ---------------- problem constants ----------------
#define DD     1024
#define LL     2048
#define BB     4
#define NH     16
#define DH     64
#define SSEL   5
#define WWIN   128
#define BKBLK  32
#define NB     64          // L / BK
#define NTOK   8192        // B*L
#define MKV    2560        // B*S*W
#define NKEY   640         // S*W keys per batch
#define DFFN   4096

// ---------------- scratch (device globals; no allocations allowed) --------
__device__ float  g_h   [NTOK * DD];     // fp32 h (logits + gather)
__device__ __half g_h16 [NTOK * DD];     // fp16 h (Q gemm A)
__device__ __half g_kv16[MKV  * DD];     // fp16 kv (K/V gemm A)
__device__ float  g_q   [NTOK * DD];
__device__ float  g_k   [MKV  * DD];
__device__ float  g_v   [MKV  * DD];
__device__ float  g_vt  [BB * DD * NKEY];
__device__ __half g_att16[NTOK * DD];    // fp16 attention out (out-proj A)
__device__ float  g_x2  [NTOK * DD];
__device__ __half g_h2_16[NTOK * DD];    // fp16 ln2 out (FFN1 A)
__device__ __half g_ff16 [NTOK * DFFN];  // fp16 FFN1 out (FFN2 A)
__device__ __half g_w16  [12582912];     // fp16 weights: ipw|opw|w_fc|w_proj
__device__ float  g_logits[BB * NB];
__device__ int    g_start [SSEL * BB];
__device__ float  g_scale [SSEL * BB];

#define W16_IPW   0
#define W16_OPW   3145728
#define W16_WFC   4194304
#define W16_WPROJ 8388608

// ---------------- helpers ----------------
__device__ __forceinline__ void mma_tf32(float* d, const uint32_t* a, const uint32_t* b) {
    asm volatile(
        "mma.sync.aligned.m16n8k8.row.col.f32.tf32.tf32.f32 "
        "{%0,%1,%2,%3}, {%4,%5,%6,%7}, {%8,%9}, {%0,%1,%2,%3};\n"
        : "+f"(d[0]), "+f"(d[1]), "+f"(d[2]), "+f"(d[3])
        : "r"(a[0]), "r"(a[1]), "r"(a[2]), "r"(a[3]), "r"(b[0]), "r"(b[1]));
}

__device__ __forceinline__ void mma_f16(float* d, const uint32_t* a, const uint32_t* b) {
    asm volatile(
        "mma.sync.aligned.m16n8k16.row.col.f32.f16.f16.f32 "
        "{%0,%1,%2,%3}, {%4,%5,%6,%7}, {%8,%9}, {%0,%1,%2,%3};\n"
        : "+f"(d[0]), "+f"(d[1]), "+f"(d[2]), "+f"(d[3])
        : "r"(a[0]), "r"(a[1]), "r"(a[2]), "r"(a[3]), "r"(b[0]), "r"(b[1]));
}

__device__ __forceinline__ void ldsm4(uint32_t& r0, uint32_t& r1, uint32_t& r2, uint32_t& r3,
                                      uint32_t addr) {
    asm volatile("ldmatrix.sync.aligned.m8n8.x4.shared.b16 {%0,%1,%2,%3}, [%4];"
                 : "=r"(r0), "=r"(r1), "=r"(r2), "=r"(r3) : "r"(addr));
}
__device__ __forceinline__ void ldsm4t(uint32_t& r0, uint32_t& r1, uint32_t& r2, uint32_t& r3,
                                       uint32_t addr) {
    asm volatile("ldmatrix.sync.aligned.m8n8.x4.trans.shared.b16 {%0,%1,%2,%3}, [%4];"
                 : "=r"(r0), "=r"(r1), "=r"(r2), "=r"(r3) : "r"(addr));
}

__device__ __forceinline__ void cp16(void* s, const void* g) {
    unsigned sa = (unsigned)__cvta_generic_to_shared(s);
    asm volatile("cp.async.cg.shared.global [%0], [%1], 16;\n" :: "r"(sa), "l"(g));
}
__device__ __forceinline__ void cp_commit() { asm volatile("cp.async.commit_group;\n"); }
__device__ __forceinline__ void cp_wait0()  { asm volatile("cp.async.wait_group 0;\n"); }

// ---------------- fp32 -> fp16 converter ----------------
__global__ void f2h_kernel(const float* __restrict__ src, __half* __restrict__ dst, int n) {
    int i = (blockIdx.x * blockDim.x + threadIdx.x) * 4;
    if (i < n) {
        float4 v = *reinterpret_cast<const float4*>(src + i);
        __half2* d = reinterpret_cast<__half2*>(dst + i);
        d[0] = __floats2half2_rn(v.x, v.y);
        d[1] = __floats2half2_rn(v.z, v.w);
    }
}

// ---------------- LayerNorm: one block per token ----------------
template<bool WF, bool WH>
__global__ void ln_kernel(const float* __restrict__ x,
                          const float* __restrict__ gam,
                          const float* __restrict__ bet,
                          float* __restrict__ out,
                          __half* __restrict__ out16) {
    __shared__ float red[8];
    const int row = blockIdx.x;
    const int t = threadIdx.x;  // 256 threads, each handles 4 floats
    const float4* xr = reinterpret_cast<const float4*>(x) + (size_t)row * (DD / 4);
    float4 v = xr[t];

    float s = v.x + v.y + v.z + v.w;
    #pragma unroll
    for (int o = 16; o; o >>= 1) s += __shfl_down_sync(0xffffffffu, s, o);
    if ((t & 31) == 0) red[t >> 5] = s;
    __syncthreads();
    float tot = red[0] + red[1] + red[2] + red[3] + red[4] + red[5] + red[6] + red[7];
    const float mean = tot * (1.0f / DD);
    __syncthreads();

    float dx = v.x - mean, dy = v.y - mean, dz = v.z - mean, dw = v.w - mean;
    float sq = dx * dx + dy * dy + dz * dz + dw * dw;
    #pragma unroll
    for (int o = 16; o; o >>= 1) sq += __shfl_down_sync(0xffffffffu, sq, o);
    if ((t & 31) == 0) red[t >> 5] = sq;
    __syncthreads();
    float var = (red[0] + red[1] + red[2] + red[3] + red[4] + red[5] + red[6] + red[7]) * (1.0f / DD);
    const float r = rsqrtf(var + 1e-5f);

    const float4 gg = reinterpret_cast<const float4*>(gam)[t];
    const float4 bb = reinterpret_cast<const float4*>(bet)[t];
    float4 o4;
    o4.x = dx * r * gg.x + bb.x;
    o4.y = dy * r * gg.y + bb.y;
    o4.z = dz * r * gg.z + bb.z;
    o4.w = dw * r * gg.w + bb.w;
    if (WF)
        reinterpret_cast<float4*>(out)[(size_t)row * (DD / 4) + t] = o4;
    if (WH) {
        __half2* d = reinterpret_cast<__half2*>(out16 + (size_t)row * DD + t * 4);
        d[0] = __floats2half2_rn(o4.x, o4.y);
        d[1] = __floats2half2_rn(o4.z, o4.w);
    }
}

// ---------------- block saliency logits ----------------
__global__ void logits_kernel(const float* __restrict__ h,
                              const float* __restrict__ w_sal,
                              const float* __restrict__ b_sal,
                              float* __restrict__ logits) {
    __shared__ float red[8];
    const int t = threadIdx.x;  // 256
    const float4 w = reinterpret_cast<const float4*>(w_sal)[t];
    const float* base = h + (size_t)blockIdx.x * BKBLK * DD;
    float acc = 0.0f;
    for (int tok = 0; tok < BKBLK; tok++) {
        float4 hv = reinterpret_cast<const float4*>(base + (size_t)tok * DD)[t];
        acc += hv.x * w.x + hv.y * w.y + hv.z * w.z + hv.w * w.w;
    }
    #pragma unroll
    for (int o = 16; o; o >>= 1) acc += __shfl_down_sync(0xffffffffu, acc, o);
    if ((t & 31) == 0) red[t >> 5] = acc;
    __syncthreads();
    if (t == 0) {
        float tot = red[0] + red[1] + red[2] + red[3] + red[4] + red[5] + red[6] + red[7];
        logits[blockIdx.x] = tot * (1.0f / BKBLK) + b_sal[0];
    }
}

// ---------------- gumbel selection ----------------
__global__ void select_kernel(const float* __restrict__ logits,
                              const float* __restrict__ gu,
                              int* __restrict__ starts,
                              float* __restrict__ scales) {
    const int sb = blockIdx.x;           // s*B + b
    const int b = sb % BB;
    const int lane = threadIdx.x;        // 32

    float u0 = gu[sb * NB + lane];
    float u1 = gu[sb * NB + 32 + lane];
    float g0 = -logf(-logf(u0 + 1e-9f) + 1e-9f);
    float g1 = -logf(-logf(u1 + 1e-9f) + 1e-9f);
    float p0 = logits[b * NB + lane] + g0;       // TAU = 1
    float p1 = logits[b * NB + 32 + lane] + g1;

    float m = p0; int idx = lane;
    if (p1 > m) { m = p1; idx = lane + 32; }
    #pragma unroll
    for (int o = 16; o; o >>= 1) {
        float om = __shfl_down_sync(0xffffffffu, m, o);
        int   oi = __shfl_down_sync(0xffffffffu, idx, o);
        if (om > m || (om == m && oi < idx)) { m = om; idx = oi; }
    }
    m   = __shfl_sync(0xffffffffu, m, 0);
    idx = __shfl_sync(0xffffffffu, idx, 0);

    float se = expf(p0 - m) + expf(p1 - m);
    #pragma unroll
    for (int o = 16; o; o >>= 1) se += __shfl_down_sync(0xffffffffu, se, o);
    if (lane == 0) {
        float w = 1.0f / se;
        float scale = (1.0f + w) - w;
        int start = idx * BKBLK + BKBLK / 2 - WWIN / 2;
        if (start < 0) start = 0;
        if (start > LL - WWIN) start = LL - WWIN;
        starts[sb] = start;
        scales[sb] = scale;
    }
}

// ---------------- window gather into kv (fp16 out) ----------------
__global__ void gather_kernel(const float* __restrict__ h,
                              const int* __restrict__ starts,
                              const float* __restrict__ scales,
                              __half* __restrict__ kv) {
    const int row = blockIdx.x;          // b*640 + s*128 + w
    const int b = row / (SSEL * WWIN);
    const int r = row % (SSEL * WWIN);
    const int s = r / WWIN;
    const int w = r % WWIN;
    const int sb = s * BB + b;
    const int src = b * LL + starts[sb] + w;
    const float sc = scales[sb];
    const int t = threadIdx.x;           // 256
    float4 v = reinterpret_cast<const float4*>(h)[(size_t)src * (DD / 4) + t];
    __half2* d = reinterpret_cast<__half2*>(kv + (size_t)row * DD + t * 4);
    d[0] = __floats2half2_rn(v.x * sc, v.y * sc);
    d[1] = __floats2half2_rn(v.z * sc, v.w * sc);
}

// ---------------- V transpose: v[b*640+j][c] -> vt[b*1024+c][j] ----------
__global__ void vtrans_kernel(const float* __restrict__ v, float* __restrict__ vt) {
    __shared__ float t[32][33];
    const int b = blockIdx.z;
    const int j0 = blockIdx.x * 32, c0 = blockIdx.y * 32;
    const int tx = threadIdx.x, ty = threadIdx.y;  // 32 x 8
    #pragma unroll
    for (int i = 0; i < 32; i += 8)
        t[ty + i][tx] = v[((size_t)(b * NKEY + j0 + ty + i)) * DD + c0 + tx];
    __syncthreads();
    #pragma unroll
    for (int i = 0; i < 32; i += 8)
        vt[((size_t)(b * DD + c0 + ty + i)) * NKEY + j0 + tx] = t[tx][ty + i];
}

// ================= FP16 tensor-core GEMM =================
// C[M,N] = A[M,K] @ op(B) + bias (+gelu) (+res)
// BT=true:  B is [N,K] (NT). BT=false: B is [K,N] (NN).
// Block 128x128x32, 8 warps, warp 64x32, mma m16n8k16 f16, fp32 accum.
#define HA_STRIDE 40   // halfs; 80B rows -> ldmatrix segments (5r)%8 distinct
#define HB_NN_STRIDE 136 // halfs; 272B rows -> segments distinct
#define HSTG 5120      // halfs per tile stage

template<bool BT, bool GELU, bool RES, bool OUTH>
__global__ __launch_bounds__(256, 2)
void hgemm(const __half* __restrict__ A,
           const __half* __restrict__ B,
           const float* __restrict__ bias,
           const float* __restrict__ res,
           void* __restrict__ Cout,
           int M, int N, int K) {
    __shared__ __half sm[4 * HSTG];   // A stages 0,1 then B stages 0,1
    __half* As = sm;
    __half* Bs = sm + 2 * HSTG;
    const uint32_t sm_u32 = (uint32_t)__cvta_generic_to_shared(sm);

    const int tid  = threadIdx.x;
    const int lane = tid & 31;
    const int wid  = tid >> 5;
    const int wm = (wid & 1) * 64;
    const int wn = (wid >> 1) * 32;
    const int lm = lane >> 2;   // group id 0..7
    const int lk = lane & 3;    // thread in group 0..3
    const int m0 = blockIdx.y * 128;
    const int n0 = blockIdx.x * 128;

    float acc[4][4][4];
    #pragma unroll
    for (int i = 0; i < 4; i++)
        #pragma unroll
        for (int j = 0; j < 4; j++)
            #pragma unroll
            for (int f = 0; f < 4; f++) acc[i][j][f] = 0.0f;

    auto issue = [&](int k0, int buf) {
        #pragma unroll
        for (int j = 0; j < 2; j++) {
            int idx = tid + j * 256;
            int r = idx >> 2, c = (idx & 3) * 8;      // 4 granules per 32-half row
            cp16(&As[buf * HSTG + r * HA_STRIDE + c],
                 A + (size_t)(m0 + r) * K + k0 + c);
        }
        #pragma unroll
        for (int j = 0; j < 2; j++) {
            int idx = tid + j * 256;
            if (BT) {
                int r = idx >> 2, c = (idx & 3) * 8;
                cp16(&Bs[buf * HSTG + r * HA_STRIDE + c],
                     B + (size_t)(n0 + r) * K + k0 + c);
            } else {
                int r = idx >> 4, c = (idx & 15) * 8; // 16 granules per 128-half row
                cp16(&Bs[buf * HSTG + r * HB_NN_STRIDE + c],
                     B + (size_t)(k0 + r) * N + n0 + c);
            }
        }
    };

    issue(0, 0);
    cp_commit();
    cp_wait0();
    __syncthreads();

    // precomputed lane pieces for ldmatrix addressing (in halfs)
    const int a_row  = lane & 15;              // row within 16
    const int a_colh = ((lane >> 4) << 3);     // 0 or 8 (k half)
    const int g  = lane >> 3;                  // 0..3 group for trans
    const int lr = lane & 7;
    const int t_krow = ((g >> 1) << 3) + lr;   // k offset within 16
    const int t_ncol = (g & 1) << 3;           // 0 or 8

    const int T = K >> 5;  // K / 32
    for (int t = 0; t < T; t++) {
        const int buf = t & 1;
        if (t + 1 < T) { issue((t + 1) << 5, buf ^ 1); cp_commit(); }

        #pragma unroll
        for (int ks = 0; ks < 2; ks++) {
            uint32_t a[4][4];
            #pragma unroll
            for (int mi = 0; mi < 4; mi++) {
                uint32_t addr = sm_u32 + 2 * (buf * HSTG +
                    (wm + mi * 16 + a_row) * HA_STRIDE + ks * 16 + a_colh);
                ldsm4(a[mi][0], a[mi][1], a[mi][2], a[mi][3], addr);
            }
            uint32_t b[4][2];
            #pragma unroll
            for (int p = 0; p < 2; p++) {
                uint32_t r0, r1, r2, r3;
                if (BT) {
                    uint32_t addr = sm_u32 + 2 * (2 * HSTG + buf * HSTG +
                        (wn + p * 16 + a_row) * HA_STRIDE + ks * 16 + a_colh);
                    ldsm4(r0, r1, r2, r3, addr);
                    // r0 = n-rows 0-7 khalf0 (b0 blk0), r1 = n 8-15 khalf0 (b0 blk1)
                    // r2 = n 0-7 khalf1 (b1 blk0), r3 = n 8-15 khalf1 (b1 blk1)
                } else {
                    uint32_t addr = sm_u32 + 2 * (2 * HSTG + buf * HSTG +
                        (ks * 16 + t_krow) * HB_NN_STRIDE + wn + p * 16 + t_ncol);
                    ldsm4t(r0, r1, r2, r3, addr);
                    // groups: (k0-7,n0-7)->blk0.b0, (k0-7,n8-15)->blk1.b0,
                    //         (k8-15,n0-7)->blk0.b1, (k8-15,n8-15)->blk1.b1
                }
                b[p * 2 + 0][0] = r0; b[p * 2 + 0][1] = r2;
                b[p * 2 + 1][0] = r1; b[p * 2 + 1][1] = r3;
            }
            #pragma unroll
            for (int mi = 0; mi < 4; mi++)
                #pragma unroll
                for (int ni = 0; ni < 4; ni++)
                    mma_f16(acc[mi][ni], a[mi], b[ni]);
        }

        if (t + 1 < T) { cp_wait0(); __syncthreads(); }
    }

    // epilogue
    #pragma unroll
    for (int ni = 0; ni < 4; ni++) {
        const int cn = n0 + wn + ni * 8 + lk * 2;
        const float bx = bias[cn], by = bias[cn + 1];
        #pragma unroll
        for (int mi = 0; mi < 4; mi++) {
            const int rm = m0 + wm + mi * 16 + lm;
            float v0 = acc[mi][ni][0] + bx;
            float v1 = acc[mi][ni][1] + by;
            float v2 = acc[mi][ni][2] + bx;
            float v3 = acc[mi][ni][3] + by;
            if (GELU) {
                float vv[4] = {v0, v1, v2, v3};
                #pragma unroll
                for (int j = 0; j < 4; j++) {
                    float v = vv[j];
                    float u = 0.7978845608028654f * (v + 0.044715f * v * v * v);
                    vv[j] = 0.5f * v * (1.0f + tanhf(u));
                }
                v0 = vv[0]; v1 = vv[1]; v2 = vv[2]; v3 = vv[3];
            }
            if (RES) {
                const float* rf = (const float*)res;
                float2 r0 = *reinterpret_cast<const float2*>(rf + (size_t)rm * N + cn);
                float2 r1 = *reinterpret_cast<const float2*>(rf + (size_t)(rm + 8) * N + cn);
                v0 += r0.x; v1 += r0.y; v2 += r1.x; v3 += r1.y;
            }
            if (OUTH) {
                __half* C = (__half*)Cout;
                *reinterpret_cast<__half2*>(C + (size_t)rm * N + cn) = __floats2half2_rn(v0, v1);
                *reinterpret_cast<__half2*>(C + (size_t)(rm + 8) * N + cn) = __floats2half2_rn(v2, v3);
            } else {
                float* C = (float*)Cout;
                float2 o0 = {v0, v1}, o1 = {v2, v3};
                *reinterpret_cast<float2*>(C + (size_t)rm * N + cn) = o0;
                *reinterpret_cast<float2*>(C + (size_t)(rm + 8) * N + cn) = o1;
            }
        }
    }
}

// ================= flash attention (TF32 mma), fp16 output ===============
#define AT_STRIDE 68
#define AT_TILE (64 * AT_STRIDE)

__global__ __launch_bounds__(128)
void fattn_kernel(const float* __restrict__ q,
                  const float* __restrict__ k,
                  const float* __restrict__ vt,
                  __half* __restrict__ o) {
    extern __shared__ float smf[];
    float* Qs = smf;                 // [m][d]
    float* Ks = smf + AT_TILE;       // [j][d]
    float* Vs = smf + 2 * AT_TILE;   // [d][j]
    float* Ps = smf + 3 * AT_TILE;   // [m][j]

    const int bh = blockIdx.y;
    const int b = bh >> 4, hh = bh & 15;
    const int q0 = blockIdx.x * 64;
    const int tid = threadIdx.x, lane = tid & 31, wid = tid >> 5;
    const int lm = lane >> 2, lk = lane & 3;
    const int wm = wid * 16;

    {
        const float* qg = q + ((size_t)(b * LL + q0)) * DD + hh * DH;
        #pragma unroll
        for (int it = 0; it < 8; it++) {
            int idx = tid + it * 128;
            int r = idx >> 4, c = (idx & 15) * 4;
            float4 x = *reinterpret_cast<const float4*>(qg + (size_t)r * DD + c);
            x.x *= 0.125f; x.y *= 0.125f; x.z *= 0.125f; x.w *= 0.125f;
            *reinterpret_cast<float4*>(&Qs[r * AT_STRIDE + c]) = x;
        }
    }

    float mrow0 = -1e30f, mrow1 = -1e30f, lrow0 = 0.0f, lrow1 = 0.0f;
    float oacc[8][4];
    #pragma unroll
    for (int ni = 0; ni < 8; ni++)
        #pragma unroll
        for (int f = 0; f < 4; f++) oacc[ni][f] = 0.0f;

    const float* kg = k + ((size_t)(b * NKEY)) * DD + hh * DH;
    const float* vg = vt + ((size_t)(b * DD + hh * DH)) * NKEY;

    for (int kt = 0; kt < NKEY / 64; kt++) {
        __syncthreads();
        #pragma unroll
        for (int it = 0; it < 8; it++) {
            int idx = tid + it * 128;
            int r = idx >> 4, c = (idx & 15) * 4;
            *reinterpret_cast<float4*>(&Ks[r * AT_STRIDE + c]) =
                *reinterpret_cast<const float4*>(kg + (size_t)(kt * 64 + r) * DD + c);
            *reinterpret_cast<float4*>(&Vs[r * AT_STRIDE + c]) =
                *reinterpret_cast<const float4*>(vg + (size_t)r * NKEY + kt * 64 + c);
        }
        __syncthreads();

        float s[8][4];
        #pragma unroll
        for (int ni = 0; ni < 8; ni++)
            #pragma unroll
            for (int f = 0; f < 4; f++) s[ni][f] = 0.0f;

        #pragma unroll
        for (int kk = 0; kk < 8; kk++) {
            uint32_t a[4];
            const float* ap = &Qs[(wm + lm) * AT_STRIDE + kk * 8 + lk];
            a[0] = __float_as_uint(ap[0]);
            a[1] = __float_as_uint(ap[8 * AT_STRIDE]);
            a[2] = __float_as_uint(ap[4]);
            a[3] = __float_as_uint(ap[8 * AT_STRIDE + 4]);
            #pragma unroll
            for (int ni = 0; ni < 8; ni++) {
                uint32_t bfr[2];
                const float* bp = &Ks[(ni * 8 + lm) * AT_STRIDE + kk * 8 + lk];
                bfr[0] = __float_as_uint(bp[0]);
                bfr[1] = __float_as_uint(bp[4]);
                mma_tf32(s[ni], a, bfr);
            }
        }

        float rm0 = -1e30f, rm1 = -1e30f;
        #pragma unroll
        for (int ni = 0; ni < 8; ni++) {
            rm0 = fmaxf(rm0, fmaxf(s[ni][0], s[ni][1]));
            rm1 = fmaxf(rm1, fmaxf(s[ni][2], s[ni][3]));
        }
        rm0 = fmaxf(rm0, __shfl_xor_sync(0xffffffffu, rm0, 1));
        rm0 = fmaxf(rm0, __shfl_xor_sync(0xffffffffu, rm0, 2));
        rm1 = fmaxf(rm1, __shfl_xor_sync(0xffffffffu, rm1, 1));
        rm1 = fmaxf(rm1, __shfl_xor_sync(0xffffffffu, rm1, 2));

        float nm0 = fmaxf(mrow0, rm0), nm1 = fmaxf(mrow1, rm1);
        float al0 = __expf(mrow0 - nm0), al1 = __expf(mrow1 - nm1);
        mrow0 = nm0; mrow1 = nm1;

        float rs0 = 0.0f, rs1 = 0.0f;
        #pragma unroll
        for (int ni = 0; ni < 8; ni++) {
            s[ni][0] = __expf(s[ni][0] - nm0);
            s[ni][1] = __expf(s[ni][1] - nm0);
            s[ni][2] = __expf(s[ni][2] - nm1);
            s[ni][3] = __expf(s[ni][3] - nm1);
            rs0 += s[ni][0] + s[ni][1];
            rs1 += s[ni][2] + s[ni][3];
        }
        rs0 += __shfl_xor_sync(0xffffffffu, rs0, 1);
        rs0 += __shfl_xor_sync(0xffffffffu, rs0, 2);
        rs1 += __shfl_xor_sync(0xffffffffu, rs1, 1);
        rs1 += __shfl_xor_sync(0xffffffffu, rs1, 2);

        lrow0 = lrow0 * al0 + rs0;
        lrow1 = lrow1 * al1 + rs1;

        #pragma unroll
        for (int ni = 0; ni < 8; ni++) {
            oacc[ni][0] *= al0; oacc[ni][1] *= al0;
            oacc[ni][2] *= al1; oacc[ni][3] *= al1;
        }

        #pragma unroll
        for (int ni = 0; ni < 8; ni++) {
            float* pp = &Ps[(wm + lm) * AT_STRIDE + ni * 8 + 2 * lk];
            pp[0] = s[ni][0];
            pp[1] = s[ni][1];
            pp[8 * AT_STRIDE] = s[ni][2];
            pp[8 * AT_STRIDE + 1] = s[ni][3];
        }
        __syncwarp();

        #pragma unroll
        for (int kk = 0; kk < 8; kk++) {
            uint32_t a[4];
            const float* ap = &Ps[(wm + lm) * AT_STRIDE + kk * 8 + lk];
            a[0] = __float_as_uint(ap[0]);
            a[1] = __float_as_uint(ap[8 * AT_STRIDE]);
            a[2] = __float_as_uint(ap[4]);
            a[3] = __float_as_uint(ap[8 * AT_STRIDE + 4]);
            #pragma unroll
            for (int ni = 0; ni < 8; ni++) {
                uint32_t bfr[2];
                const float* bp = &Vs[(ni * 8 + lm) * AT_STRIDE + kk * 8 + lk];
                bfr[0] = __float_as_uint(bp[0]);
                bfr[1] = __float_as_uint(bp[4]);
                mma_tf32(oacc[ni], a, bfr);
            }
        }
    }

    const float inv0 = 1.0f / lrow0, inv1 = 1.0f / lrow1;
    __half* og = o + ((size_t)(b * LL + q0 + wm + lm)) * DD + hh * DH;
    #pragma unroll
    for (int ni = 0; ni < 8; ni++) {
        const int cc = ni * 8 + 2 * lk;
        *reinterpret_cast<__half2*>(og + cc) =
            __floats2half2_rn(oacc[ni][0] * inv0, oacc[ni][1] * inv0);
        *reinterpret_cast<__half2*>(og + (size_t)8 * DD + cc) =
            __floats2half2_rn(oacc[ni][2] * inv1, oacc[ni][3] * inv1);
    }
}

// ---------------- driver ----------------
extern "C" void kernel_launch(void* const* d_in, const int* in_sizes, int n_in,
                              void* d_out, int out_size) {
    const float* x        = (const float*)d_in[0];
    const float* gumbel_u = (const float*)d_in[1];
    const float* ln1_g    = (const float*)d_in[2];
    const float* ln1_b    = (const float*)d_in[3];
    const float* ln2_g    = (const float*)d_in[4];
    const float* ln2_b    = (const float*)d_in[5];
    const float* w_sal    = (const float*)d_in[6];
    const float* b_sal    = (const float*)d_in[7];
    const float* ipw      = (const float*)d_in[8];
    const float* ipb      = (const float*)d_in[9];
    const float* opw      = (const float*)d_in[10];
    const float* opb      = (const float*)d_in[11];
    const float* w_fc     = (const float*)d_in[12];
    const float* b_fc     = (const float*)d_in[13];
    const float* w_proj   = (const float*)d_in[14];
    const float* b_proj   = (const float*)d_in[15];
    float* out = (float*)d_out;

    void* p;
    cudaGetSymbolAddress(&p, g_h);      float*  h     = (float*)p;
    cudaGetSymbolAddress(&p, g_h16);    __half* h16   = (__half*)p;
    cudaGetSymbolAddress(&p, g_kv16);   __half* kv16  = (__half*)p;
    cudaGetSymbolAddress(&p, g_q);      float*  qb    = (float*)p;
    cudaGetSymbolAddress(&p, g_k);      float*  kb    = (float*)p;
    cudaGetSymbolAddress(&p, g_v);      float*  vb    = (float*)p;
    cudaGetSymbolAddress(&p, g_vt);     float*  vtb   = (float*)p;
    cudaGetSymbolAddress(&p, g_att16);  __half* att16 = (__half*)p;
    cudaGetSymbolAddress(&p, g_x2);     float*  x2    = (float*)p;
    cudaGetSymbolAddress(&p, g_h2_16);  __half* h2_16 = (__half*)p;
    cudaGetSymbolAddress(&p, g_ff16);   __half* ff16  = (__half*)p;
    cudaGetSymbolAddress(&p, g_w16);    __half* w16   = (__half*)p;
    cudaGetSymbolAddress(&p, g_logits); float*  logi  = (float*)p;
    cudaGetSymbolAddress(&p, g_start);  int*    st    = (int*)p;
    cudaGetSymbolAddress(&p, g_scale);  float*  sc    = (float*)p;

    const int ATTN_SMEM = 4 * AT_TILE * 4;  // 69632
    cudaFuncSetAttribute(fattn_kernel, cudaFuncAttributeMaxDynamicSharedMemorySize, ATTN_SMEM);

    // 0. weight conversion fp32 -> fp16
    f2h_kernel<<<(3 * DD * DD / 4 + 255) / 256, 256>>>(ipw,    w16 + W16_IPW,   3 * DD * DD);
    f2h_kernel<<<(DD * DD / 4 + 255) / 256, 256>>>(opw,        w16 + W16_OPW,   DD * DD);
    f2h_kernel<<<(DD * DFFN / 4 + 255) / 256, 256>>>(w_fc,     w16 + W16_WFC,   DD * DFFN);
    f2h_kernel<<<(DFFN * DD / 4 + 255) / 256, 256>>>(w_proj,   w16 + W16_WPROJ, DFFN * DD);
    // 1. LN1 (fp32 + fp16 outputs)
    ln_kernel<true, true><<<NTOK, 256>>>(x, ln1_g, ln1_b, h, h16);
    // 2. saliency logits
    logits_kernel<<<BB * NB, 256>>>(h, w_sal, b_sal, logi);
    // 3. gumbel window selection
    select_kernel<<<SSEL * BB, 32>>>(logi, gumbel_u, st, sc);
    // 4. gather windows -> kv (fp16)
    gather_kernel<<<MKV, 256>>>(h, st, sc, kv16);
    // 5. Q/K/V projections (NT, fp16 in, fp32 out)
    hgemm<true, false, false, false><<<dim3(DD / 128, NTOK / 128), 256>>>(
        h16, w16 + W16_IPW, ipb, nullptr, qb, NTOK, DD, DD);
    hgemm<true, false, false, false><<<dim3(DD / 128, MKV / 128), 256>>>(
        kv16, w16 + W16_IPW + (size_t)DD * DD, ipb + DD, nullptr, kb, MKV, DD, DD);
    hgemm<true, false, false, false><<<dim3(DD / 128, MKV / 128), 256>>>(
        kv16, w16 + W16_IPW + 2 * (size_t)DD * DD, ipb + 2 * DD, nullptr, vb, MKV, DD, DD);
    // 5b. transpose V
    vtrans_kernel<<<dim3(NKEY / 32, DD / 32, BB), dim3(32, 8)>>>(vb, vtb);
    // 6. attention (tf32 flash, fp16 out)
    fattn_kernel<<<dim3(LL / 64, BB * NH), 128, ATTN_SMEM>>>(qb, kb, vtb, att16);
    // 7. out proj + residual (fp32 out)
    hgemm<true, false, true, false><<<dim3(DD / 128, NTOK / 128), 256>>>(
        att16, w16 + W16_OPW, opb, x, x2, NTOK, DD, DD);
    // 8. LN2 (fp16 out only)
    ln_kernel<false, true><<<NTOK, 256>>>(x2, ln2_g, ln2_b, nullptr, h2_16);
    // 9. FFN up + gelu (NN, fp16 out)
    hgemm<false, true, false, true><<<dim3(DFFN / 128, NTOK / 128), 256>>>(
        h2_16, w16 + W16_WFC, b_fc, nullptr, ff16, NTOK, DFFN, DD);
    // 10. FFN down + residual (NN, fp32 out) -> out
    hgemm<false, false, true, false><<<dim3(DD / 128, NTOK / 128), 256>>>(
        ff16, w16 + W16_WPROJ, b_proj, x2, out, NTOK, DD, DFFN);
}

// round 7
// speedup vs baseline: 6.0065x; 1.0462x over previous
#include <cuda_runtime.h>
#include <cuda_fp16.h>
#include <math.h>
#include <stdint.h>

// ---------------- problem constants ----------------
#define DD     1024
#define LL     2048
#define BB     4
#define NH     16
#define DH     64
#define SSEL   5
#define WWIN   128
#define BKBLK  32
#define NB     64          // L / BK
#define NTOK   8192        // B*L
#define MKV    2560        // B*S*W
#define NKEY   640         // S*W keys per batch
#define DFFN   4096

// ---------------- scratch (device globals; no allocations allowed) --------
__device__ float  g_h   [NTOK * DD];     // fp32 h (logits + gather)
__device__ __half g_h16 [NTOK * DD];     // fp16 h (Q gemm A)
__device__ __half g_kv16[MKV  * DD];     // fp16 kv (K/V gemm A)
__device__ float  g_q   [NTOK * DD];
__device__ float  g_k   [MKV  * DD];
__device__ float  g_v   [MKV  * DD];
__device__ float  g_vt  [BB * DD * NKEY];
__device__ __half g_att16[NTOK * DD];    // fp16 attention out (out-proj A)
__device__ float  g_x2  [NTOK * DD];
__device__ __half g_h2_16[NTOK * DD];    // fp16 ln2 out (FFN1 A)
__device__ __half g_ff16 [NTOK * DFFN];  // fp16 FFN1 out (FFN2 A)
__device__ __half g_w16  [12582912];     // fp16 weights: ipw | opw | w_fc | w_proj
__device__ float  g_logits[BB * NB];
__device__ int    g_start [SSEL * BB];
__device__ float  g_scale [SSEL * BB];

#define W16_IPW   0
#define W16_OPW   3145728
#define W16_WFC   4194304
#define W16_WPROJ 8388608

// ---------------- helpers ----------------
__device__ __forceinline__ void mma_tf32(float* d, const uint32_t* a, const uint32_t* b) {
    asm volatile(
        "mma.sync.aligned.m16n8k8.row.col.f32.tf32.tf32.f32 "
        "{%0,%1,%2,%3}, {%4,%5,%6,%7}, {%8,%9}, {%0,%1,%2,%3};\n"
        : "+f"(d[0]), "+f"(d[1]), "+f"(d[2]), "+f"(d[3])
        : "r"(a[0]), "r"(a[1]), "r"(a[2]), "r"(a[3]), "r"(b[0]), "r"(b[1]));
}

__device__ __forceinline__ void mma_f16(float* d, const uint32_t* a, const uint32_t* b) {
    asm volatile(
        "mma.sync.aligned.m16n8k16.row.col.f32.f16.f16.f32 "
        "{%0,%1,%2,%3}, {%4,%5,%6,%7}, {%8,%9}, {%0,%1,%2,%3};\n"
        : "+f"(d[0]), "+f"(d[1]), "+f"(d[2]), "+f"(d[3])
        : "r"(a[0]), "r"(a[1]), "r"(a[2]), "r"(a[3]), "r"(b[0]), "r"(b[1]));
}

__device__ __forceinline__ void ldsm4(uint32_t& r0, uint32_t& r1, uint32_t& r2, uint32_t& r3,
                                      uint32_t addr) {
    asm volatile("ldmatrix.sync.aligned.m8n8.x4.shared.b16 {%0,%1,%2,%3}, [%4];"
                 : "=r"(r0), "=r"(r1), "=r"(r2), "=r"(r3) : "r"(addr));
}
__device__ __forceinline__ void ldsm4t(uint32_t& r0, uint32_t& r1, uint32_t& r2, uint32_t& r3,
                                       uint32_t addr) {
    asm volatile("ldmatrix.sync.aligned.m8n8.x4.trans.shared.b16 {%0,%1,%2,%3}, [%4];"
                 : "=r"(r0), "=r"(r1), "=r"(r2), "=r"(r3) : "r"(addr));
}

__device__ __forceinline__ void cp16(void* s, const void* g) {
    unsigned sa = (unsigned)__cvta_generic_to_shared(s);
    asm volatile("cp.async.cg.shared.global [%0], [%1], 16;\n" :: "r"(sa), "l"(g));
}
__device__ __forceinline__ void cp_commit() { asm volatile("cp.async.commit_group;\n"); }
__device__ __forceinline__ void cp_wait0()  { asm volatile("cp.async.wait_group 0;\n"); }

// ---------------- fp32 -> fp16 converter ----------------
__global__ void f2h_kernel(const float* __restrict__ src, __half* __restrict__ dst, int n) {
    int i = (blockIdx.x * blockDim.x + threadIdx.x) * 4;
    if (i < n) {
        float4 v = *reinterpret_cast<const float4*>(src + i);
        __half2* d = reinterpret_cast<__half2*>(dst + i);
        d[0] = __floats2half2_rn(v.x, v.y);
        d[1] = __floats2half2_rn(v.z, v.w);
    }
}

// ---------------- LayerNorm: one block per token ----------------
template<bool WF, bool WH>
__global__ void ln_kernel(const float* __restrict__ x,
                          const float* __restrict__ gam,
                          const float* __restrict__ bet,
                          float* __restrict__ out,
                          __half* __restrict__ out16) {
    __shared__ float red[8];
    const int row = blockIdx.x;
    const int t = threadIdx.x;  // 256
    const float4* xr = reinterpret_cast<const float4*>(x) + (size_t)row * (DD / 4);
    float4 v = xr[t];

    float s = v.x + v.y + v.z + v.w;
    #pragma unroll
    for (int o = 16; o; o >>= 1) s += __shfl_down_sync(0xffffffffu, s, o);
    if ((t & 31) == 0) red[t >> 5] = s;
    __syncthreads();
    float tot = red[0] + red[1] + red[2] + red[3] + red[4] + red[5] + red[6] + red[7];
    const float mean = tot * (1.0f / DD);
    __syncthreads();

    float dx = v.x - mean, dy = v.y - mean, dz = v.z - mean, dw = v.w - mean;
    float sq = dx * dx + dy * dy + dz * dz + dw * dw;
    #pragma unroll
    for (int o = 16; o; o >>= 1) sq += __shfl_down_sync(0xffffffffu, sq, o);
    if ((t & 31) == 0) red[t >> 5] = sq;
    __syncthreads();
    float var = (red[0] + red[1] + red[2] + red[3] + red[4] + red[5] + red[6] + red[7]) * (1.0f / DD);
    const float r = rsqrtf(var + 1e-5f);

    const float4 gg = reinterpret_cast<const float4*>(gam)[t];
    const float4 bb = reinterpret_cast<const float4*>(bet)[t];
    float4 o4;
    o4.x = dx * r * gg.x + bb.x;
    o4.y = dy * r * gg.y + bb.y;
    o4.z = dz * r * gg.z + bb.z;
    o4.w = dw * r * gg.w + bb.w;
    if (WF)
        reinterpret_cast<float4*>(out)[(size_t)row * (DD / 4) + t] = o4;
    if (WH) {
        __half2* d = reinterpret_cast<__half2*>(out16 + (size_t)row * DD + t * 4);
        d[0] = __floats2half2_rn(o4.x, o4.y);
        d[1] = __floats2half2_rn(o4.z, o4.w);
    }
}

// ---------------- block saliency logits ----------------
__global__ void logits_kernel(const float* __restrict__ h,
                              const float* __restrict__ w_sal,
                              const float* __restrict__ b_sal,
                              float* __restrict__ logits) {
    __shared__ float red[8];
    const int t = threadIdx.x;  // 256
    const float4 w = reinterpret_cast<const float4*>(w_sal)[t];
    const float* base = h + (size_t)blockIdx.x * BKBLK * DD;
    float acc = 0.0f;
    for (int tok = 0; tok < BKBLK; tok++) {
        float4 hv = reinterpret_cast<const float4*>(base + (size_t)tok * DD)[t];
        acc += hv.x * w.x + hv.y * w.y + hv.z * w.z + hv.w * w.w;
    }
    #pragma unroll
    for (int o = 16; o; o >>= 1) acc += __shfl_down_sync(0xffffffffu, acc, o);
    if ((t & 31) == 0) red[t >> 5] = acc;
    __syncthreads();
    if (t == 0) {
        float tot = red[0] + red[1] + red[2] + red[3] + red[4] + red[5] + red[6] + red[7];
        logits[blockIdx.x] = tot * (1.0f / BKBLK) + b_sal[0];
    }
}

// ---------------- gumbel selection ----------------
__global__ void select_kernel(const float* __restrict__ logits,
                              const float* __restrict__ gu,
                              int* __restrict__ starts,
                              float* __restrict__ scales) {
    const int sb = blockIdx.x;           // s*B + b
    const int b = sb % BB;
    const int lane = threadIdx.x;        // 32

    float u0 = gu[sb * NB + lane];
    float u1 = gu[sb * NB + 32 + lane];
    float g0 = -logf(-logf(u0 + 1e-9f) + 1e-9f);
    float g1 = -logf(-logf(u1 + 1e-9f) + 1e-9f);
    float p0 = logits[b * NB + lane] + g0;       // TAU = 1
    float p1 = logits[b * NB + 32 + lane] + g1;

    float m = p0; int idx = lane;
    if (p1 > m) { m = p1; idx = lane + 32; }
    #pragma unroll
    for (int o = 16; o; o >>= 1) {
        float om = __shfl_down_sync(0xffffffffu, m, o);
        int   oi = __shfl_down_sync(0xffffffffu, idx, o);
        if (om > m || (om == m && oi < idx)) { m = om; idx = oi; }
    }
    m   = __shfl_sync(0xffffffffu, m, 0);
    idx = __shfl_sync(0xffffffffu, idx, 0);

    float se = expf(p0 - m) + expf(p1 - m);
    #pragma unroll
    for (int o = 16; o; o >>= 1) se += __shfl_down_sync(0xffffffffu, se, o);
    if (lane == 0) {
        float w = 1.0f / se;
        float scale = (1.0f + w) - w;
        int start = idx * BKBLK + BKBLK / 2 - WWIN / 2;
        if (start < 0) start = 0;
        if (start > LL - WWIN) start = LL - WWIN;
        starts[sb] = start;
        scales[sb] = scale;
    }
}

// ---------------- window gather into kv (fp16 out) ----------------
__global__ void gather_kernel(const float* __restrict__ h,
                              const int* __restrict__ starts,
                              const float* __restrict__ scales,
                              __half* __restrict__ kv) {
    const int row = blockIdx.x;          // b*640 + s*128 + w
    const int b = row / (SSEL * WWIN);
    const int r = row % (SSEL * WWIN);
    const int s = r / WWIN;
    const int w = r % WWIN;
    const int sb = s * BB + b;
    const int src = b * LL + starts[sb] + w;
    const float sc = scales[sb];
    const int t = threadIdx.x;           // 256
    float4 v = reinterpret_cast<const float4*>(h)[(size_t)src * (DD / 4) + t];
    __half2* d = reinterpret_cast<__half2*>(kv + (size_t)row * DD + t * 4);
    d[0] = __floats2half2_rn(v.x * sc, v.y * sc);
    d[1] = __floats2half2_rn(v.z * sc, v.w * sc);
}

// ---------------- V transpose: v[b*640+j][c] -> vt[b*1024+c][j] ----------
__global__ void vtrans_kernel(const float* __restrict__ v, float* __restrict__ vt) {
    __shared__ float t[32][33];
    const int b = blockIdx.z;
    const int j0 = blockIdx.x * 32, c0 = blockIdx.y * 32;
    const int tx = threadIdx.x, ty = threadIdx.y;  // 32 x 8
    #pragma unroll
    for (int i = 0; i < 32; i += 8)
        t[ty + i][tx] = v[((size_t)(b * NKEY + j0 + ty + i)) * DD + c0 + tx];
    __syncthreads();
    #pragma unroll
    for (int i = 0; i < 32; i += 8)
        vt[((size_t)(b * DD + c0 + ty + i)) * NKEY + j0 + tx] = t[tx][ty + i];
}

// ================= FP16 tensor-core GEMM (verbatim round-4) =================
#define HA_STRIDE 40     // halfs
#define HB_NN_STRIDE 136 // halfs
#define HSTG 5120        // halfs per tile stage

template<bool BT, bool GELU, bool RES, bool OUTH>
__global__ __launch_bounds__(256, 2)
void hgemm(const __half* __restrict__ A,
           const __half* __restrict__ B,
           const float* __restrict__ bias,
           const float* __restrict__ res,
           void* __restrict__ Cout,
           int M, int N, int K) {
    __shared__ __half sm[4 * HSTG];
    __half* As = sm;
    __half* Bs = sm + 2 * HSTG;
    const uint32_t sm_u32 = (uint32_t)__cvta_generic_to_shared(sm);

    const int tid  = threadIdx.x;
    const int lane = tid & 31;
    const int wid  = tid >> 5;
    const int wm = (wid & 1) * 64;
    const int wn = (wid >> 1) * 32;
    const int lm = lane >> 2;
    const int lk = lane & 3;
    const int m0 = blockIdx.y * 128;
    const int n0 = blockIdx.x * 128;

    float acc[4][4][4];
    #pragma unroll
    for (int i = 0; i < 4; i++)
        #pragma unroll
        for (int j = 0; j < 4; j++)
            #pragma unroll
            for (int f = 0; f < 4; f++) acc[i][j][f] = 0.0f;

    auto issue = [&](int k0, int buf) {
        #pragma unroll
        for (int j = 0; j < 2; j++) {
            int idx = tid + j * 256;
            int r = idx >> 2, c = (idx & 3) * 8;
            cp16(&As[buf * HSTG + r * HA_STRIDE + c],
                 A + (size_t)(m0 + r) * K + k0 + c);
        }
        #pragma unroll
        for (int j = 0; j < 2; j++) {
            int idx = tid + j * 256;
            if (BT) {
                int r = idx >> 2, c = (idx & 3) * 8;
                cp16(&Bs[buf * HSTG + r * HA_STRIDE + c],
                     B + (size_t)(n0 + r) * K + k0 + c);
            } else {
                int r = idx >> 4, c = (idx & 15) * 8;
                cp16(&Bs[buf * HSTG + r * HB_NN_STRIDE + c],
                     B + (size_t)(k0 + r) * N + n0 + c);
            }
        }
    };

    issue(0, 0);
    cp_commit();
    cp_wait0();
    __syncthreads();

    const int a_row  = lane & 15;
    const int a_colh = ((lane >> 4) << 3);
    const int g  = lane >> 3;
    const int lr = lane & 7;
    const int t_krow = ((g >> 1) << 3) + lr;
    const int t_ncol = (g & 1) << 3;

    const int T = K >> 5;
    for (int t = 0; t < T; t++) {
        const int buf = t & 1;
        if (t + 1 < T) { issue((t + 1) << 5, buf ^ 1); cp_commit(); }

        #pragma unroll
        for (int ks = 0; ks < 2; ks++) {
            uint32_t a[4][4];
            #pragma unroll
            for (int mi = 0; mi < 4; mi++) {
                uint32_t addr = sm_u32 + 2 * (buf * HSTG +
                    (wm + mi * 16 + a_row) * HA_STRIDE + ks * 16 + a_colh);
                ldsm4(a[mi][0], a[mi][1], a[mi][2], a[mi][3], addr);
            }
            uint32_t b[4][2];
            #pragma unroll
            for (int p = 0; p < 2; p++) {
                uint32_t r0, r1, r2, r3;
                if (BT) {
                    uint32_t addr = sm_u32 + 2 * (2 * HSTG + buf * HSTG +
                        (wn + p * 16 + a_row) * HA_STRIDE + ks * 16 + a_colh);
                    ldsm4(r0, r1, r2, r3, addr);
                } else {
                    uint32_t addr = sm_u32 + 2 * (2 * HSTG + buf * HSTG +
                        (ks * 16 + t_krow) * HB_NN_STRIDE + wn + p * 16 + t_ncol);
                    ldsm4t(r0, r1, r2, r3, addr);
                }
                b[p * 2 + 0][0] = r0; b[p * 2 + 0][1] = r2;
                b[p * 2 + 1][0] = r1; b[p * 2 + 1][1] = r3;
            }
            #pragma unroll
            for (int mi = 0; mi < 4; mi++)
                #pragma unroll
                for (int ni = 0; ni < 4; ni++)
                    mma_f16(acc[mi][ni], a[mi], b[ni]);
        }

        if (t + 1 < T) { cp_wait0(); __syncthreads(); }
    }

    #pragma unroll
    for (int ni = 0; ni < 4; ni++) {
        const int cn = n0 + wn + ni * 8 + lk * 2;
        const float bx = bias[cn], by = bias[cn + 1];
        #pragma unroll
        for (int mi = 0; mi < 4; mi++) {
            const int rm = m0 + wm + mi * 16 + lm;
            float v0 = acc[mi][ni][0] + bx;
            float v1 = acc[mi][ni][1] + by;
            float v2 = acc[mi][ni][2] + bx;
            float v3 = acc[mi][ni][3] + by;
            if (GELU) {
                float vv[4] = {v0, v1, v2, v3};
                #pragma unroll
                for (int j = 0; j < 4; j++) {
                    float v = vv[j];
                    float u = 0.7978845608028654f * (v + 0.044715f * v * v * v);
                    vv[j] = 0.5f * v * (1.0f + tanhf(u));
                }
                v0 = vv[0]; v1 = vv[1]; v2 = vv[2]; v3 = vv[3];
            }
            if (RES) {
                const float* rf = (const float*)res;
                float2 r0 = *reinterpret_cast<const float2*>(rf + (size_t)rm * N + cn);
                float2 r1 = *reinterpret_cast<const float2*>(rf + (size_t)(rm + 8) * N + cn);
                v0 += r0.x; v1 += r0.y; v2 += r1.x; v3 += r1.y;
            }
            if (OUTH) {
                __half* C = (__half*)Cout;
                *reinterpret_cast<__half2*>(C + (size_t)rm * N + cn) = __floats2half2_rn(v0, v1);
                *reinterpret_cast<__half2*>(C + (size_t)(rm + 8) * N + cn) = __floats2half2_rn(v2, v3);
            } else {
                float* C = (float*)Cout;
                float2 o0 = {v0, v1}, o1 = {v2, v3};
                *reinterpret_cast<float2*>(C + (size_t)rm * N + cn) = o0;
                *reinterpret_cast<float2*>(C + (size_t)(rm + 8) * N + cn) = o1;
            }
        }
    }
}

// ============ fused QKV GEMM (NT, fp32 out) — self-contained copy ============
// grid (8, 104): y<64 -> Q (A=h16, M=NTOK), y<84 -> K, else V (A=kv16, M=MKV).
__global__ __launch_bounds__(256, 2)
void hgemm_qkv(const __half* __restrict__ h16,
               const __half* __restrict__ kv16,
               const __half* __restrict__ ipw16,
               const float* __restrict__ ipb,
               float* __restrict__ qo,
               float* __restrict__ ko,
               float* __restrict__ vo) {
    __shared__ __half sm[4 * HSTG];
    __half* As = sm;
    __half* Bs = sm + 2 * HSTG;
    const uint32_t sm_u32 = (uint32_t)__cvta_generic_to_shared(sm);

    const int y = blockIdx.y;
    int seg, my;
    if (y < 64)      { seg = 0; my = y; }
    else if (y < 84) { seg = 1; my = y - 64; }
    else             { seg = 2; my = y - 84; }
    const __half* A = (seg == 0) ? h16 : kv16;
    const __half* B = ipw16 + (size_t)seg * DD * DD;
    const float* bias = ipb + seg * DD;
    float* C = (seg == 0) ? qo : ((seg == 1) ? ko : vo);
    const int K = DD, N = DD;
    const int m0 = my * 128;
    const int n0 = blockIdx.x * 128;

    const int tid  = threadIdx.x;
    const int lane = tid & 31;
    const int wid  = tid >> 5;
    const int wm = (wid & 1) * 64;
    const int wn = (wid >> 1) * 32;
    const int lm = lane >> 2;
    const int lk = lane & 3;

    float acc[4][4][4];
    #pragma unroll
    for (int i = 0; i < 4; i++)
        #pragma unroll
        for (int j = 0; j < 4; j++)
            #pragma unroll
            for (int f = 0; f < 4; f++) acc[i][j][f] = 0.0f;

    auto issue = [&](int k0, int buf) {
        #pragma unroll
        for (int j = 0; j < 2; j++) {
            int idx = tid + j * 256;
            int r = idx >> 2, c = (idx & 3) * 8;
            cp16(&As[buf * HSTG + r * HA_STRIDE + c],
                 A + (size_t)(m0 + r) * K + k0 + c);
        }
        #pragma unroll
        for (int j = 0; j < 2; j++) {
            int idx = tid + j * 256;
            int r = idx >> 2, c = (idx & 3) * 8;
            cp16(&Bs[buf * HSTG + r * HA_STRIDE + c],
                 B + (size_t)(n0 + r) * K + k0 + c);
        }
    };

    issue(0, 0);
    cp_commit();
    cp_wait0();
    __syncthreads();

    const int a_row  = lane & 15;
    const int a_colh = ((lane >> 4) << 3);

    const int T = K >> 5;
    for (int t = 0; t < T; t++) {
        const int buf = t & 1;
        if (t + 1 < T) { issue((t + 1) << 5, buf ^ 1); cp_commit(); }

        #pragma unroll
        for (int ks = 0; ks < 2; ks++) {
            uint32_t a[4][4];
            #pragma unroll
            for (int mi = 0; mi < 4; mi++) {
                uint32_t addr = sm_u32 + 2 * (buf * HSTG +
                    (wm + mi * 16 + a_row) * HA_STRIDE + ks * 16 + a_colh);
                ldsm4(a[mi][0], a[mi][1], a[mi][2], a[mi][3], addr);
            }
            uint32_t b[4][2];
            #pragma unroll
            for (int p = 0; p < 2; p++) {
                uint32_t r0, r1, r2, r3;
                uint32_t addr = sm_u32 + 2 * (2 * HSTG + buf * HSTG +
                    (wn + p * 16 + a_row) * HA_STRIDE + ks * 16 + a_colh);
                ldsm4(r0, r1, r2, r3, addr);
                b[p * 2 + 0][0] = r0; b[p * 2 + 0][1] = r2;
                b[p * 2 + 1][0] = r1; b[p * 2 + 1][1] = r3;
            }
            #pragma unroll
            for (int mi = 0; mi < 4; mi++)
                #pragma unroll
                for (int ni = 0; ni < 4; ni++)
                    mma_f16(acc[mi][ni], a[mi], b[ni]);
        }

        if (t + 1 < T) { cp_wait0(); __syncthreads(); }
    }

    #pragma unroll
    for (int ni = 0; ni < 4; ni++) {
        const int cn = n0 + wn + ni * 8 + lk * 2;
        const float bx = bias[cn], by = bias[cn + 1];
        #pragma unroll
        for (int mi = 0; mi < 4; mi++) {
            const int rm = m0 + wm + mi * 16 + lm;
            float2 o0 = {acc[mi][ni][0] + bx, acc[mi][ni][1] + by};
            float2 o1 = {acc[mi][ni][2] + bx, acc[mi][ni][3] + by};
            *reinterpret_cast<float2*>(C + (size_t)rm * N + cn) = o0;
            *reinterpret_cast<float2*>(C + (size_t)(rm + 8) * N + cn) = o1;
        }
    }
}

// ================= flash attention (TF32 mma), fp16 output ===============
#define AT_STRIDE 68
#define AT_TILE (64 * AT_STRIDE)

__global__ __launch_bounds__(128)
void fattn_kernel(const float* __restrict__ q,
                  const float* __restrict__ k,
                  const float* __restrict__ vt,
                  __half* __restrict__ o) {
    extern __shared__ float smf[];
    float* Qs = smf;                 // [m][d]
    float* Ks = smf + AT_TILE;       // [j][d]
    float* Vs = smf + 2 * AT_TILE;   // [d][j]
    float* Ps = smf + 3 * AT_TILE;   // [m][j]

    const int bh = blockIdx.y;
    const int b = bh >> 4, hh = bh & 15;
    const int q0 = blockIdx.x * 64;
    const int tid = threadIdx.x, lane = tid & 31, wid = tid >> 5;
    const int lm = lane >> 2, lk = lane & 3;
    const int wm = wid * 16;

    {
        const float* qg = q + ((size_t)(b * LL + q0)) * DD + hh * DH;
        #pragma unroll
        for (int it = 0; it < 8; it++) {
            int idx = tid + it * 128;
            int r = idx >> 4, c = (idx & 15) * 4;
            float4 x = *reinterpret_cast<const float4*>(qg + (size_t)r * DD + c);
            x.x *= 0.125f; x.y *= 0.125f; x.z *= 0.125f; x.w *= 0.125f;
            *reinterpret_cast<float4*>(&Qs[r * AT_STRIDE + c]) = x;
        }
    }

    float mrow0 = -1e30f, mrow1 = -1e30f, lrow0 = 0.0f, lrow1 = 0.0f;
    float oacc[8][4];
    #pragma unroll
    for (int ni = 0; ni < 8; ni++)
        #pragma unroll
        for (int f = 0; f < 4; f++) oacc[ni][f] = 0.0f;

    const float* kg = k + ((size_t)(b * NKEY)) * DD + hh * DH;
    const float* vg = vt + ((size_t)(b * DD + hh * DH)) * NKEY;

    for (int kt = 0; kt < NKEY / 64; kt++) {
        __syncthreads();
        #pragma unroll
        for (int it = 0; it < 8; it++) {
            int idx = tid + it * 128;
            int r = idx >> 4, c = (idx & 15) * 4;
            *reinterpret_cast<float4*>(&Ks[r * AT_STRIDE + c]) =
                *reinterpret_cast<const float4*>(kg + (size_t)(kt * 64 + r) * DD + c);
            *reinterpret_cast<float4*>(&Vs[r * AT_STRIDE + c]) =
                *reinterpret_cast<const float4*>(vg + (size_t)r * NKEY + kt * 64 + c);
        }
        __syncthreads();

        float s[8][4];
        #pragma unroll
        for (int ni = 0; ni < 8; ni++)
            #pragma unroll
            for (int f = 0; f < 4; f++) s[ni][f] = 0.0f;

        #pragma unroll
        for (int kk = 0; kk < 8; kk++) {
            uint32_t a[4];
            const float* ap = &Qs[(wm + lm) * AT_STRIDE + kk * 8 + lk];
            a[0] = __float_as_uint(ap[0]);
            a[1] = __float_as_uint(ap[8 * AT_STRIDE]);
            a[2] = __float_as_uint(ap[4]);
            a[3] = __float_as_uint(ap[8 * AT_STRIDE + 4]);
            #pragma unroll
            for (int ni = 0; ni < 8; ni++) {
                uint32_t bfr[2];
                const float* bp = &Ks[(ni * 8 + lm) * AT_STRIDE + kk * 8 + lk];
                bfr[0] = __float_as_uint(bp[0]);
                bfr[1] = __float_as_uint(bp[4]);
                mma_tf32(s[ni], a, bfr);
            }
        }

        float rm0 = -1e30f, rm1 = -1e30f;
        #pragma unroll
        for (int ni = 0; ni < 8; ni++) {
            rm0 = fmaxf(rm0, fmaxf(s[ni][0], s[ni][1]));
            rm1 = fmaxf(rm1, fmaxf(s[ni][2], s[ni][3]));
        }
        rm0 = fmaxf(rm0, __shfl_xor_sync(0xffffffffu, rm0, 1));
        rm0 = fmaxf(rm0, __shfl_xor_sync(0xffffffffu, rm0, 2));
        rm1 = fmaxf(rm1, __shfl_xor_sync(0xffffffffu, rm1, 1));
        rm1 = fmaxf(rm1, __shfl_xor_sync(0xffffffffu, rm1, 2));

        float nm0 = fmaxf(mrow0, rm0), nm1 = fmaxf(mrow1, rm1);
        float al0 = __expf(mrow0 - nm0), al1 = __expf(mrow1 - nm1);
        mrow0 = nm0; mrow1 = nm1;

        float rs0 = 0.0f, rs1 = 0.0f;
        #pragma unroll
        for (int ni = 0; ni < 8; ni++) {
            s[ni][0] = __expf(s[ni][0] - nm0);
            s[ni][1] = __expf(s[ni][1] - nm0);
            s[ni][2] = __expf(s[ni][2] - nm1);
            s[ni][3] = __expf(s[ni][3] - nm1);
            rs0 += s[ni][0] + s[ni][1];
            rs1 += s[ni][2] + s[ni][3];
        }
        rs0 += __shfl_xor_sync(0xffffffffu, rs0, 1);
        rs0 += __shfl_xor_sync(0xffffffffu, rs0, 2);
        rs1 += __shfl_xor_sync(0xffffffffu, rs1, 1);
        rs1 += __shfl_xor_sync(0xffffffffu, rs1, 2);

        lrow0 = lrow0 * al0 + rs0;
        lrow1 = lrow1 * al1 + rs1;

        #pragma unroll
        for (int ni = 0; ni < 8; ni++) {
            oacc[ni][0] *= al0; oacc[ni][1] *= al0;
            oacc[ni][2] *= al1; oacc[ni][3] *= al1;
        }

        #pragma unroll
        for (int ni = 0; ni < 8; ni++) {
            float* pp = &Ps[(wm + lm) * AT_STRIDE + ni * 8 + 2 * lk];
            pp[0] = s[ni][0];
            pp[1] = s[ni][1];
            pp[8 * AT_STRIDE] = s[ni][2];
            pp[8 * AT_STRIDE + 1] = s[ni][3];
        }
        __syncwarp();

        #pragma unroll
        for (int kk = 0; kk < 8; kk++) {
            uint32_t a[4];
            const float* ap = &Ps[(wm + lm) * AT_STRIDE + kk * 8 + lk];
            a[0] = __float_as_uint(ap[0]);
            a[1] = __float_as_uint(ap[8 * AT_STRIDE]);
            a[2] = __float_as_uint(ap[4]);
            a[3] = __float_as_uint(ap[8 * AT_STRIDE + 4]);
            #pragma unroll
            for (int ni = 0; ni < 8; ni++) {
                uint32_t bfr[2];
                const float* bp = &Vs[(ni * 8 + lm) * AT_STRIDE + kk * 8 + lk];
                bfr[0] = __float_as_uint(bp[0]);
                bfr[1] = __float_as_uint(bp[4]);
                mma_tf32(oacc[ni], a, bfr);
            }
        }
    }

    const float inv0 = 1.0f / lrow0, inv1 = 1.0f / lrow1;
    __half* og = o + ((size_t)(b * LL + q0 + wm + lm)) * DD + hh * DH;
    #pragma unroll
    for (int ni = 0; ni < 8; ni++) {
        const int cc = ni * 8 + 2 * lk;
        *reinterpret_cast<__half2*>(og + cc) =
            __floats2half2_rn(oacc[ni][0] * inv0, oacc[ni][1] * inv0);
        *reinterpret_cast<__half2*>(og + (size_t)8 * DD + cc) =
            __floats2half2_rn(oacc[ni][2] * inv1, oacc[ni][3] * inv1);
    }
}

// ---------------- driver ----------------
extern "C" void kernel_launch(void* const* d_in, const int* in_sizes, int n_in,
                              void* d_out, int out_size) {
    const float* x        = (const float*)d_in[0];
    const float* gumbel_u = (const float*)d_in[1];
    const float* ln1_g    = (const float*)d_in[2];
    const float* ln1_b    = (const float*)d_in[3];
    const float* ln2_g    = (const float*)d_in[4];
    const float* ln2_b    = (const float*)d_in[5];
    const float* w_sal    = (const float*)d_in[6];
    const float* b_sal    = (const float*)d_in[7];
    const float* ipw      = (const float*)d_in[8];
    const float* ipb      = (const float*)d_in[9];
    const float* opw      = (const float*)d_in[10];
    const float* opb      = (const float*)d_in[11];
    const float* w_fc     = (const float*)d_in[12];
    const float* b_fc     = (const float*)d_in[13];
    const float* w_proj   = (const float*)d_in[14];
    const float* b_proj   = (const float*)d_in[15];
    float* out = (float*)d_out;

    void* p;
    cudaGetSymbolAddress(&p, g_h);      float*  h     = (float*)p;
    cudaGetSymbolAddress(&p, g_h16);    __half* h16   = (__half*)p;
    cudaGetSymbolAddress(&p, g_kv16);   __half* kv16  = (__half*)p;
    cudaGetSymbolAddress(&p, g_q);      float*  qb    = (float*)p;
    cudaGetSymbolAddress(&p, g_k);      float*  kb    = (float*)p;
    cudaGetSymbolAddress(&p, g_v);      float*  vb    = (float*)p;
    cudaGetSymbolAddress(&p, g_vt);     float*  vtb   = (float*)p;
    cudaGetSymbolAddress(&p, g_att16);  __half* att16 = (__half*)p;
    cudaGetSymbolAddress(&p, g_x2);     float*  x2    = (float*)p;
    cudaGetSymbolAddress(&p, g_h2_16);  __half* h2_16 = (__half*)p;
    cudaGetSymbolAddress(&p, g_ff16);   __half* ff16  = (__half*)p;
    cudaGetSymbolAddress(&p, g_w16);    __half* w16   = (__half*)p;
    cudaGetSymbolAddress(&p, g_logits); float*  logi  = (float*)p;
    cudaGetSymbolAddress(&p, g_start);  int*    st    = (int*)p;
    cudaGetSymbolAddress(&p, g_scale);  float*  sc    = (float*)p;

    const int ATTN_SMEM = 4 * AT_TILE * 4;  // 69632
    cudaFuncSetAttribute(fattn_kernel, cudaFuncAttributeMaxDynamicSharedMemorySize, ATTN_SMEM);

    // 0. weight prep: fp16 copies
    f2h_kernel<<<(3 * DD * DD / 4 + 255) / 256, 256>>>(ipw,  w16 + W16_IPW, 3 * DD * DD);
    f2h_kernel<<<(DD * DD / 4 + 255) / 256, 256>>>(opw,      w16 + W16_OPW, DD * DD);
    f2h_kernel<<<(DD * DFFN / 4 + 255) / 256, 256>>>(w_fc,   w16 + W16_WFC,   DD * DFFN);
    f2h_kernel<<<(DFFN * DD / 4 + 255) / 256, 256>>>(w_proj, w16 + W16_WPROJ, DFFN * DD);
    // 1. LN1
    ln_kernel<true, true><<<NTOK, 256>>>(x, ln1_g, ln1_b, h, h16);
    // 2-3. saliency + selection
    logits_kernel<<<BB * NB, 256>>>(h, w_sal, b_sal, logi);
    select_kernel<<<SSEL * BB, 32>>>(logi, gumbel_u, st, sc);
    // 4. gather -> kv16
    gather_kernel<<<MKV, 256>>>(h, st, sc, kv16);
    // 5. fused QKV projection (fp32 out)
    hgemm_qkv<<<dim3(DD / 128, 64 + 20 + 20), 256>>>(h16, kv16, w16 + W16_IPW, ipb,
                                                     qb, kb, vb);
    // 5b. V transpose (f32)
    vtrans_kernel<<<dim3(NKEY / 32, DD / 32, BB), dim3(32, 8)>>>(vb, vtb);
    // 6. attention (tf32 flash, fp16 out)
    fattn_kernel<<<dim3(LL / 64, BB * NH), 128, ATTN_SMEM>>>(qb, kb, vtb, att16);
    // 7. out proj + residual (fp32 out)
    hgemm<true, false, true, false><<<dim3(DD / 128, NTOK / 128), 256>>>(
        att16, w16 + W16_OPW, opb, x, x2, NTOK, DD, DD);
    // 8. LN2 (fp16 out)
    ln_kernel<false, true><<<NTOK, 256>>>(x2, ln2_g, ln2_b, nullptr, h2_16);
    // 9. FFN up + gelu (NN, fp16 out)
    hgemm<false, true, false, true><<<dim3(DFFN / 128, NTOK / 128), 256>>>(
        h2_16, w16 + W16_WFC, b_fc, nullptr, ff16, NTOK, DFFN, DD);
    // 10. FFN down + residual (NN, fp32 out) -> out
    hgemm<false, false, true, false><<<dim3(DD / 128, NTOK / 128), 256>>>(
        ff16, w16 + W16_WPROJ, b_proj, x2, out, NTOK, DD, DFFN);
}

// round 9
// speedup vs baseline: 6.5729x; 1.0943x over previous
#include <cuda_runtime.h>
#include <cuda_fp16.h>
#include <math.h>
#include <stdint.h>

// ---------------- problem constants ----------------
#define DD     1024
#define LL     2048
#define BB     4
#define NH     16
#define DH     64
#define SSEL   5
#define WWIN   128
#define BKBLK  32
#define NB     64          // L / BK
#define NTOK   8192        // B*L
#define MKV    2560        // B*S*W
#define NKEY   640         // S*W keys per batch
#define DFFN   4096

// ---------------- scratch (device globals; no allocations allowed) --------
__device__ float  g_h   [NTOK * DD];     // fp32 h (logits + gather)
__device__ __half g_h16 [NTOK * DD];     // fp16 h (Q gemm A)
__device__ __half g_kv16[MKV  * DD];     // fp16 kv (K/V gemm A)
__device__ float  g_q   [NTOK * DD];
__device__ float  g_k   [MKV  * DD];
__device__ float  g_v   [MKV  * DD];
__device__ float  g_vt  [BB * DD * NKEY];
__device__ __half g_att16[NTOK * DD];    // fp16 attention out (out-proj A)
__device__ float  g_x2  [NTOK * DD];
__device__ __half g_h2_16[NTOK * DD];    // fp16 ln2 out (FFN1 A)
__device__ __half g_ff16 [NTOK * DFFN];  // fp16 FFN1 out (FFN2 A)
__device__ __half g_w16  [12582912];     // fp16 weights: ipw | opw | w_fc | w_proj
__device__ float  g_logits[BB * NB];
__device__ int    g_start [SSEL * BB];
__device__ float  g_scale [SSEL * BB];

#define W16_IPW   0
#define W16_OPW   3145728
#define W16_WFC   4194304
#define W16_WPROJ 8388608
#define W16_TOTAL 12582912

// ---------------- helpers ----------------
__device__ __forceinline__ uint32_t h2u(__half2 h) {
    union { __half2 h; uint32_t u; } cvt;
    cvt.h = h;
    return cvt.u;
}

__device__ __forceinline__ void mma_f16(float* d, const uint32_t* a, const uint32_t* b) {
    asm volatile(
        "mma.sync.aligned.m16n8k16.row.col.f32.f16.f16.f32 "
        "{%0,%1,%2,%3}, {%4,%5,%6,%7}, {%8,%9}, {%0,%1,%2,%3};\n"
        : "+f"(d[0]), "+f"(d[1]), "+f"(d[2]), "+f"(d[3])
        : "r"(a[0]), "r"(a[1]), "r"(a[2]), "r"(a[3]), "r"(b[0]), "r"(b[1]));
}

__device__ __forceinline__ void ldsm4(uint32_t& r0, uint32_t& r1, uint32_t& r2, uint32_t& r3,
                                      uint32_t addr) {
    asm volatile("ldmatrix.sync.aligned.m8n8.x4.shared.b16 {%0,%1,%2,%3}, [%4];"
                 : "=r"(r0), "=r"(r1), "=r"(r2), "=r"(r3) : "r"(addr));
}
__device__ __forceinline__ void ldsm4t(uint32_t& r0, uint32_t& r1, uint32_t& r2, uint32_t& r3,
                                       uint32_t addr) {
    asm volatile("ldmatrix.sync.aligned.m8n8.x4.trans.shared.b16 {%0,%1,%2,%3}, [%4];"
                 : "=r"(r0), "=r"(r1), "=r"(r2), "=r"(r3) : "r"(addr));
}

__device__ __forceinline__ void cp16(void* s, const void* g) {
    unsigned sa = (unsigned)__cvta_generic_to_shared(s);
    asm volatile("cp.async.cg.shared.global [%0], [%1], 16;\n" :: "r"(sa), "l"(g));
}
__device__ __forceinline__ void cp_commit() { asm volatile("cp.async.commit_group;\n"); }
__device__ __forceinline__ void cp_wait0()  { asm volatile("cp.async.wait_group 0;\n"); }

// ---------------- fused fp32 -> fp16 weight conversion ----------------
__global__ void f2h_all_kernel(const float* __restrict__ ipw,
                               const float* __restrict__ opw,
                               const float* __restrict__ wfc,
                               const float* __restrict__ wproj,
                               __half* __restrict__ w16) {
    int i = (blockIdx.x * blockDim.x + threadIdx.x) * 4;
    if (i >= W16_TOTAL) return;
    const float* src;
    if (i < W16_OPW)        src = ipw + i;
    else if (i < W16_WFC)   src = opw + (i - W16_OPW);
    else if (i < W16_WPROJ) src = wfc + (i - W16_WFC);
    else                    src = wproj + (i - W16_WPROJ);
    float4 v = *reinterpret_cast<const float4*>(src);
    __half2* d = reinterpret_cast<__half2*>(w16 + i);
    d[0] = __floats2half2_rn(v.x, v.y);
    d[1] = __floats2half2_rn(v.z, v.w);
}

// ---------------- LayerNorm: one block per token ----------------
template<bool WF, bool WH>
__global__ void ln_kernel(const float* __restrict__ x,
                          const float* __restrict__ gam,
                          const float* __restrict__ bet,
                          float* __restrict__ out,
                          __half* __restrict__ out16) {
    __shared__ float red[8];
    const int row = blockIdx.x;
    const int t = threadIdx.x;  // 256
    const float4* xr = reinterpret_cast<const float4*>(x) + (size_t)row * (DD / 4);
    float4 v = xr[t];

    float s = v.x + v.y + v.z + v.w;
    #pragma unroll
    for (int o = 16; o; o >>= 1) s += __shfl_down_sync(0xffffffffu, s, o);
    if ((t & 31) == 0) red[t >> 5] = s;
    __syncthreads();
    float tot = red[0] + red[1] + red[2] + red[3] + red[4] + red[5] + red[6] + red[7];
    const float mean = tot * (1.0f / DD);
    __syncthreads();

    float dx = v.x - mean, dy = v.y - mean, dz = v.z - mean, dw = v.w - mean;
    float sq = dx * dx + dy * dy + dz * dz + dw * dw;
    #pragma unroll
    for (int o = 16; o; o >>= 1) sq += __shfl_down_sync(0xffffffffu, sq, o);
    if ((t & 31) == 0) red[t >> 5] = sq;
    __syncthreads();
    float var = (red[0] + red[1] + red[2] + red[3] + red[4] + red[5] + red[6] + red[7]) * (1.0f / DD);
    const float r = rsqrtf(var + 1e-5f);

    const float4 gg = reinterpret_cast<const float4*>(gam)[t];
    const float4 bb = reinterpret_cast<const float4*>(bet)[t];
    float4 o4;
    o4.x = dx * r * gg.x + bb.x;
    o4.y = dy * r * gg.y + bb.y;
    o4.z = dz * r * gg.z + bb.z;
    o4.w = dw * r * gg.w + bb.w;
    if (WF)
        reinterpret_cast<float4*>(out)[(size_t)row * (DD / 4) + t] = o4;
    if (WH) {
        __half2* d = reinterpret_cast<__half2*>(out16 + (size_t)row * DD + t * 4);
        d[0] = __floats2half2_rn(o4.x, o4.y);
        d[1] = __floats2half2_rn(o4.z, o4.w);
    }
}

// ---------------- block saliency logits ----------------
__global__ void logits_kernel(const float* __restrict__ h,
                              const float* __restrict__ w_sal,
                              const float* __restrict__ b_sal,
                              float* __restrict__ logits) {
    __shared__ float red[8];
    const int t = threadIdx.x;  // 256
    const float4 w = reinterpret_cast<const float4*>(w_sal)[t];
    const float* base = h + (size_t)blockIdx.x * BKBLK * DD;
    float acc = 0.0f;
    for (int tok = 0; tok < BKBLK; tok++) {
        float4 hv = reinterpret_cast<const float4*>(base + (size_t)tok * DD)[t];
        acc += hv.x * w.x + hv.y * w.y + hv.z * w.z + hv.w * w.w;
    }
    #pragma unroll
    for (int o = 16; o; o >>= 1) acc += __shfl_down_sync(0xffffffffu, acc, o);
    if ((t & 31) == 0) red[t >> 5] = acc;
    __syncthreads();
    if (t == 0) {
        float tot = red[0] + red[1] + red[2] + red[3] + red[4] + red[5] + red[6] + red[7];
        logits[blockIdx.x] = tot * (1.0f / BKBLK) + b_sal[0];
    }
}

// ---------------- gumbel selection ----------------
__global__ void select_kernel(const float* __restrict__ logits,
                              const float* __restrict__ gu,
                              int* __restrict__ starts,
                              float* __restrict__ scales) {
    const int sb = blockIdx.x;           // s*B + b
    const int b = sb % BB;
    const int lane = threadIdx.x;        // 32

    float u0 = gu[sb * NB + lane];
    float u1 = gu[sb * NB + 32 + lane];
    float g0 = -logf(-logf(u0 + 1e-9f) + 1e-9f);
    float g1 = -logf(-logf(u1 + 1e-9f) + 1e-9f);
    float p0 = logits[b * NB + lane] + g0;       // TAU = 1
    float p1 = logits[b * NB + 32 + lane] + g1;

    float m = p0; int idx = lane;
    if (p1 > m) { m = p1; idx = lane + 32; }
    #pragma unroll
    for (int o = 16; o; o >>= 1) {
        float om = __shfl_down_sync(0xffffffffu, m, o);
        int   oi = __shfl_down_sync(0xffffffffu, idx, o);
        if (om > m || (om == m && oi < idx)) { m = om; idx = oi; }
    }
    m   = __shfl_sync(0xffffffffu, m, 0);
    idx = __shfl_sync(0xffffffffu, idx, 0);

    float se = expf(p0 - m) + expf(p1 - m);
    #pragma unroll
    for (int o = 16; o; o >>= 1) se += __shfl_down_sync(0xffffffffu, se, o);
    if (lane == 0) {
        float w = 1.0f / se;
        float scale = (1.0f + w) - w;
        int start = idx * BKBLK + BKBLK / 2 - WWIN / 2;
        if (start < 0) start = 0;
        if (start > LL - WWIN) start = LL - WWIN;
        starts[sb] = start;
        scales[sb] = scale;
    }
}

// ---------------- window gather into kv (fp16 out) ----------------
__global__ void gather_kernel(const float* __restrict__ h,
                              const int* __restrict__ starts,
                              const float* __restrict__ scales,
                              __half* __restrict__ kv) {
    const int row = blockIdx.x;          // b*640 + s*128 + w
    const int b = row / (SSEL * WWIN);
    const int r = row % (SSEL * WWIN);
    const int s = r / WWIN;
    const int w = r % WWIN;
    const int sb = s * BB + b;
    const int src = b * LL + starts[sb] + w;
    const float sc = scales[sb];
    const int t = threadIdx.x;           // 256
    float4 v = reinterpret_cast<const float4*>(h)[(size_t)src * (DD / 4) + t];
    __half2* d = reinterpret_cast<__half2*>(kv + (size_t)row * DD + t * 4);
    d[0] = __floats2half2_rn(v.x * sc, v.y * sc);
    d[1] = __floats2half2_rn(v.z * sc, v.w * sc);
}

// ---------------- V transpose: v[b*640+j][c] -> vt[b*1024+c][j] ----------
__global__ void vtrans_kernel(const float* __restrict__ v, float* __restrict__ vt) {
    __shared__ float t[32][33];
    const int b = blockIdx.z;
    const int j0 = blockIdx.x * 32, c0 = blockIdx.y * 32;
    const int tx = threadIdx.x, ty = threadIdx.y;  // 32 x 8
    #pragma unroll
    for (int i = 0; i < 32; i += 8)
        t[ty + i][tx] = v[((size_t)(b * NKEY + j0 + ty + i)) * DD + c0 + tx];
    __syncthreads();
    #pragma unroll
    for (int i = 0; i < 32; i += 8)
        vt[((size_t)(b * DD + c0 + ty + i)) * NKEY + j0 + tx] = t[tx][ty + i];
}

// ================= FP16 tensor-core GEMM (verbatim round-4) =================
#define HA_STRIDE 40     // halfs
#define HB_NN_STRIDE 136 // halfs
#define HSTG 5120        // halfs per tile stage

template<bool BT, bool GELU, bool RES, bool OUTH>
__global__ __launch_bounds__(256, 2)
void hgemm(const __half* __restrict__ A,
           const __half* __restrict__ B,
           const float* __restrict__ bias,
           const float* __restrict__ res,
           void* __restrict__ Cout,
           int M, int N, int K) {
    __shared__ __half sm[4 * HSTG];
    __half* As = sm;
    __half* Bs = sm + 2 * HSTG;
    const uint32_t sm_u32 = (uint32_t)__cvta_generic_to_shared(sm);

    const int tid  = threadIdx.x;
    const int lane = tid & 31;
    const int wid  = tid >> 5;
    const int wm = (wid & 1) * 64;
    const int wn = (wid >> 1) * 32;
    const int lm = lane >> 2;
    const int lk = lane & 3;
    const int m0 = blockIdx.y * 128;
    const int n0 = blockIdx.x * 128;

    float acc[4][4][4];
    #pragma unroll
    for (int i = 0; i < 4; i++)
        #pragma unroll
        for (int j = 0; j < 4; j++)
            #pragma unroll
            for (int f = 0; f < 4; f++) acc[i][j][f] = 0.0f;

    auto issue = [&](int k0, int buf) {
        #pragma unroll
        for (int j = 0; j < 2; j++) {
            int idx = tid + j * 256;
            int r = idx >> 2, c = (idx & 3) * 8;
            cp16(&As[buf * HSTG + r * HA_STRIDE + c],
                 A + (size_t)(m0 + r) * K + k0 + c);
        }
        #pragma unroll
        for (int j = 0; j < 2; j++) {
            int idx = tid + j * 256;
            if (BT) {
                int r = idx >> 2, c = (idx & 3) * 8;
                cp16(&Bs[buf * HSTG + r * HA_STRIDE + c],
                     B + (size_t)(n0 + r) * K + k0 + c);
            } else {
                int r = idx >> 4, c = (idx & 15) * 8;
                cp16(&Bs[buf * HSTG + r * HB_NN_STRIDE + c],
                     B + (size_t)(k0 + r) * N + n0 + c);
            }
        }
    };

    issue(0, 0);
    cp_commit();
    cp_wait0();
    __syncthreads();

    const int a_row  = lane & 15;
    const int a_colh = ((lane >> 4) << 3);
    const int g  = lane >> 3;
    const int lr = lane & 7;
    const int t_krow = ((g >> 1) << 3) + lr;
    const int t_ncol = (g & 1) << 3;

    const int T = K >> 5;
    for (int t = 0; t < T; t++) {
        const int buf = t & 1;
        if (t + 1 < T) { issue((t + 1) << 5, buf ^ 1); cp_commit(); }

        #pragma unroll
        for (int ks = 0; ks < 2; ks++) {
            uint32_t a[4][4];
            #pragma unroll
            for (int mi = 0; mi < 4; mi++) {
                uint32_t addr = sm_u32 + 2 * (buf * HSTG +
                    (wm + mi * 16 + a_row) * HA_STRIDE + ks * 16 + a_colh);
                ldsm4(a[mi][0], a[mi][1], a[mi][2], a[mi][3], addr);
            }
            uint32_t b[4][2];
            #pragma unroll
            for (int p = 0; p < 2; p++) {
                uint32_t r0, r1, r2, r3;
                if (BT) {
                    uint32_t addr = sm_u32 + 2 * (2 * HSTG + buf * HSTG +
                        (wn + p * 16 + a_row) * HA_STRIDE + ks * 16 + a_colh);
                    ldsm4(r0, r1, r2, r3, addr);
                } else {
                    uint32_t addr = sm_u32 + 2 * (2 * HSTG + buf * HSTG +
                        (ks * 16 + t_krow) * HB_NN_STRIDE + wn + p * 16 + t_ncol);
                    ldsm4t(r0, r1, r2, r3, addr);
                }
                b[p * 2 + 0][0] = r0; b[p * 2 + 0][1] = r2;
                b[p * 2 + 1][0] = r1; b[p * 2 + 1][1] = r3;
            }
            #pragma unroll
            for (int mi = 0; mi < 4; mi++)
                #pragma unroll
                for (int ni = 0; ni < 4; ni++)
                    mma_f16(acc[mi][ni], a[mi], b[ni]);
        }

        if (t + 1 < T) { cp_wait0(); __syncthreads(); }
    }

    #pragma unroll
    for (int ni = 0; ni < 4; ni++) {
        const int cn = n0 + wn + ni * 8 + lk * 2;
        const float bx = bias[cn], by = bias[cn + 1];
        #pragma unroll
        for (int mi = 0; mi < 4; mi++) {
            const int rm = m0 + wm + mi * 16 + lm;
            float v0 = acc[mi][ni][0] + bx;
            float v1 = acc[mi][ni][1] + by;
            float v2 = acc[mi][ni][2] + bx;
            float v3 = acc[mi][ni][3] + by;
            if (GELU) {
                float vv[4] = {v0, v1, v2, v3};
                #pragma unroll
                for (int j = 0; j < 4; j++) {
                    float v = vv[j];
                    float u = 0.7978845608028654f * (v + 0.044715f * v * v * v);
                    vv[j] = 0.5f * v * (1.0f + tanhf(u));
                }
                v0 = vv[0]; v1 = vv[1]; v2 = vv[2]; v3 = vv[3];
            }
            if (RES) {
                const float* rf = (const float*)res;
                float2 r0 = *reinterpret_cast<const float2*>(rf + (size_t)rm * N + cn);
                float2 r1 = *reinterpret_cast<const float2*>(rf + (size_t)(rm + 8) * N + cn);
                v0 += r0.x; v1 += r0.y; v2 += r1.x; v3 += r1.y;
            }
            if (OUTH) {
                __half* C = (__half*)Cout;
                *reinterpret_cast<__half2*>(C + (size_t)rm * N + cn) = __floats2half2_rn(v0, v1);
                *reinterpret_cast<__half2*>(C + (size_t)(rm + 8) * N + cn) = __floats2half2_rn(v2, v3);
            } else {
                float* C = (float*)Cout;
                float2 o0 = {v0, v1}, o1 = {v2, v3};
                *reinterpret_cast<float2*>(C + (size_t)rm * N + cn) = o0;
                *reinterpret_cast<float2*>(C + (size_t)(rm + 8) * N + cn) = o1;
            }
        }
    }
}

// ============ fused QKV GEMM (NT, fp32 out) — verbatim round-7 ============
__global__ __launch_bounds__(256, 2)
void hgemm_qkv(const __half* __restrict__ h16,
               const __half* __restrict__ kv16,
               const __half* __restrict__ ipw16,
               const float* __restrict__ ipb,
               float* __restrict__ qo,
               float* __restrict__ ko,
               float* __restrict__ vo) {
    __shared__ __half sm[4 * HSTG];
    __half* As = sm;
    __half* Bs = sm + 2 * HSTG;
    const uint32_t sm_u32 = (uint32_t)__cvta_generic_to_shared(sm);

    const int y = blockIdx.y;
    int seg, my;
    if (y < 64)      { seg = 0; my = y; }
    else if (y < 84) { seg = 1; my = y - 64; }
    else             { seg = 2; my = y - 84; }
    const __half* A = (seg == 0) ? h16 : kv16;
    const __half* B = ipw16 + (size_t)seg * DD * DD;
    const float* bias = ipb + seg * DD;
    float* C = (seg == 0) ? qo : ((seg == 1) ? ko : vo);
    const int K = DD, N = DD;
    const int m0 = my * 128;
    const int n0 = blockIdx.x * 128;

    const int tid  = threadIdx.x;
    const int lane = tid & 31;
    const int wid  = tid >> 5;
    const int wm = (wid & 1) * 64;
    const int wn = (wid >> 1) * 32;
    const int lm = lane >> 2;
    const int lk = lane & 3;

    float acc[4][4][4];
    #pragma unroll
    for (int i = 0; i < 4; i++)
        #pragma unroll
        for (int j = 0; j < 4; j++)
            #pragma unroll
            for (int f = 0; f < 4; f++) acc[i][j][f] = 0.0f;

    auto issue = [&](int k0, int buf) {
        #pragma unroll
        for (int j = 0; j < 2; j++) {
            int idx = tid + j * 256;
            int r = idx >> 2, c = (idx & 3) * 8;
            cp16(&As[buf * HSTG + r * HA_STRIDE + c],
                 A + (size_t)(m0 + r) * K + k0 + c);
        }
        #pragma unroll
        for (int j = 0; j < 2; j++) {
            int idx = tid + j * 256;
            int r = idx >> 2, c = (idx & 3) * 8;
            cp16(&Bs[buf * HSTG + r * HA_STRIDE + c],
                 B + (size_t)(n0 + r) * K + k0 + c);
        }
    };

    issue(0, 0);
    cp_commit();
    cp_wait0();
    __syncthreads();

    const int a_row  = lane & 15;
    const int a_colh = ((lane >> 4) << 3);

    const int T = K >> 5;
    for (int t = 0; t < T; t++) {
        const int buf = t & 1;
        if (t + 1 < T) { issue((t + 1) << 5, buf ^ 1); cp_commit(); }

        #pragma unroll
        for (int ks = 0; ks < 2; ks++) {
            uint32_t a[4][4];
            #pragma unroll
            for (int mi = 0; mi < 4; mi++) {
                uint32_t addr = sm_u32 + 2 * (buf * HSTG +
                    (wm + mi * 16 + a_row) * HA_STRIDE + ks * 16 + a_colh);
                ldsm4(a[mi][0], a[mi][1], a[mi][2], a[mi][3], addr);
            }
            uint32_t b[4][2];
            #pragma unroll
            for (int p = 0; p < 2; p++) {
                uint32_t r0, r1, r2, r3;
                uint32_t addr = sm_u32 + 2 * (2 * HSTG + buf * HSTG +
                    (wn + p * 16 + a_row) * HA_STRIDE + ks * 16 + a_colh);
                ldsm4(r0, r1, r2, r3, addr);
                b[p * 2 + 0][0] = r0; b[p * 2 + 0][1] = r2;
                b[p * 2 + 1][0] = r1; b[p * 2 + 1][1] = r3;
            }
            #pragma unroll
            for (int mi = 0; mi < 4; mi++)
                #pragma unroll
                for (int ni = 0; ni < 4; ni++)
                    mma_f16(acc[mi][ni], a[mi], b[ni]);
        }

        if (t + 1 < T) { cp_wait0(); __syncthreads(); }
    }

    #pragma unroll
    for (int ni = 0; ni < 4; ni++) {
        const int cn = n0 + wn + ni * 8 + lk * 2;
        const float bx = bias[cn], by = bias[cn + 1];
        #pragma unroll
        for (int mi = 0; mi < 4; mi++) {
            const int rm = m0 + wm + mi * 16 + lm;
            float2 o0 = {acc[mi][ni][0] + bx, acc[mi][ni][1] + by};
            float2 o1 = {acc[mi][ni][2] + bx, acc[mi][ni][3] + by};
            *reinterpret_cast<float2*>(C + (size_t)rm * N + cn) = o0;
            *reinterpret_cast<float2*>(C + (size_t)(rm + 8) * N + cn) = o1;
        }
    }
}

// ============ flash attention: fp16 mma, fp32 inputs, fp16 output ==========
#define FA_STR 72   // halfs per smem row (64 + 8 pad); row pitch 144B

__global__ __launch_bounds__(128)
void fattn16_kernel(const float* __restrict__ q,
                    const float* __restrict__ k,
                    const float* __restrict__ vt,
                    __half* __restrict__ o) {
    __shared__ __half Qh[64 * FA_STR];
    __shared__ __half Kh[64 * FA_STR];
    __shared__ __half Vh[64 * FA_STR];
    __shared__ __half Ph[64 * FA_STR];
    const uint32_t Qu = (uint32_t)__cvta_generic_to_shared(Qh);
    const uint32_t Ku = (uint32_t)__cvta_generic_to_shared(Kh);
    const uint32_t Vu = (uint32_t)__cvta_generic_to_shared(Vh);
    const uint32_t Pu = (uint32_t)__cvta_generic_to_shared(Ph);

    const int bh = blockIdx.y;
    const int b = bh >> 4, hh = bh & 15;
    const int q0 = blockIdx.x * 64;
    const int tid = threadIdx.x, lane = tid & 31, wid = tid >> 5;
    const int lm = lane >> 2, lk = lane & 3;
    const int wm = wid * 16;

    const int a_row  = lane & 15;
    const int a_colh = ((lane >> 4) << 3);

    // load Q tile (fp32 -> fp16, scaled by 1/8)
    {
        const float* qg = q + ((size_t)(b * LL + q0)) * DD + hh * DH;
        #pragma unroll
        for (int it = 0; it < 8; it++) {
            int idx = tid + it * 128;
            int r = idx >> 4, c = (idx & 15) * 4;
            float4 x = *reinterpret_cast<const float4*>(qg + (size_t)r * DD + c);
            uint2 pk;
            pk.x = h2u(__floats2half2_rn(x.x * 0.125f, x.y * 0.125f));
            pk.y = h2u(__floats2half2_rn(x.z * 0.125f, x.w * 0.125f));
            *reinterpret_cast<uint2*>(&Qh[r * FA_STR + c]) = pk;  // 8B-aligned
        }
    }

    float mrow0 = -1e30f, mrow1 = -1e30f, lrow0 = 0.0f, lrow1 = 0.0f;
    float oacc[8][4];
    #pragma unroll
    for (int ni = 0; ni < 8; ni++)
        #pragma unroll
        for (int f = 0; f < 4; f++) oacc[ni][f] = 0.0f;

    const float* kg = k + ((size_t)(b * NKEY)) * DD + hh * DH;
    const float* vg = vt + ((size_t)(b * DD + hh * DH)) * NKEY;

    for (int kt = 0; kt < NKEY / 64; kt++) {
        __syncthreads();
        #pragma unroll
        for (int it = 0; it < 8; it++) {
            int idx = tid + it * 128;
            int r = idx >> 4, c = (idx & 15) * 4;
            float4 xk = *reinterpret_cast<const float4*>(kg + (size_t)(kt * 64 + r) * DD + c);
            uint2 pk;
            pk.x = h2u(__floats2half2_rn(xk.x, xk.y));
            pk.y = h2u(__floats2half2_rn(xk.z, xk.w));
            *reinterpret_cast<uint2*>(&Kh[r * FA_STR + c]) = pk;
            float4 xv = *reinterpret_cast<const float4*>(vg + (size_t)r * NKEY + kt * 64 + c);
            uint2 pv;
            pv.x = h2u(__floats2half2_rn(xv.x, xv.y));
            pv.y = h2u(__floats2half2_rn(xv.z, xv.w));
            *reinterpret_cast<uint2*>(&Vh[r * FA_STR + c]) = pv;
        }
        __syncthreads();

        // S = Q @ K^T (fp16 mma)
        float s[8][4];
        #pragma unroll
        for (int ni = 0; ni < 8; ni++)
            #pragma unroll
            for (int f = 0; f < 4; f++) s[ni][f] = 0.0f;

        #pragma unroll
        for (int kk = 0; kk < 4; kk++) {
            uint32_t a[4];
            ldsm4(a[0], a[1], a[2], a[3],
                  Qu + 2 * ((wm + a_row) * FA_STR + kk * 16 + a_colh));
            #pragma unroll
            for (int p = 0; p < 4; p++) {
                uint32_t r0, r1, r2, r3;
                ldsm4(r0, r1, r2, r3,
                      Ku + 2 * ((p * 16 + a_row) * FA_STR + kk * 16 + a_colh));
                uint32_t b0[2] = {r0, r2}, b1[2] = {r1, r3};
                mma_f16(s[p * 2 + 0], a, b0);
                mma_f16(s[p * 2 + 1], a, b1);
            }
        }

        // online softmax (rows lm, lm+8)
        float rm0 = -1e30f, rm1 = -1e30f;
        #pragma unroll
        for (int ni = 0; ni < 8; ni++) {
            rm0 = fmaxf(rm0, fmaxf(s[ni][0], s[ni][1]));
            rm1 = fmaxf(rm1, fmaxf(s[ni][2], s[ni][3]));
        }
        rm0 = fmaxf(rm0, __shfl_xor_sync(0xffffffffu, rm0, 1));
        rm0 = fmaxf(rm0, __shfl_xor_sync(0xffffffffu, rm0, 2));
        rm1 = fmaxf(rm1, __shfl_xor_sync(0xffffffffu, rm1, 1));
        rm1 = fmaxf(rm1, __shfl_xor_sync(0xffffffffu, rm1, 2));

        float nm0 = fmaxf(mrow0, rm0), nm1 = fmaxf(mrow1, rm1);
        float al0 = __expf(mrow0 - nm0), al1 = __expf(mrow1 - nm1);
        mrow0 = nm0; mrow1 = nm1;

        float rs0 = 0.0f, rs1 = 0.0f;
        #pragma unroll
        for (int ni = 0; ni < 8; ni++) {
            s[ni][0] = __expf(s[ni][0] - nm0);
            s[ni][1] = __expf(s[ni][1] - nm0);
            s[ni][2] = __expf(s[ni][2] - nm1);
            s[ni][3] = __expf(s[ni][3] - nm1);
            rs0 += s[ni][0] + s[ni][1];
            rs1 += s[ni][2] + s[ni][3];
        }
        rs0 += __shfl_xor_sync(0xffffffffu, rs0, 1);
        rs0 += __shfl_xor_sync(0xffffffffu, rs0, 2);
        rs1 += __shfl_xor_sync(0xffffffffu, rs1, 1);
        rs1 += __shfl_xor_sync(0xffffffffu, rs1, 2);

        lrow0 = lrow0 * al0 + rs0;
        lrow1 = lrow1 * al1 + rs1;

        #pragma unroll
        for (int ni = 0; ni < 8; ni++) {
            oacc[ni][0] *= al0; oacc[ni][1] *= al0;
            oacc[ni][2] *= al1; oacc[ni][3] *= al1;
        }

        // P -> smem fp16 (own warp rows only)
        #pragma unroll
        for (int ni = 0; ni < 8; ni++) {
            __half* pp = &Ph[(wm + lm) * FA_STR + ni * 8 + 2 * lk];
            *reinterpret_cast<__half2*>(pp) = __floats2half2_rn(s[ni][0], s[ni][1]);
            *reinterpret_cast<__half2*>(pp + 8 * FA_STR) = __floats2half2_rn(s[ni][2], s[ni][3]);
        }
        __syncwarp();

        // O += P @ V (fp16 mma; Vh is [d][j])
        #pragma unroll
        for (int kk = 0; kk < 4; kk++) {
            uint32_t a[4];
            ldsm4(a[0], a[1], a[2], a[3],
                  Pu + 2 * ((wm + a_row) * FA_STR + kk * 16 + a_colh));
            #pragma unroll
            for (int p = 0; p < 4; p++) {
                uint32_t r0, r1, r2, r3;
                ldsm4(r0, r1, r2, r3,
                      Vu + 2 * ((p * 16 + a_row) * FA_STR + kk * 16 + a_colh));
                uint32_t b0[2] = {r0, r2}, b1[2] = {r1, r3};
                mma_f16(oacc[p * 2 + 0], a, b0);
                mma_f16(oacc[p * 2 + 1], a, b1);
            }
        }
    }

    const float inv0 = 1.0f / lrow0, inv1 = 1.0f / lrow1;
    __half* og = o + ((size_t)(b * LL + q0 + wm + lm)) * DD + hh * DH;
    #pragma unroll
    for (int ni = 0; ni < 8; ni++) {
        const int cc = ni * 8 + 2 * lk;
        *reinterpret_cast<__half2*>(og + cc) =
            __floats2half2_rn(oacc[ni][0] * inv0, oacc[ni][1] * inv0);
        *reinterpret_cast<__half2*>(og + (size_t)8 * DD + cc) =
            __floats2half2_rn(oacc[ni][2] * inv1, oacc[ni][3] * inv1);
    }
}

// ---------------- driver ----------------
extern "C" void kernel_launch(void* const* d_in, const int* in_sizes, int n_in,
                              void* d_out, int out_size) {
    const float* x        = (const float*)d_in[0];
    const float* gumbel_u = (const float*)d_in[1];
    const float* ln1_g    = (const float*)d_in[2];
    const float* ln1_b    = (const float*)d_in[3];
    const float* ln2_g    = (const float*)d_in[4];
    const float* ln2_b    = (const float*)d_in[5];
    const float* w_sal    = (const float*)d_in[6];
    const float* b_sal    = (const float*)d_in[7];
    const float* ipw      = (const float*)d_in[8];
    const float* ipb      = (const float*)d_in[9];
    const float* opw      = (const float*)d_in[10];
    const float* opb      = (const float*)d_in[11];
    const float* w_fc     = (const float*)d_in[12];
    const float* b_fc     = (const float*)d_in[13];
    const float* w_proj   = (const float*)d_in[14];
    const float* b_proj   = (const float*)d_in[15];
    float* out = (float*)d_out;

    void* p;
    cudaGetSymbolAddress(&p, g_h);      float*  h     = (float*)p;
    cudaGetSymbolAddress(&p, g_h16);    __half* h16   = (__half*)p;
    cudaGetSymbolAddress(&p, g_kv16);   __half* kv16  = (__half*)p;
    cudaGetSymbolAddress(&p, g_q);      float*  qb    = (float*)p;
    cudaGetSymbolAddress(&p, g_k);      float*  kb    = (float*)p;
    cudaGetSymbolAddress(&p, g_v);      float*  vb    = (float*)p;
    cudaGetSymbolAddress(&p, g_vt);     float*  vtb   = (float*)p;
    cudaGetSymbolAddress(&p, g_att16);  __half* att16 = (__half*)p;
    cudaGetSymbolAddress(&p, g_x2);     float*  x2    = (float*)p;
    cudaGetSymbolAddress(&p, g_h2_16);  __half* h2_16 = (__half*)p;
    cudaGetSymbolAddress(&p, g_ff16);   __half* ff16  = (__half*)p;
    cudaGetSymbolAddress(&p, g_w16);    __half* w16   = (__half*)p;
    cudaGetSymbolAddress(&p, g_logits); float*  logi  = (float*)p;
    cudaGetSymbolAddress(&p, g_start);  int*    st    = (int*)p;
    cudaGetSymbolAddress(&p, g_scale);  float*  sc    = (float*)p;

    // 0. weight prep: fused fp16 conversion
    f2h_all_kernel<<<(W16_TOTAL / 4 + 255) / 256, 256>>>(ipw, opw, w_fc, w_proj, w16);
    // 1. LN1
    ln_kernel<true, true><<<NTOK, 256>>>(x, ln1_g, ln1_b, h, h16);
    // 2-3. saliency + selection
    logits_kernel<<<BB * NB, 256>>>(h, w_sal, b_sal, logi);
    select_kernel<<<SSEL * BB, 32>>>(logi, gumbel_u, st, sc);
    // 4. gather -> kv16
    gather_kernel<<<MKV, 256>>>(h, st, sc, kv16);
    // 5. fused QKV projection (fp32 out)
    hgemm_qkv<<<dim3(DD / 128, 64 + 20 + 20), 256>>>(h16, kv16, w16 + W16_IPW, ipb,
                                                     qb, kb, vb);
    // 5b. V transpose (f32)
    vtrans_kernel<<<dim3(NKEY / 32, DD / 32, BB), dim3(32, 8)>>>(vb, vtb);
    // 6. attention (fp16 mma flash, fp32 inputs, fp16 out)
    fattn16_kernel<<<dim3(LL / 64, BB * NH), 128>>>(qb, kb, vtb, att16);
    // 7. out proj + residual (fp32 out)
    hgemm<true, false, true, false><<<dim3(DD / 128, NTOK / 128), 256>>>(
        att16, w16 + W16_OPW, opb, x, x2, NTOK, DD, DD);
    // 8. LN2 (fp16 out)
    ln_kernel<false, true><<<NTOK, 256>>>(x2, ln2_g, ln2_b, nullptr, h2_16);
    // 9. FFN up + gelu (NN, fp16 out)
    hgemm<false, true, false, true><<<dim3(DFFN / 128, NTOK / 128), 256>>>(
        h2_16, w16 + W16_WFC, b_fc, nullptr, ff16, NTOK, DFFN, DD);
    // 10. FFN down + residual (NN, fp32 out) -> out
    hgemm<false, false, true, false><<<dim3(DD / 128, NTOK / 128), 256>>>(
        ff16, w16 + W16_WPROJ, b_proj, x2, out, NTOK, DD, DFFN);
}

// round 10
// speedup vs baseline: 6.6973x; 1.0189x over previous
#include <cuda_runtime.h>
#include <cuda_fp16.h>
#include <math.h>
#include <stdint.h>

// ---------------- problem constants ----------------
#define DD     1024
#define LL     2048
#define BB     4
#define NH     16
#define DH     64
#define SSEL   5
#define WWIN   128
#define BKBLK  32
#define NB     64          // L / BK
#define NTOK   8192        // B*L
#define MKV    2560        // B*S*W
#define NKEY   640         // S*W keys per batch
#define DFFN   4096

// ---------------- scratch (device globals; no allocations allowed) --------
__device__ float  g_h   [NTOK * DD];     // fp32 h (logits + gather)
__device__ __half g_h16 [NTOK * DD];     // fp16 h (Q gemm A)
__device__ __half g_kv16[MKV  * DD];     // fp16 kv (K/V gemm A)
__device__ __half g_q16 [NTOK * DD];
__device__ __half g_k16 [MKV  * DD];
__device__ __half g_v16 [MKV  * DD];
__device__ __half g_vt16[BB * DD * NKEY];
__device__ __half g_att16[NTOK * DD];    // fp16 attention out (out-proj A)
__device__ float  g_x2  [NTOK * DD];
__device__ __half g_h2_16[NTOK * DD];    // fp16 ln2 out (FFN1 A)
__device__ __half g_ff16 [NTOK * DFFN];  // fp16 FFN1 out (FFN2 A)
__device__ __half g_w16  [12582912];     // fp16 weights: ipw | opw | w_fc | w_proj
__device__ float  g_logits[BB * NB];
__device__ int    g_start [SSEL * BB];
__device__ float  g_scale [SSEL * BB];

#define W16_IPW   0
#define W16_OPW   3145728
#define W16_WFC   4194304
#define W16_WPROJ 8388608
#define W16_TOTAL 12582912

// ---------------- helpers ----------------
__device__ __forceinline__ uint32_t h2u(__half2 h) {
    union { __half2 h; uint32_t u; } cvt;
    cvt.h = h;
    return cvt.u;
}

__device__ __forceinline__ void mma_f16(float* d, const uint32_t* a, const uint32_t* b) {
    asm volatile(
        "mma.sync.aligned.m16n8k16.row.col.f32.f16.f16.f32 "
        "{%0,%1,%2,%3}, {%4,%5,%6,%7}, {%8,%9}, {%0,%1,%2,%3};\n"
        : "+f"(d[0]), "+f"(d[1]), "+f"(d[2]), "+f"(d[3])
        : "r"(a[0]), "r"(a[1]), "r"(a[2]), "r"(a[3]), "r"(b[0]), "r"(b[1]));
}

__device__ __forceinline__ void ldsm4(uint32_t& r0, uint32_t& r1, uint32_t& r2, uint32_t& r3,
                                      uint32_t addr) {
    asm volatile("ldmatrix.sync.aligned.m8n8.x4.shared.b16 {%0,%1,%2,%3}, [%4];"
                 : "=r"(r0), "=r"(r1), "=r"(r2), "=r"(r3) : "r"(addr));
}
__device__ __forceinline__ void ldsm4t(uint32_t& r0, uint32_t& r1, uint32_t& r2, uint32_t& r3,
                                       uint32_t addr) {
    asm volatile("ldmatrix.sync.aligned.m8n8.x4.trans.shared.b16 {%0,%1,%2,%3}, [%4];"
                 : "=r"(r0), "=r"(r1), "=r"(r2), "=r"(r3) : "r"(addr));
}

__device__ __forceinline__ void cp16(void* s, const void* g) {
    unsigned sa = (unsigned)__cvta_generic_to_shared(s);
    asm volatile("cp.async.cg.shared.global [%0], [%1], 16;\n" :: "r"(sa), "l"(g));
}
__device__ __forceinline__ void cp_commit() { asm volatile("cp.async.commit_group;\n"); }
__device__ __forceinline__ void cp_wait0()  { asm volatile("cp.async.wait_group 0;\n"); }

// ---------------- fused fp32 -> fp16 weight conversion ----------------
__global__ void f2h_all_kernel(const float* __restrict__ ipw,
                               const float* __restrict__ opw,
                               const float* __restrict__ wfc,
                               const float* __restrict__ wproj,
                               __half* __restrict__ w16) {
    int i = (blockIdx.x * blockDim.x + threadIdx.x) * 4;
    if (i >= W16_TOTAL) return;
    const float* src;
    if (i < W16_OPW)        src = ipw + i;
    else if (i < W16_WFC)   src = opw + (i - W16_OPW);
    else if (i < W16_WPROJ) src = wfc + (i - W16_WFC);
    else                    src = wproj + (i - W16_WPROJ);
    float4 v = *reinterpret_cast<const float4*>(src);
    __half2* d = reinterpret_cast<__half2*>(w16 + i);
    d[0] = __floats2half2_rn(v.x, v.y);
    d[1] = __floats2half2_rn(v.z, v.w);
}

// ---------------- LayerNorm: one block per token ----------------
template<bool WF, bool WH>
__global__ void ln_kernel(const float* __restrict__ x,
                          const float* __restrict__ gam,
                          const float* __restrict__ bet,
                          float* __restrict__ out,
                          __half* __restrict__ out16) {
    __shared__ float red[8];
    const int row = blockIdx.x;
    const int t = threadIdx.x;  // 256
    const float4* xr = reinterpret_cast<const float4*>(x) + (size_t)row * (DD / 4);
    float4 v = xr[t];

    float s = v.x + v.y + v.z + v.w;
    #pragma unroll
    for (int o = 16; o; o >>= 1) s += __shfl_down_sync(0xffffffffu, s, o);
    if ((t & 31) == 0) red[t >> 5] = s;
    __syncthreads();
    float tot = red[0] + red[1] + red[2] + red[3] + red[4] + red[5] + red[6] + red[7];
    const float mean = tot * (1.0f / DD);
    __syncthreads();

    float dx = v.x - mean, dy = v.y - mean, dz = v.z - mean, dw = v.w - mean;
    float sq = dx * dx + dy * dy + dz * dz + dw * dw;
    #pragma unroll
    for (int o = 16; o; o >>= 1) sq += __shfl_down_sync(0xffffffffu, sq, o);
    if ((t & 31) == 0) red[t >> 5] = sq;
    __syncthreads();
    float var = (red[0] + red[1] + red[2] + red[3] + red[4] + red[5] + red[6] + red[7]) * (1.0f / DD);
    const float r = rsqrtf(var + 1e-5f);

    const float4 gg = reinterpret_cast<const float4*>(gam)[t];
    const float4 bb = reinterpret_cast<const float4*>(bet)[t];
    float4 o4;
    o4.x = dx * r * gg.x + bb.x;
    o4.y = dy * r * gg.y + bb.y;
    o4.z = dz * r * gg.z + bb.z;
    o4.w = dw * r * gg.w + bb.w;
    if (WF)
        reinterpret_cast<float4*>(out)[(size_t)row * (DD / 4) + t] = o4;
    if (WH) {
        __half2* d = reinterpret_cast<__half2*>(out16 + (size_t)row * DD + t * 4);
        d[0] = __floats2half2_rn(o4.x, o4.y);
        d[1] = __floats2half2_rn(o4.z, o4.w);
    }
}

// ---------------- block saliency logits ----------------
__global__ void logits_kernel(const float* __restrict__ h,
                              const float* __restrict__ w_sal,
                              const float* __restrict__ b_sal,
                              float* __restrict__ logits) {
    __shared__ float red[8];
    const int t = threadIdx.x;  // 256
    const float4 w = reinterpret_cast<const float4*>(w_sal)[t];
    const float* base = h + (size_t)blockIdx.x * BKBLK * DD;
    float acc = 0.0f;
    for (int tok = 0; tok < BKBLK; tok++) {
        float4 hv = reinterpret_cast<const float4*>(base + (size_t)tok * DD)[t];
        acc += hv.x * w.x + hv.y * w.y + hv.z * w.z + hv.w * w.w;
    }
    #pragma unroll
    for (int o = 16; o; o >>= 1) acc += __shfl_down_sync(0xffffffffu, acc, o);
    if ((t & 31) == 0) red[t >> 5] = acc;
    __syncthreads();
    if (t == 0) {
        float tot = red[0] + red[1] + red[2] + red[3] + red[4] + red[5] + red[6] + red[7];
        logits[blockIdx.x] = tot * (1.0f / BKBLK) + b_sal[0];
    }
}

// ---------------- gumbel selection ----------------
__global__ void select_kernel(const float* __restrict__ logits,
                              const float* __restrict__ gu,
                              int* __restrict__ starts,
                              float* __restrict__ scales) {
    const int sb = blockIdx.x;           // s*B + b
    const int b = sb % BB;
    const int lane = threadIdx.x;        // 32

    float u0 = gu[sb * NB + lane];
    float u1 = gu[sb * NB + 32 + lane];
    float g0 = -logf(-logf(u0 + 1e-9f) + 1e-9f);
    float g1 = -logf(-logf(u1 + 1e-9f) + 1e-9f);
    float p0 = logits[b * NB + lane] + g0;       // TAU = 1
    float p1 = logits[b * NB + 32 + lane] + g1;

    float m = p0; int idx = lane;
    if (p1 > m) { m = p1; idx = lane + 32; }
    #pragma unroll
    for (int o = 16; o; o >>= 1) {
        float om = __shfl_down_sync(0xffffffffu, m, o);
        int   oi = __shfl_down_sync(0xffffffffu, idx, o);
        if (om > m || (om == m && oi < idx)) { m = om; idx = oi; }
    }
    m   = __shfl_sync(0xffffffffu, m, 0);
    idx = __shfl_sync(0xffffffffu, idx, 0);

    float se = expf(p0 - m) + expf(p1 - m);
    #pragma unroll
    for (int o = 16; o; o >>= 1) se += __shfl_down_sync(0xffffffffu, se, o);
    if (lane == 0) {
        float w = 1.0f / se;
        float scale = (1.0f + w) - w;
        int start = idx * BKBLK + BKBLK / 2 - WWIN / 2;
        if (start < 0) start = 0;
        if (start > LL - WWIN) start = LL - WWIN;
        starts[sb] = start;
        scales[sb] = scale;
    }
}

// ---------------- window gather into kv (fp16 out) ----------------
__global__ void gather_kernel(const float* __restrict__ h,
                              const int* __restrict__ starts,
                              const float* __restrict__ scales,
                              __half* __restrict__ kv) {
    const int row = blockIdx.x;          // b*640 + s*128 + w
    const int b = row / (SSEL * WWIN);
    const int r = row % (SSEL * WWIN);
    const int s = r / WWIN;
    const int w = r % WWIN;
    const int sb = s * BB + b;
    const int src = b * LL + starts[sb] + w;
    const float sc = scales[sb];
    const int t = threadIdx.x;           // 256
    float4 v = reinterpret_cast<const float4*>(h)[(size_t)src * (DD / 4) + t];
    __half2* d = reinterpret_cast<__half2*>(kv + (size_t)row * DD + t * 4);
    d[0] = __floats2half2_rn(v.x * sc, v.y * sc);
    d[1] = __floats2half2_rn(v.z * sc, v.w * sc);
}

// ---------------- fp16 V transpose: v[b*640+j][c] -> vt[b*1024+c][j] -----
__global__ void vtrans16_kernel(const __half* __restrict__ v, __half* __restrict__ vt) {
    __shared__ __half t[32][34];
    const int b = blockIdx.z;
    const int j0 = blockIdx.x * 32, c0 = blockIdx.y * 32;
    const int tx = threadIdx.x, ty = threadIdx.y;  // 32 x 8
    #pragma unroll
    for (int i = 0; i < 32; i += 8)
        t[ty + i][tx] = v[((size_t)(b * NKEY + j0 + ty + i)) * DD + c0 + tx];
    __syncthreads();
    #pragma unroll
    for (int i = 0; i < 32; i += 8)
        vt[((size_t)(b * DD + c0 + ty + i)) * NKEY + j0 + tx] = t[tx][ty + i];
}

// ================= FP16 tensor-core GEMM (verbatim round-4) =================
#define HA_STRIDE 40     // halfs
#define HB_NN_STRIDE 136 // halfs
#define HSTG 5120        // halfs per tile stage

template<bool BT, bool GELU, bool RES, bool OUTH>
__global__ __launch_bounds__(256, 2)
void hgemm(const __half* __restrict__ A,
           const __half* __restrict__ B,
           const float* __restrict__ bias,
           const float* __restrict__ res,
           void* __restrict__ Cout,
           int M, int N, int K) {
    __shared__ __half sm[4 * HSTG];
    __half* As = sm;
    __half* Bs = sm + 2 * HSTG;
    const uint32_t sm_u32 = (uint32_t)__cvta_generic_to_shared(sm);

    const int tid  = threadIdx.x;
    const int lane = tid & 31;
    const int wid  = tid >> 5;
    const int wm = (wid & 1) * 64;
    const int wn = (wid >> 1) * 32;
    const int lm = lane >> 2;
    const int lk = lane & 3;
    const int m0 = blockIdx.y * 128;
    const int n0 = blockIdx.x * 128;

    float acc[4][4][4];
    #pragma unroll
    for (int i = 0; i < 4; i++)
        #pragma unroll
        for (int j = 0; j < 4; j++)
            #pragma unroll
            for (int f = 0; f < 4; f++) acc[i][j][f] = 0.0f;

    auto issue = [&](int k0, int buf) {
        #pragma unroll
        for (int j = 0; j < 2; j++) {
            int idx = tid + j * 256;
            int r = idx >> 2, c = (idx & 3) * 8;
            cp16(&As[buf * HSTG + r * HA_STRIDE + c],
                 A + (size_t)(m0 + r) * K + k0 + c);
        }
        #pragma unroll
        for (int j = 0; j < 2; j++) {
            int idx = tid + j * 256;
            if (BT) {
                int r = idx >> 2, c = (idx & 3) * 8;
                cp16(&Bs[buf * HSTG + r * HA_STRIDE + c],
                     B + (size_t)(n0 + r) * K + k0 + c);
            } else {
                int r = idx >> 4, c = (idx & 15) * 8;
                cp16(&Bs[buf * HSTG + r * HB_NN_STRIDE + c],
                     B + (size_t)(k0 + r) * N + n0 + c);
            }
        }
    };

    issue(0, 0);
    cp_commit();
    cp_wait0();
    __syncthreads();

    const int a_row  = lane & 15;
    const int a_colh = ((lane >> 4) << 3);
    const int g  = lane >> 3;
    const int lr = lane & 7;
    const int t_krow = ((g >> 1) << 3) + lr;
    const int t_ncol = (g & 1) << 3;

    const int T = K >> 5;
    for (int t = 0; t < T; t++) {
        const int buf = t & 1;
        if (t + 1 < T) { issue((t + 1) << 5, buf ^ 1); cp_commit(); }

        #pragma unroll
        for (int ks = 0; ks < 2; ks++) {
            uint32_t a[4][4];
            #pragma unroll
            for (int mi = 0; mi < 4; mi++) {
                uint32_t addr = sm_u32 + 2 * (buf * HSTG +
                    (wm + mi * 16 + a_row) * HA_STRIDE + ks * 16 + a_colh);
                ldsm4(a[mi][0], a[mi][1], a[mi][2], a[mi][3], addr);
            }
            uint32_t b[4][2];
            #pragma unroll
            for (int p = 0; p < 2; p++) {
                uint32_t r0, r1, r2, r3;
                if (BT) {
                    uint32_t addr = sm_u32 + 2 * (2 * HSTG + buf * HSTG +
                        (wn + p * 16 + a_row) * HA_STRIDE + ks * 16 + a_colh);
                    ldsm4(r0, r1, r2, r3, addr);
                } else {
                    uint32_t addr = sm_u32 + 2 * (2 * HSTG + buf * HSTG +
                        (ks * 16 + t_krow) * HB_NN_STRIDE + wn + p * 16 + t_ncol);
                    ldsm4t(r0, r1, r2, r3, addr);
                }
                b[p * 2 + 0][0] = r0; b[p * 2 + 0][1] = r2;
                b[p * 2 + 1][0] = r1; b[p * 2 + 1][1] = r3;
            }
            #pragma unroll
            for (int mi = 0; mi < 4; mi++)
                #pragma unroll
                for (int ni = 0; ni < 4; ni++)
                    mma_f16(acc[mi][ni], a[mi], b[ni]);
        }

        if (t + 1 < T) { cp_wait0(); __syncthreads(); }
    }

    #pragma unroll
    for (int ni = 0; ni < 4; ni++) {
        const int cn = n0 + wn + ni * 8 + lk * 2;
        const float bx = bias[cn], by = bias[cn + 1];
        #pragma unroll
        for (int mi = 0; mi < 4; mi++) {
            const int rm = m0 + wm + mi * 16 + lm;
            float v0 = acc[mi][ni][0] + bx;
            float v1 = acc[mi][ni][1] + by;
            float v2 = acc[mi][ni][2] + bx;
            float v3 = acc[mi][ni][3] + by;
            if (GELU) {
                float vv[4] = {v0, v1, v2, v3};
                #pragma unroll
                for (int j = 0; j < 4; j++) {
                    float v = vv[j];
                    float u = 0.7978845608028654f * (v + 0.044715f * v * v * v);
                    vv[j] = 0.5f * v * (1.0f + tanhf(u));
                }
                v0 = vv[0]; v1 = vv[1]; v2 = vv[2]; v3 = vv[3];
            }
            if (RES) {
                const float* rf = (const float*)res;
                float2 r0 = *reinterpret_cast<const float2*>(rf + (size_t)rm * N + cn);
                float2 r1 = *reinterpret_cast<const float2*>(rf + (size_t)(rm + 8) * N + cn);
                v0 += r0.x; v1 += r0.y; v2 += r1.x; v3 += r1.y;
            }
            if (OUTH) {
                __half* C = (__half*)Cout;
                *reinterpret_cast<__half2*>(C + (size_t)rm * N + cn) = __floats2half2_rn(v0, v1);
                *reinterpret_cast<__half2*>(C + (size_t)(rm + 8) * N + cn) = __floats2half2_rn(v2, v3);
            } else {
                float* C = (float*)Cout;
                float2 o0 = {v0, v1}, o1 = {v2, v3};
                *reinterpret_cast<float2*>(C + (size_t)rm * N + cn) = o0;
                *reinterpret_cast<float2*>(C + (size_t)(rm + 8) * N + cn) = o1;
            }
        }
    }
}

// ============ fused QKV GEMM (NT, fp16 out) — round-7 copy + OUTH stores ====
__global__ __launch_bounds__(256, 2)
void hgemm_qkv(const __half* __restrict__ h16,
               const __half* __restrict__ kv16,
               const __half* __restrict__ ipw16,
               const float* __restrict__ ipb,
               __half* __restrict__ qo,
               __half* __restrict__ ko,
               __half* __restrict__ vo) {
    __shared__ __half sm[4 * HSTG];
    __half* As = sm;
    __half* Bs = sm + 2 * HSTG;
    const uint32_t sm_u32 = (uint32_t)__cvta_generic_to_shared(sm);

    const int y = blockIdx.y;
    int seg, my;
    if (y < 64)      { seg = 0; my = y; }
    else if (y < 84) { seg = 1; my = y - 64; }
    else             { seg = 2; my = y - 84; }
    const __half* A = (seg == 0) ? h16 : kv16;
    const __half* B = ipw16 + (size_t)seg * DD * DD;
    const float* bias = ipb + seg * DD;
    __half* C = (seg == 0) ? qo : ((seg == 1) ? ko : vo);
    const int K = DD, N = DD;
    const int m0 = my * 128;
    const int n0 = blockIdx.x * 128;

    const int tid  = threadIdx.x;
    const int lane = tid & 31;
    const int wid  = tid >> 5;
    const int wm = (wid & 1) * 64;
    const int wn = (wid >> 1) * 32;
    const int lm = lane >> 2;
    const int lk = lane & 3;

    float acc[4][4][4];
    #pragma unroll
    for (int i = 0; i < 4; i++)
        #pragma unroll
        for (int j = 0; j < 4; j++)
            #pragma unroll
            for (int f = 0; f < 4; f++) acc[i][j][f] = 0.0f;

    auto issue = [&](int k0, int buf) {
        #pragma unroll
        for (int j = 0; j < 2; j++) {
            int idx = tid + j * 256;
            int r = idx >> 2, c = (idx & 3) * 8;
            cp16(&As[buf * HSTG + r * HA_STRIDE + c],
                 A + (size_t)(m0 + r) * K + k0 + c);
        }
        #pragma unroll
        for (int j = 0; j < 2; j++) {
            int idx = tid + j * 256;
            int r = idx >> 2, c = (idx & 3) * 8;
            cp16(&Bs[buf * HSTG + r * HA_STRIDE + c],
                 B + (size_t)(n0 + r) * K + k0 + c);
        }
    };

    issue(0, 0);
    cp_commit();
    cp_wait0();
    __syncthreads();

    const int a_row  = lane & 15;
    const int a_colh = ((lane >> 4) << 3);

    const int T = K >> 5;
    for (int t = 0; t < T; t++) {
        const int buf = t & 1;
        if (t + 1 < T) { issue((t + 1) << 5, buf ^ 1); cp_commit(); }

        #pragma unroll
        for (int ks = 0; ks < 2; ks++) {
            uint32_t a[4][4];
            #pragma unroll
            for (int mi = 0; mi < 4; mi++) {
                uint32_t addr = sm_u32 + 2 * (buf * HSTG +
                    (wm + mi * 16 + a_row) * HA_STRIDE + ks * 16 + a_colh);
                ldsm4(a[mi][0], a[mi][1], a[mi][2], a[mi][3], addr);
            }
            uint32_t b[4][2];
            #pragma unroll
            for (int p = 0; p < 2; p++) {
                uint32_t r0, r1, r2, r3;
                uint32_t addr = sm_u32 + 2 * (2 * HSTG + buf * HSTG +
                    (wn + p * 16 + a_row) * HA_STRIDE + ks * 16 + a_colh);
                ldsm4(r0, r1, r2, r3, addr);
                b[p * 2 + 0][0] = r0; b[p * 2 + 0][1] = r2;
                b[p * 2 + 1][0] = r1; b[p * 2 + 1][1] = r3;
            }
            #pragma unroll
            for (int mi = 0; mi < 4; mi++)
                #pragma unroll
                for (int ni = 0; ni < 4; ni++)
                    mma_f16(acc[mi][ni], a[mi], b[ni]);
        }

        if (t + 1 < T) { cp_wait0(); __syncthreads(); }
    }

    #pragma unroll
    for (int ni = 0; ni < 4; ni++) {
        const int cn = n0 + wn + ni * 8 + lk * 2;
        const float bx = bias[cn], by = bias[cn + 1];
        #pragma unroll
        for (int mi = 0; mi < 4; mi++) {
            const int rm = m0 + wm + mi * 16 + lm;
            *reinterpret_cast<__half2*>(C + (size_t)rm * N + cn) =
                __floats2half2_rn(acc[mi][ni][0] + bx, acc[mi][ni][1] + by);
            *reinterpret_cast<__half2*>(C + (size_t)(rm + 8) * N + cn) =
                __floats2half2_rn(acc[mi][ni][2] + bx, acc[mi][ni][3] + by);
        }
    }
}

// ============ flash attention: fp16 mma, fp16 inputs, fp16 output ==========
#define FA_STR 72   // halfs per smem row (64 + 8 pad); row pitch 144B

__global__ __launch_bounds__(128)
void fattn16_kernel(const __half* __restrict__ q,
                    const __half* __restrict__ k,
                    const __half* __restrict__ vt,
                    __half* __restrict__ o) {
    __shared__ __half Qh[64 * FA_STR];
    __shared__ __half Kh[64 * FA_STR];
    __shared__ __half Vh[64 * FA_STR];
    __shared__ __half Ph[64 * FA_STR];
    const uint32_t Qu = (uint32_t)__cvta_generic_to_shared(Qh);
    const uint32_t Ku = (uint32_t)__cvta_generic_to_shared(Kh);
    const uint32_t Vu = (uint32_t)__cvta_generic_to_shared(Vh);
    const uint32_t Pu = (uint32_t)__cvta_generic_to_shared(Ph);

    const int bh = blockIdx.y;
    const int b = bh >> 4, hh = bh & 15;
    const int q0 = blockIdx.x * 64;
    const int tid = threadIdx.x, lane = tid & 31, wid = tid >> 5;
    const int lm = lane >> 2, lk = lane & 3;
    const int wm = wid * 16;

    const int a_row  = lane & 15;
    const int a_colh = ((lane >> 4) << 3);

    // load Q tile (fp16, scaled by 1/8 — exact in fp16)
    {
        const __half2 sc = __floats2half2_rn(0.125f, 0.125f);
        const __half* qg = q + ((size_t)(b * LL + q0)) * DD + hh * DH;
        #pragma unroll
        for (int it = 0; it < 4; it++) {
            int idx = tid + it * 128;
            int r = idx >> 3, c = (idx & 7) * 8;
            uint4 raw = *reinterpret_cast<const uint4*>(qg + (size_t)r * DD + c);
            __half2* hp = reinterpret_cast<__half2*>(&raw);
            hp[0] = __hmul2(hp[0], sc); hp[1] = __hmul2(hp[1], sc);
            hp[2] = __hmul2(hp[2], sc); hp[3] = __hmul2(hp[3], sc);
            *reinterpret_cast<uint4*>(&Qh[r * FA_STR + c]) = raw;
        }
    }

    float mrow0 = -1e30f, mrow1 = -1e30f, lrow0 = 0.0f, lrow1 = 0.0f;
    float oacc[8][4];
    #pragma unroll
    for (int ni = 0; ni < 8; ni++)
        #pragma unroll
        for (int f = 0; f < 4; f++) oacc[ni][f] = 0.0f;

    const __half* kg = k + ((size_t)(b * NKEY)) * DD + hh * DH;
    const __half* vg = vt + ((size_t)(b * DD + hh * DH)) * NKEY;

    for (int kt = 0; kt < NKEY / 64; kt++) {
        __syncthreads();
        #pragma unroll
        for (int it = 0; it < 4; it++) {
            int idx = tid + it * 128;
            int r = idx >> 3, c = (idx & 7) * 8;
            *reinterpret_cast<uint4*>(&Kh[r * FA_STR + c]) =
                *reinterpret_cast<const uint4*>(kg + (size_t)(kt * 64 + r) * DD + c);
            *reinterpret_cast<uint4*>(&Vh[r * FA_STR + c]) =
                *reinterpret_cast<const uint4*>(vg + (size_t)r * NKEY + kt * 64 + c);
        }
        __syncthreads();

        // S = Q @ K^T (fp16 mma)
        float s[8][4];
        #pragma unroll
        for (int ni = 0; ni < 8; ni++)
            #pragma unroll
            for (int f = 0; f < 4; f++) s[ni][f] = 0.0f;

        #pragma unroll
        for (int kk = 0; kk < 4; kk++) {
            uint32_t a[4];
            ldsm4(a[0], a[1], a[2], a[3],
                  Qu + 2 * ((wm + a_row) * FA_STR + kk * 16 + a_colh));
            #pragma unroll
            for (int p = 0; p < 4; p++) {
                uint32_t r0, r1, r2, r3;
                ldsm4(r0, r1, r2, r3,
                      Ku + 2 * ((p * 16 + a_row) * FA_STR + kk * 16 + a_colh));
                uint32_t b0[2] = {r0, r2}, b1[2] = {r1, r3};
                mma_f16(s[p * 2 + 0], a, b0);
                mma_f16(s[p * 2 + 1], a, b1);
            }
        }

        // online softmax (rows lm, lm+8)
        float rm0 = -1e30f, rm1 = -1e30f;
        #pragma unroll
        for (int ni = 0; ni < 8; ni++) {
            rm0 = fmaxf(rm0, fmaxf(s[ni][0], s[ni][1]));
            rm1 = fmaxf(rm1, fmaxf(s[ni][2], s[ni][3]));
        }
        rm0 = fmaxf(rm0, __shfl_xor_sync(0xffffffffu, rm0, 1));
        rm0 = fmaxf(rm0, __shfl_xor_sync(0xffffffffu, rm0, 2));
        rm1 = fmaxf(rm1, __shfl_xor_sync(0xffffffffu, rm1, 1));
        rm1 = fmaxf(rm1, __shfl_xor_sync(0xffffffffu, rm1, 2));

        float nm0 = fmaxf(mrow0, rm0), nm1 = fmaxf(mrow1, rm1);
        float al0 = __expf(mrow0 - nm0), al1 = __expf(mrow1 - nm1);
        mrow0 = nm0; mrow1 = nm1;

        float rs0 = 0.0f, rs1 = 0.0f;
        #pragma unroll
        for (int ni = 0; ni < 8; ni++) {
            s[ni][0] = __expf(s[ni][0] - nm0);
            s[ni][1] = __expf(s[ni][1] - nm0);
            s[ni][2] = __expf(s[ni][2] - nm1);
            s[ni][3] = __expf(s[ni][3] - nm1);
            rs0 += s[ni][0] + s[ni][1];
            rs1 += s[ni][2] + s[ni][3];
        }
        rs0 += __shfl_xor_sync(0xffffffffu, rs0, 1);
        rs0 += __shfl_xor_sync(0xffffffffu, rs0, 2);
        rs1 += __shfl_xor_sync(0xffffffffu, rs1, 1);
        rs1 += __shfl_xor_sync(0xffffffffu, rs1, 2);

        lrow0 = lrow0 * al0 + rs0;
        lrow1 = lrow1 * al1 + rs1;

        #pragma unroll
        for (int ni = 0; ni < 8; ni++) {
            oacc[ni][0] *= al0; oacc[ni][1] *= al0;
            oacc[ni][2] *= al1; oacc[ni][3] *= al1;
        }

        // P -> smem fp16 (own warp rows only)
        #pragma unroll
        for (int ni = 0; ni < 8; ni++) {
            __half* pp = &Ph[(wm + lm) * FA_STR + ni * 8 + 2 * lk];
            *reinterpret_cast<__half2*>(pp) = __floats2half2_rn(s[ni][0], s[ni][1]);
            *reinterpret_cast<__half2*>(pp + 8 * FA_STR) = __floats2half2_rn(s[ni][2], s[ni][3]);
        }
        __syncwarp();

        // O += P @ V (fp16 mma; Vh is [d][j])
        #pragma unroll
        for (int kk = 0; kk < 4; kk++) {
            uint32_t a[4];
            ldsm4(a[0], a[1], a[2], a[3],
                  Pu + 2 * ((wm + a_row) * FA_STR + kk * 16 + a_colh));
            #pragma unroll
            for (int p = 0; p < 4; p++) {
                uint32_t r0, r1, r2, r3;
                ldsm4(r0, r1, r2, r3,
                      Vu + 2 * ((p * 16 + a_row) * FA_STR + kk * 16 + a_colh));
                uint32_t b0[2] = {r0, r2}, b1[2] = {r1, r3};
                mma_f16(oacc[p * 2 + 0], a, b0);
                mma_f16(oacc[p * 2 + 1], a, b1);
            }
        }
    }

    const float inv0 = 1.0f / lrow0, inv1 = 1.0f / lrow1;
    __half* og = o + ((size_t)(b * LL + q0 + wm + lm)) * DD + hh * DH;
    #pragma unroll
    for (int ni = 0; ni < 8; ni++) {
        const int cc = ni * 8 + 2 * lk;
        *reinterpret_cast<__half2*>(og + cc) =
            __floats2half2_rn(oacc[ni][0] * inv0, oacc[ni][1] * inv0);
        *reinterpret_cast<__half2*>(og + (size_t)8 * DD + cc) =
            __floats2half2_rn(oacc[ni][2] * inv1, oacc[ni][3] * inv1);
    }
}

// ---------------- driver ----------------
extern "C" void kernel_launch(void* const* d_in, const int* in_sizes, int n_in,
                              void* d_out, int out_size) {
    const float* x        = (const float*)d_in[0];
    const float* gumbel_u = (const float*)d_in[1];
    const float* ln1_g    = (const float*)d_in[2];
    const float* ln1_b    = (const float*)d_in[3];
    const float* ln2_g    = (const float*)d_in[4];
    const float* ln2_b    = (const float*)d_in[5];
    const float* w_sal    = (const float*)d_in[6];
    const float* b_sal    = (const float*)d_in[7];
    const float* ipw      = (const float*)d_in[8];
    const float* ipb      = (const float*)d_in[9];
    const float* opw      = (const float*)d_in[10];
    const float* opb      = (const float*)d_in[11];
    const float* w_fc     = (const float*)d_in[12];
    const float* b_fc     = (const float*)d_in[13];
    const float* w_proj   = (const float*)d_in[14];
    const float* b_proj   = (const float*)d_in[15];
    float* out = (float*)d_out;

    void* p;
    cudaGetSymbolAddress(&p, g_h);      float*  h     = (float*)p;
    cudaGetSymbolAddress(&p, g_h16);    __half* h16   = (__half*)p;
    cudaGetSymbolAddress(&p, g_kv16);   __half* kv16  = (__half*)p;
    cudaGetSymbolAddress(&p, g_q16);    __half* q16   = (__half*)p;
    cudaGetSymbolAddress(&p, g_k16);    __half* k16   = (__half*)p;
    cudaGetSymbolAddress(&p, g_v16);    __half* v16   = (__half*)p;
    cudaGetSymbolAddress(&p, g_vt16);   __half* vt16  = (__half*)p;
    cudaGetSymbolAddress(&p, g_att16);  __half* att16 = (__half*)p;
    cudaGetSymbolAddress(&p, g_x2);     float*  x2    = (float*)p;
    cudaGetSymbolAddress(&p, g_h2_16);  __half* h2_16 = (__half*)p;
    cudaGetSymbolAddress(&p, g_ff16);   __half* ff16  = (__half*)p;
    cudaGetSymbolAddress(&p, g_w16);    __half* w16   = (__half*)p;
    cudaGetSymbolAddress(&p, g_logits); float*  logi  = (float*)p;
    cudaGetSymbolAddress(&p, g_start);  int*    st    = (int*)p;
    cudaGetSymbolAddress(&p, g_scale);  float*  sc    = (float*)p;

    // 0. weight prep: fused fp16 conversion
    f2h_all_kernel<<<(W16_TOTAL / 4 + 255) / 256, 256>>>(ipw, opw, w_fc, w_proj, w16);
    // 1. LN1
    ln_kernel<true, true><<<NTOK, 256>>>(x, ln1_g, ln1_b, h, h16);
    // 2-3. saliency + selection
    logits_kernel<<<BB * NB, 256>>>(h, w_sal, b_sal, logi);
    select_kernel<<<SSEL * BB, 32>>>(logi, gumbel_u, st, sc);
    // 4. gather -> kv16
    gather_kernel<<<MKV, 256>>>(h, st, sc, kv16);
    // 5. fused QKV projection (fp16 out)
    hgemm_qkv<<<dim3(DD / 128, 64 + 20 + 20), 256>>>(h16, kv16, w16 + W16_IPW, ipb,
                                                     q16, k16, v16);
    // 5b. V transpose (fp16)
    vtrans16_kernel<<<dim3(NKEY / 32, DD / 32, BB), dim3(32, 8)>>>(v16, vt16);
    // 6. attention (fp16 mma flash, fp16 in/out)
    fattn16_kernel<<<dim3(LL / 64, BB * NH), 128>>>(q16, k16, vt16, att16);
    // 7. out proj + residual (fp32 out)
    hgemm<true, false, true, false><<<dim3(DD / 128, NTOK / 128), 256>>>(
        att16, w16 + W16_OPW, opb, x, x2, NTOK, DD, DD);
    // 8. LN2 (fp16 out)
    ln_kernel<false, true><<<NTOK, 256>>>(x2, ln2_g, ln2_b, nullptr, h2_16);
    // 9. FFN up + gelu (NN, fp16 out)
    hgemm<false, true, false, true><<<dim3(DFFN / 128, NTOK / 128), 256>>>(
        h2_16, w16 + W16_WFC, b_fc, nullptr, ff16, NTOK, DFFN, DD);
    // 10. FFN down + residual (NN, fp32 out) -> out
    hgemm<false, false, true, false><<<dim3(DD / 128, NTOK / 128), 256>>>(
        ff16, w16 + W16_WPROJ, b_proj, x2, out, NTOK, DD, DFFN);
}

// round 11
// speedup vs baseline: 6.7294x; 1.0048x over previous
#include <cuda_runtime.h>
#include <cuda_fp16.h>
#include <math.h>
#include <stdint.h>

// ---------------- problem constants ----------------
#define DD     1024
#define LL     2048
#define BB     4
#define NH     16
#define DH     64
#define SSEL   5
#define WWIN   128
#define BKBLK  32
#define NB     64          // L / BK
#define NTOK   8192        // B*L
#define MKV    2560        // B*S*W
#define NKEY   640         // S*W keys per batch
#define DFFN   4096

// ---------------- scratch (device globals; no allocations allowed) --------
__device__ float  g_h   [NTOK * DD];     // fp32 h (logits + gather)
__device__ __half g_h16 [NTOK * DD];     // fp16 h (Q gemm A)
__device__ __half g_kv16[MKV  * DD];     // fp16 kv (K/V gemm A)
__device__ __half g_q16 [NTOK * DD];
__device__ __half g_k16 [MKV  * DD];
__device__ __half g_v16 [MKV  * DD];
__device__ __half g_vt16[BB * DD * NKEY];
__device__ __half g_att16[NTOK * DD];    // fp16 attention out (out-proj A)
__device__ float  g_x2  [NTOK * DD];
__device__ __half g_h2_16[NTOK * DD];    // fp16 ln2 out (FFN1 A)
__device__ __half g_ff16 [NTOK * DFFN];  // fp16 FFN1 out (FFN2 A)
__device__ __half g_w16  [12582912];     // fp16 weights: ipw | opw | w_fc | w_proj
__device__ float  g_logits[BB * NB];

#define W16_IPW   0
#define W16_OPW   3145728
#define W16_WFC   4194304
#define W16_WPROJ 8388608
#define W16_TOTAL 12582912

// ---------------- helpers ----------------
__device__ __forceinline__ uint32_t h2u(__half2 h) {
    union { __half2 h; uint32_t u; } cvt;
    cvt.h = h;
    return cvt.u;
}

__device__ __forceinline__ void mma_f16(float* d, const uint32_t* a, const uint32_t* b) {
    asm volatile(
        "mma.sync.aligned.m16n8k16.row.col.f32.f16.f16.f32 "
        "{%0,%1,%2,%3}, {%4,%5,%6,%7}, {%8,%9}, {%0,%1,%2,%3};\n"
        : "+f"(d[0]), "+f"(d[1]), "+f"(d[2]), "+f"(d[3])
        : "r"(a[0]), "r"(a[1]), "r"(a[2]), "r"(a[3]), "r"(b[0]), "r"(b[1]));
}

__device__ __forceinline__ void ldsm4(uint32_t& r0, uint32_t& r1, uint32_t& r2, uint32_t& r3,
                                      uint32_t addr) {
    asm volatile("ldmatrix.sync.aligned.m8n8.x4.shared.b16 {%0,%1,%2,%3}, [%4];"
                 : "=r"(r0), "=r"(r1), "=r"(r2), "=r"(r3) : "r"(addr));
}
__device__ __forceinline__ void ldsm4t(uint32_t& r0, uint32_t& r1, uint32_t& r2, uint32_t& r3,
                                       uint32_t addr) {
    asm volatile("ldmatrix.sync.aligned.m8n8.x4.trans.shared.b16 {%0,%1,%2,%3}, [%4];"
                 : "=r"(r0), "=r"(r1), "=r"(r2), "=r"(r3) : "r"(addr));
}

__device__ __forceinline__ void cp16(void* s, const void* g) {
    unsigned sa = (unsigned)__cvta_generic_to_shared(s);
    asm volatile("cp.async.cg.shared.global [%0], [%1], 16;\n" :: "r"(sa), "l"(g));
}
__device__ __forceinline__ void cp_commit() { asm volatile("cp.async.commit_group;\n"); }
__device__ __forceinline__ void cp_wait0()  { asm volatile("cp.async.wait_group 0;\n"); }

// ---------------- fused fp32 -> fp16 weight conversion ----------------
__global__ void f2h_all_kernel(const float* __restrict__ ipw,
                               const float* __restrict__ opw,
                               const float* __restrict__ wfc,
                               const float* __restrict__ wproj,
                               __half* __restrict__ w16) {
    int i = (blockIdx.x * blockDim.x + threadIdx.x) * 4;
    if (i >= W16_TOTAL) return;
    const float* src;
    if (i < W16_OPW)        src = ipw + i;
    else if (i < W16_WFC)   src = opw + (i - W16_OPW);
    else if (i < W16_WPROJ) src = wfc + (i - W16_WFC);
    else                    src = wproj + (i - W16_WPROJ);
    float4 v = *reinterpret_cast<const float4*>(src);
    __half2* d = reinterpret_cast<__half2*>(w16 + i);
    d[0] = __floats2half2_rn(v.x, v.y);
    d[1] = __floats2half2_rn(v.z, v.w);
}

// ---------------- LayerNorm: one block per token ----------------
template<bool WF, bool WH>
__global__ void ln_kernel(const float* __restrict__ x,
                          const float* __restrict__ gam,
                          const float* __restrict__ bet,
                          float* __restrict__ out,
                          __half* __restrict__ out16) {
    __shared__ float red[8];
    const int row = blockIdx.x;
    const int t = threadIdx.x;  // 256
    const float4* xr = reinterpret_cast<const float4*>(x) + (size_t)row * (DD / 4);
    float4 v = xr[t];

    float s = v.x + v.y + v.z + v.w;
    #pragma unroll
    for (int o = 16; o; o >>= 1) s += __shfl_down_sync(0xffffffffu, s, o);
    if ((t & 31) == 0) red[t >> 5] = s;
    __syncthreads();
    float tot = red[0] + red[1] + red[2] + red[3] + red[4] + red[5] + red[6] + red[7];
    const float mean = tot * (1.0f / DD);
    __syncthreads();

    float dx = v.x - mean, dy = v.y - mean, dz = v.z - mean, dw = v.w - mean;
    float sq = dx * dx + dy * dy + dz * dz + dw * dw;
    #pragma unroll
    for (int o = 16; o; o >>= 1) sq += __shfl_down_sync(0xffffffffu, sq, o);
    if ((t & 31) == 0) red[t >> 5] = sq;
    __syncthreads();
    float var = (red[0] + red[1] + red[2] + red[3] + red[4] + red[5] + red[6] + red[7]) * (1.0f / DD);
    const float r = rsqrtf(var + 1e-5f);

    const float4 gg = reinterpret_cast<const float4*>(gam)[t];
    const float4 bb = reinterpret_cast<const float4*>(bet)[t];
    float4 o4;
    o4.x = dx * r * gg.x + bb.x;
    o4.y = dy * r * gg.y + bb.y;
    o4.z = dz * r * gg.z + bb.z;
    o4.w = dw * r * gg.w + bb.w;
    if (WF)
        reinterpret_cast<float4*>(out)[(size_t)row * (DD / 4) + t] = o4;
    if (WH) {
        __half2* d = reinterpret_cast<__half2*>(out16 + (size_t)row * DD + t * 4);
        d[0] = __floats2half2_rn(o4.x, o4.y);
        d[1] = __floats2half2_rn(o4.z, o4.w);
    }
}

// ---------------- block saliency logits ----------------
__global__ void logits_kernel(const float* __restrict__ h,
                              const float* __restrict__ w_sal,
                              const float* __restrict__ b_sal,
                              float* __restrict__ logits) {
    __shared__ float red[8];
    const int t = threadIdx.x;  // 256
    const float4 w = reinterpret_cast<const float4*>(w_sal)[t];
    const float* base = h + (size_t)blockIdx.x * BKBLK * DD;
    float acc = 0.0f;
    for (int tok = 0; tok < BKBLK; tok++) {
        float4 hv = reinterpret_cast<const float4*>(base + (size_t)tok * DD)[t];
        acc += hv.x * w.x + hv.y * w.y + hv.z * w.z + hv.w * w.w;
    }
    #pragma unroll
    for (int o = 16; o; o >>= 1) acc += __shfl_down_sync(0xffffffffu, acc, o);
    if ((t & 31) == 0) red[t >> 5] = acc;
    __syncthreads();
    if (t == 0) {
        float tot = red[0] + red[1] + red[2] + red[3] + red[4] + red[5] + red[6] + red[7];
        logits[blockIdx.x] = tot * (1.0f / BKBLK) + b_sal[0];
    }
}

// -------- fused selection + window gather (fp16 out) --------
// Each block handles one kv row; warp 0 recomputes the (s,b) selection.
__global__ void gather_kernel(const float* __restrict__ h,
                              const float* __restrict__ logits,
                              const float* __restrict__ gu,
                              __half* __restrict__ kv) {
    __shared__ int   s_start;
    __shared__ float s_scale;

    const int row = blockIdx.x;          // b*640 + s*128 + w
    const int b = row / (SSEL * WWIN);
    const int r = row % (SSEL * WWIN);
    const int s = r / WWIN;
    const int w = r % WWIN;
    const int sb = s * BB + b;
    const int t = threadIdx.x;           // 256

    if (t < 32) {
        const int lane = t;
        float u0 = gu[sb * NB + lane];
        float u1 = gu[sb * NB + 32 + lane];
        float g0 = -logf(-logf(u0 + 1e-9f) + 1e-9f);
        float g1 = -logf(-logf(u1 + 1e-9f) + 1e-9f);
        float p0 = logits[b * NB + lane] + g0;       // TAU = 1
        float p1 = logits[b * NB + 32 + lane] + g1;

        float m = p0; int idx = lane;
        if (p1 > m) { m = p1; idx = lane + 32; }
        #pragma unroll
        for (int o = 16; o; o >>= 1) {
            float om = __shfl_down_sync(0xffffffffu, m, o);
            int   oi = __shfl_down_sync(0xffffffffu, idx, o);
            if (om > m || (om == m && oi < idx)) { m = om; idx = oi; }
        }
        m   = __shfl_sync(0xffffffffu, m, 0);
        idx = __shfl_sync(0xffffffffu, idx, 0);

        float se = expf(p0 - m) + expf(p1 - m);
        #pragma unroll
        for (int o = 16; o; o >>= 1) se += __shfl_down_sync(0xffffffffu, se, o);
        if (lane == 0) {
            float ww = 1.0f / se;
            float scale = (1.0f + ww) - ww;
            int start = idx * BKBLK + BKBLK / 2 - WWIN / 2;
            if (start < 0) start = 0;
            if (start > LL - WWIN) start = LL - WWIN;
            s_start = start;
            s_scale = scale;
        }
    }
    __syncthreads();

    const int src = b * LL + s_start + w;
    const float sc = s_scale;
    float4 v = reinterpret_cast<const float4*>(h)[(size_t)src * (DD / 4) + t];
    __half2* d = reinterpret_cast<__half2*>(kv + (size_t)row * DD + t * 4);
    d[0] = __floats2half2_rn(v.x * sc, v.y * sc);
    d[1] = __floats2half2_rn(v.z * sc, v.w * sc);
}

// ---------------- fp16 V transpose: v[b*640+j][c] -> vt[b*1024+c][j] -----
__global__ void vtrans16_kernel(const __half* __restrict__ v, __half* __restrict__ vt) {
    __shared__ __half t[32][34];
    const int b = blockIdx.z;
    const int j0 = blockIdx.x * 32, c0 = blockIdx.y * 32;
    const int tx = threadIdx.x, ty = threadIdx.y;  // 32 x 8
    #pragma unroll
    for (int i = 0; i < 32; i += 8)
        t[ty + i][tx] = v[((size_t)(b * NKEY + j0 + ty + i)) * DD + c0 + tx];
    __syncthreads();
    #pragma unroll
    for (int i = 0; i < 32; i += 8)
        vt[((size_t)(b * DD + c0 + ty + i)) * NKEY + j0 + tx] = t[tx][ty + i];
}

// ================= FP16 tensor-core GEMM (verbatim round-4) =================
#define HA_STRIDE 40     // halfs
#define HB_NN_STRIDE 136 // halfs
#define HSTG 5120        // halfs per tile stage

template<bool BT, bool GELU, bool RES, bool OUTH>
__global__ __launch_bounds__(256, 2)
void hgemm(const __half* __restrict__ A,
           const __half* __restrict__ B,
           const float* __restrict__ bias,
           const float* __restrict__ res,
           void* __restrict__ Cout,
           int M, int N, int K) {
    __shared__ __half sm[4 * HSTG];
    __half* As = sm;
    __half* Bs = sm + 2 * HSTG;
    const uint32_t sm_u32 = (uint32_t)__cvta_generic_to_shared(sm);

    const int tid  = threadIdx.x;
    const int lane = tid & 31;
    const int wid  = tid >> 5;
    const int wm = (wid & 1) * 64;
    const int wn = (wid >> 1) * 32;
    const int lm = lane >> 2;
    const int lk = lane & 3;
    const int m0 = blockIdx.y * 128;
    const int n0 = blockIdx.x * 128;

    float acc[4][4][4];
    #pragma unroll
    for (int i = 0; i < 4; i++)
        #pragma unroll
        for (int j = 0; j < 4; j++)
            #pragma unroll
            for (int f = 0; f < 4; f++) acc[i][j][f] = 0.0f;

    auto issue = [&](int k0, int buf) {
        #pragma unroll
        for (int j = 0; j < 2; j++) {
            int idx = tid + j * 256;
            int r = idx >> 2, c = (idx & 3) * 8;
            cp16(&As[buf * HSTG + r * HA_STRIDE + c],
                 A + (size_t)(m0 + r) * K + k0 + c);
        }
        #pragma unroll
        for (int j = 0; j < 2; j++) {
            int idx = tid + j * 256;
            if (BT) {
                int r = idx >> 2, c = (idx & 3) * 8;
                cp16(&Bs[buf * HSTG + r * HA_STRIDE + c],
                     B + (size_t)(n0 + r) * K + k0 + c);
            } else {
                int r = idx >> 4, c = (idx & 15) * 8;
                cp16(&Bs[buf * HSTG + r * HB_NN_STRIDE + c],
                     B + (size_t)(k0 + r) * N + n0 + c);
            }
        }
    };

    issue(0, 0);
    cp_commit();
    cp_wait0();
    __syncthreads();

    const int a_row  = lane & 15;
    const int a_colh = ((lane >> 4) << 3);
    const int g  = lane >> 3;
    const int lr = lane & 7;
    const int t_krow = ((g >> 1) << 3) + lr;
    const int t_ncol = (g & 1) << 3;

    const int T = K >> 5;
    for (int t = 0; t < T; t++) {
        const int buf = t & 1;
        if (t + 1 < T) { issue((t + 1) << 5, buf ^ 1); cp_commit(); }

        #pragma unroll
        for (int ks = 0; ks < 2; ks++) {
            uint32_t a[4][4];
            #pragma unroll
            for (int mi = 0; mi < 4; mi++) {
                uint32_t addr = sm_u32 + 2 * (buf * HSTG +
                    (wm + mi * 16 + a_row) * HA_STRIDE + ks * 16 + a_colh);
                ldsm4(a[mi][0], a[mi][1], a[mi][2], a[mi][3], addr);
            }
            uint32_t b[4][2];
            #pragma unroll
            for (int p = 0; p < 2; p++) {
                uint32_t r0, r1, r2, r3;
                if (BT) {
                    uint32_t addr = sm_u32 + 2 * (2 * HSTG + buf * HSTG +
                        (wn + p * 16 + a_row) * HA_STRIDE + ks * 16 + a_colh);
                    ldsm4(r0, r1, r2, r3, addr);
                } else {
                    uint32_t addr = sm_u32 + 2 * (2 * HSTG + buf * HSTG +
                        (ks * 16 + t_krow) * HB_NN_STRIDE + wn + p * 16 + t_ncol);
                    ldsm4t(r0, r1, r2, r3, addr);
                }
                b[p * 2 + 0][0] = r0; b[p * 2 + 0][1] = r2;
                b[p * 2 + 1][0] = r1; b[p * 2 + 1][1] = r3;
            }
            #pragma unroll
            for (int mi = 0; mi < 4; mi++)
                #pragma unroll
                for (int ni = 0; ni < 4; ni++)
                    mma_f16(acc[mi][ni], a[mi], b[ni]);
        }

        if (t + 1 < T) { cp_wait0(); __syncthreads(); }
    }

    #pragma unroll
    for (int ni = 0; ni < 4; ni++) {
        const int cn = n0 + wn + ni * 8 + lk * 2;
        const float bx = bias[cn], by = bias[cn + 1];
        #pragma unroll
        for (int mi = 0; mi < 4; mi++) {
            const int rm = m0 + wm + mi * 16 + lm;
            float v0 = acc[mi][ni][0] + bx;
            float v1 = acc[mi][ni][1] + by;
            float v2 = acc[mi][ni][2] + bx;
            float v3 = acc[mi][ni][3] + by;
            if (GELU) {
                float vv[4] = {v0, v1, v2, v3};
                #pragma unroll
                for (int j = 0; j < 4; j++) {
                    float v = vv[j];
                    float u = 0.7978845608028654f * (v + 0.044715f * v * v * v);
                    vv[j] = 0.5f * v * (1.0f + tanhf(u));
                }
                v0 = vv[0]; v1 = vv[1]; v2 = vv[2]; v3 = vv[3];
            }
            if (RES) {
                const float* rf = (const float*)res;
                float2 r0 = *reinterpret_cast<const float2*>(rf + (size_t)rm * N + cn);
                float2 r1 = *reinterpret_cast<const float2*>(rf + (size_t)(rm + 8) * N + cn);
                v0 += r0.x; v1 += r0.y; v2 += r1.x; v3 += r1.y;
            }
            if (OUTH) {
                __half* C = (__half*)Cout;
                *reinterpret_cast<__half2*>(C + (size_t)rm * N + cn) = __floats2half2_rn(v0, v1);
                *reinterpret_cast<__half2*>(C + (size_t)(rm + 8) * N + cn) = __floats2half2_rn(v2, v3);
            } else {
                float* C = (float*)Cout;
                float2 o0 = {v0, v1}, o1 = {v2, v3};
                *reinterpret_cast<float2*>(C + (size_t)rm * N + cn) = o0;
                *reinterpret_cast<float2*>(C + (size_t)(rm + 8) * N + cn) = o1;
            }
        }
    }
}

// ============ fused QKV GEMM (NT, fp16 out) — verbatim round-10 ============
__global__ __launch_bounds__(256, 2)
void hgemm_qkv(const __half* __restrict__ h16,
               const __half* __restrict__ kv16,
               const __half* __restrict__ ipw16,
               const float* __restrict__ ipb,
               __half* __restrict__ qo,
               __half* __restrict__ ko,
               __half* __restrict__ vo) {
    __shared__ __half sm[4 * HSTG];
    __half* As = sm;
    __half* Bs = sm + 2 * HSTG;
    const uint32_t sm_u32 = (uint32_t)__cvta_generic_to_shared(sm);

    const int y = blockIdx.y;
    int seg, my;
    if (y < 64)      { seg = 0; my = y; }
    else if (y < 84) { seg = 1; my = y - 64; }
    else             { seg = 2; my = y - 84; }
    const __half* A = (seg == 0) ? h16 : kv16;
    const __half* B = ipw16 + (size_t)seg * DD * DD;
    const float* bias = ipb + seg * DD;
    __half* C = (seg == 0) ? qo : ((seg == 1) ? ko : vo);
    const int K = DD, N = DD;
    const int m0 = my * 128;
    const int n0 = blockIdx.x * 128;

    const int tid  = threadIdx.x;
    const int lane = tid & 31;
    const int wid  = tid >> 5;
    const int wm = (wid & 1) * 64;
    const int wn = (wid >> 1) * 32;
    const int lm = lane >> 2;
    const int lk = lane & 3;

    float acc[4][4][4];
    #pragma unroll
    for (int i = 0; i < 4; i++)
        #pragma unroll
        for (int j = 0; j < 4; j++)
            #pragma unroll
            for (int f = 0; f < 4; f++) acc[i][j][f] = 0.0f;

    auto issue = [&](int k0, int buf) {
        #pragma unroll
        for (int j = 0; j < 2; j++) {
            int idx = tid + j * 256;
            int r = idx >> 2, c = (idx & 3) * 8;
            cp16(&As[buf * HSTG + r * HA_STRIDE + c],
                 A + (size_t)(m0 + r) * K + k0 + c);
        }
        #pragma unroll
        for (int j = 0; j < 2; j++) {
            int idx = tid + j * 256;
            int r = idx >> 2, c = (idx & 3) * 8;
            cp16(&Bs[buf * HSTG + r * HA_STRIDE + c],
                 B + (size_t)(n0 + r) * K + k0 + c);
        }
    };

    issue(0, 0);
    cp_commit();
    cp_wait0();
    __syncthreads();

    const int a_row  = lane & 15;
    const int a_colh = ((lane >> 4) << 3);

    const int T = K >> 5;
    for (int t = 0; t < T; t++) {
        const int buf = t & 1;
        if (t + 1 < T) { issue((t + 1) << 5, buf ^ 1); cp_commit(); }

        #pragma unroll
        for (int ks = 0; ks < 2; ks++) {
            uint32_t a[4][4];
            #pragma unroll
            for (int mi = 0; mi < 4; mi++) {
                uint32_t addr = sm_u32 + 2 * (buf * HSTG +
                    (wm + mi * 16 + a_row) * HA_STRIDE + ks * 16 + a_colh);
                ldsm4(a[mi][0], a[mi][1], a[mi][2], a[mi][3], addr);
            }
            uint32_t b[4][2];
            #pragma unroll
            for (int p = 0; p < 2; p++) {
                uint32_t r0, r1, r2, r3;
                uint32_t addr = sm_u32 + 2 * (2 * HSTG + buf * HSTG +
                    (wn + p * 16 + a_row) * HA_STRIDE + ks * 16 + a_colh);
                ldsm4(r0, r1, r2, r3, addr);
                b[p * 2 + 0][0] = r0; b[p * 2 + 0][1] = r2;
                b[p * 2 + 1][0] = r1; b[p * 2 + 1][1] = r3;
            }
            #pragma unroll
            for (int mi = 0; mi < 4; mi++)
                #pragma unroll
                for (int ni = 0; ni < 4; ni++)
                    mma_f16(acc[mi][ni], a[mi], b[ni]);
        }

        if (t + 1 < T) { cp_wait0(); __syncthreads(); }
    }

    #pragma unroll
    for (int ni = 0; ni < 4; ni++) {
        const int cn = n0 + wn + ni * 8 + lk * 2;
        const float bx = bias[cn], by = bias[cn + 1];
        #pragma unroll
        for (int mi = 0; mi < 4; mi++) {
            const int rm = m0 + wm + mi * 16 + lm;
            *reinterpret_cast<__half2*>(C + (size_t)rm * N + cn) =
                __floats2half2_rn(acc[mi][ni][0] + bx, acc[mi][ni][1] + by);
            *reinterpret_cast<__half2*>(C + (size_t)(rm + 8) * N + cn) =
                __floats2half2_rn(acc[mi][ni][2] + bx, acc[mi][ni][3] + by);
        }
    }
}

// ====== flash attention: fp16 mma, 128 queries/block, 8 warps ==============
#define FA_STR 72   // halfs per smem row (64 + 8 pad); row pitch 144B
// dynamic smem layout (halfs): Q[128*FA_STR] | K[64*FA_STR] | V[64*FA_STR] | P[128*FA_STR]
#define FA_Q_OFF 0
#define FA_K_OFF (128 * FA_STR)
#define FA_V_OFF (192 * FA_STR)
#define FA_P_OFF (256 * FA_STR)
#define FA_SMEM_HALFS (384 * FA_STR)

__global__ __launch_bounds__(256)
void fattn16_kernel(const __half* __restrict__ q,
                    const __half* __restrict__ k,
                    const __half* __restrict__ vt,
                    __half* __restrict__ o) {
    extern __shared__ __half fsm[];
    __half* Qh = fsm + FA_Q_OFF;
    __half* Kh = fsm + FA_K_OFF;
    __half* Vh = fsm + FA_V_OFF;
    __half* Ph = fsm + FA_P_OFF;
    const uint32_t base_u = (uint32_t)__cvta_generic_to_shared(fsm);
    const uint32_t Qu = base_u + 2 * FA_Q_OFF;
    const uint32_t Ku = base_u + 2 * FA_K_OFF;
    const uint32_t Vu = base_u + 2 * FA_V_OFF;
    const uint32_t Pu = base_u + 2 * FA_P_OFF;

    const int bh = blockIdx.y;
    const int b = bh >> 4, hh = bh & 15;
    const int q0 = blockIdx.x * 128;
    const int tid = threadIdx.x, lane = tid & 31, wid = tid >> 5;
    const int lm = lane >> 2, lk = lane & 3;
    const int wm = wid * 16;   // 8 warps -> 128 query rows

    const int a_row  = lane & 15;
    const int a_colh = ((lane >> 4) << 3);

    // load Q tile: 128 rows (scaled by 1/8, exact in fp16)
    {
        const __half2 sc = __floats2half2_rn(0.125f, 0.125f);
        const __half* qg = q + ((size_t)(b * LL + q0)) * DD + hh * DH;
        #pragma unroll
        for (int it = 0; it < 4; it++) {
            int idx = tid + it * 256;          // 0..1023
            int r = idx >> 3, c = (idx & 7) * 8;
            uint4 raw = *reinterpret_cast<const uint4*>(qg + (size_t)r * DD + c);
            __half2* hp = reinterpret_cast<__half2*>(&raw);
            hp[0] = __hmul2(hp[0], sc); hp[1] = __hmul2(hp[1], sc);
            hp[2] = __hmul2(hp[2], sc); hp[3] = __hmul2(hp[3], sc);
            *reinterpret_cast<uint4*>(&Qh[r * FA_STR + c]) = raw;
        }
    }

    float mrow0 = -1e30f, mrow1 = -1e30f, lrow0 = 0.0f, lrow1 = 0.0f;
    float oacc[8][4];
    #pragma unroll
    for (int ni = 0; ni < 8; ni++)
        #pragma unroll
        for (int f = 0; f < 4; f++) oacc[ni][f] = 0.0f;

    const __half* kg = k + ((size_t)(b * NKEY)) * DD + hh * DH;
    const __half* vg = vt + ((size_t)(b * DD + hh * DH)) * NKEY;

    for (int kt = 0; kt < NKEY / 64; kt++) {
        __syncthreads();
        // K and V: 64 rows x 64 halfs each -> 512 uint4 loads each, 256 threads
        #pragma unroll
        for (int it = 0; it < 2; it++) {
            int idx = tid + it * 256;
            int r = idx >> 3, c = (idx & 7) * 8;
            *reinterpret_cast<uint4*>(&Kh[r * FA_STR + c]) =
                *reinterpret_cast<const uint4*>(kg + (size_t)(kt * 64 + r) * DD + c);
            *reinterpret_cast<uint4*>(&Vh[r * FA_STR + c]) =
                *reinterpret_cast<const uint4*>(vg + (size_t)r * NKEY + kt * 64 + c);
        }
        __syncthreads();

        // S = Q @ K^T (fp16 mma)
        float s[8][4];
        #pragma unroll
        for (int ni = 0; ni < 8; ni++)
            #pragma unroll
            for (int f = 0; f < 4; f++) s[ni][f] = 0.0f;

        #pragma unroll
        for (int kk = 0; kk < 4; kk++) {
            uint32_t a[4];
            ldsm4(a[0], a[1], a[2], a[3],
                  Qu + 2 * ((wm + a_row) * FA_STR + kk * 16 + a_colh));
            #pragma unroll
            for (int p = 0; p < 4; p++) {
                uint32_t r0, r1, r2, r3;
                ldsm4(r0, r1, r2, r3,
                      Ku + 2 * ((p * 16 + a_row) * FA_STR + kk * 16 + a_colh));
                uint32_t b0[2] = {r0, r2}, b1[2] = {r1, r3};
                mma_f16(s[p * 2 + 0], a, b0);
                mma_f16(s[p * 2 + 1], a, b1);
            }
        }

        // online softmax (rows lm, lm+8)
        float rm0 = -1e30f, rm1 = -1e30f;
        #pragma unroll
        for (int ni = 0; ni < 8; ni++) {
            rm0 = fmaxf(rm0, fmaxf(s[ni][0], s[ni][1]));
            rm1 = fmaxf(rm1, fmaxf(s[ni][2], s[ni][3]));
        }
        rm0 = fmaxf(rm0, __shfl_xor_sync(0xffffffffu, rm0, 1));
        rm0 = fmaxf(rm0, __shfl_xor_sync(0xffffffffu, rm0, 2));
        rm1 = fmaxf(rm1, __shfl_xor_sync(0xffffffffu, rm1, 1));
        rm1 = fmaxf(rm1, __shfl_xor_sync(0xffffffffu, rm1, 2));

        float nm0 = fmaxf(mrow0, rm0), nm1 = fmaxf(mrow1, rm1);
        float al0 = __expf(mrow0 - nm0), al1 = __expf(mrow1 - nm1);
        mrow0 = nm0; mrow1 = nm1;

        float rs0 = 0.0f, rs1 = 0.0f;
        #pragma unroll
        for (int ni = 0; ni < 8; ni++) {
            s[ni][0] = __expf(s[ni][0] - nm0);
            s[ni][1] = __expf(s[ni][1] - nm0);
            s[ni][2] = __expf(s[ni][2] - nm1);
            s[ni][3] = __expf(s[ni][3] - nm1);
            rs0 += s[ni][0] + s[ni][1];
            rs1 += s[ni][2] + s[ni][3];
        }
        rs0 += __shfl_xor_sync(0xffffffffu, rs0, 1);
        rs0 += __shfl_xor_sync(0xffffffffu, rs0, 2);
        rs1 += __shfl_xor_sync(0xffffffffu, rs1, 1);
        rs1 += __shfl_xor_sync(0xffffffffu, rs1, 2);

        lrow0 = lrow0 * al0 + rs0;
        lrow1 = lrow1 * al1 + rs1;

        #pragma unroll
        for (int ni = 0; ni < 8; ni++) {
            oacc[ni][0] *= al0; oacc[ni][1] *= al0;
            oacc[ni][2] *= al1; oacc[ni][3] *= al1;
        }

        // P -> smem fp16 (own warp rows only)
        #pragma unroll
        for (int ni = 0; ni < 8; ni++) {
            __half* pp = &Ph[(wm + lm) * FA_STR + ni * 8 + 2 * lk];
            *reinterpret_cast<__half2*>(pp) = __floats2half2_rn(s[ni][0], s[ni][1]);
            *reinterpret_cast<__half2*>(pp + 8 * FA_STR) = __floats2half2_rn(s[ni][2], s[ni][3]);
        }
        __syncwarp();

        // O += P @ V (fp16 mma; Vh is [d][j])
        #pragma unroll
        for (int kk = 0; kk < 4; kk++) {
            uint32_t a[4];
            ldsm4(a[0], a[1], a[2], a[3],
                  Pu + 2 * ((wm + a_row) * FA_STR + kk * 16 + a_colh));
            #pragma unroll
            for (int p = 0; p < 4; p++) {
                uint32_t r0, r1, r2, r3;
                ldsm4(r0, r1, r2, r3,
                      Vu + 2 * ((p * 16 + a_row) * FA_STR + kk * 16 + a_colh));
                uint32_t b0[2] = {r0, r2}, b1[2] = {r1, r3};
                mma_f16(oacc[p * 2 + 0], a, b0);
                mma_f16(oacc[p * 2 + 1], a, b1);
            }
        }
    }

    const float inv0 = 1.0f / lrow0, inv1 = 1.0f / lrow1;
    __half* og = o + ((size_t)(b * LL + q0 + wm + lm)) * DD + hh * DH;
    #pragma unroll
    for (int ni = 0; ni < 8; ni++) {
        const int cc = ni * 8 + 2 * lk;
        *reinterpret_cast<__half2*>(og + cc) =
            __floats2half2_rn(oacc[ni][0] * inv0, oacc[ni][1] * inv0);
        *reinterpret_cast<__half2*>(og + (size_t)8 * DD + cc) =
            __floats2half2_rn(oacc[ni][2] * inv1, oacc[ni][3] * inv1);
    }
}

// ---------------- driver ----------------
extern "C" void kernel_launch(void* const* d_in, const int* in_sizes, int n_in,
                              void* d_out, int out_size) {
    const float* x        = (const float*)d_in[0];
    const float* gumbel_u = (const float*)d_in[1];
    const float* ln1_g    = (const float*)d_in[2];
    const float* ln1_b    = (const float*)d_in[3];
    const float* ln2_g    = (const float*)d_in[4];
    const float* ln2_b    = (const float*)d_in[5];
    const float* w_sal    = (const float*)d_in[6];
    const float* b_sal    = (const float*)d_in[7];
    const float* ipw      = (const float*)d_in[8];
    const float* ipb      = (const float*)d_in[9];
    const float* opw      = (const float*)d_in[10];
    const float* opb      = (const float*)d_in[11];
    const float* w_fc     = (const float*)d_in[12];
    const float* b_fc     = (const float*)d_in[13];
    const float* w_proj   = (const float*)d_in[14];
    const float* b_proj   = (const float*)d_in[15];
    float* out = (float*)d_out;

    void* p;
    cudaGetSymbolAddress(&p, g_h);      float*  h     = (float*)p;
    cudaGetSymbolAddress(&p, g_h16);    __half* h16   = (__half*)p;
    cudaGetSymbolAddress(&p, g_kv16);   __half* kv16  = (__half*)p;
    cudaGetSymbolAddress(&p, g_q16);    __half* q16   = (__half*)p;
    cudaGetSymbolAddress(&p, g_k16);    __half* k16   = (__half*)p;
    cudaGetSymbolAddress(&p, g_v16);    __half* v16   = (__half*)p;
    cudaGetSymbolAddress(&p, g_vt16);   __half* vt16  = (__half*)p;
    cudaGetSymbolAddress(&p, g_att16);  __half* att16 = (__half*)p;
    cudaGetSymbolAddress(&p, g_x2);     float*  x2    = (float*)p;
    cudaGetSymbolAddress(&p, g_h2_16);  __half* h2_16 = (__half*)p;
    cudaGetSymbolAddress(&p, g_ff16);   __half* ff16  = (__half*)p;
    cudaGetSymbolAddress(&p, g_w16);    __half* w16   = (__half*)p;
    cudaGetSymbolAddress(&p, g_logits); float*  logi  = (float*)p;

    const int FA_SMEM = FA_SMEM_HALFS * 2;   // 55296 bytes
    cudaFuncSetAttribute(fattn16_kernel, cudaFuncAttributeMaxDynamicSharedMemorySize, FA_SMEM);

    // 0. weight prep: fused fp16 conversion
    f2h_all_kernel<<<(W16_TOTAL / 4 + 255) / 256, 256>>>(ipw, opw, w_fc, w_proj, w16);
    // 1. LN1
    ln_kernel<true, true><<<NTOK, 256>>>(x, ln1_g, ln1_b, h, h16);
    // 2. saliency logits
    logits_kernel<<<BB * NB, 256>>>(h, w_sal, b_sal, logi);
    // 3+4. fused selection + gather -> kv16
    gather_kernel<<<MKV, 256>>>(h, logi, gumbel_u, kv16);
    // 5. fused QKV projection (fp16 out)
    hgemm_qkv<<<dim3(DD / 128, 64 + 20 + 20), 256>>>(h16, kv16, w16 + W16_IPW, ipb,
                                                     q16, k16, v16);
    // 5b. V transpose (fp16)
    vtrans16_kernel<<<dim3(NKEY / 32, DD / 32, BB), dim3(32, 8)>>>(v16, vt16);
    // 6. attention (fp16 mma flash, 128 q/block)
    fattn16_kernel<<<dim3(LL / 128, BB * NH), 256, FA_SMEM>>>(q16, k16, vt16, att16);
    // 7. out proj + residual (fp32 out)
    hgemm<true, false, true, false><<<dim3(DD / 128, NTOK / 128), 256>>>(
        att16, w16 + W16_OPW, opb, x, x2, NTOK, DD, DD);
    // 8. LN2 (fp16 out)
    ln_kernel<false, true><<<NTOK, 256>>>(x2, ln2_g, ln2_b, nullptr, h2_16);
    // 9. FFN up + gelu (NN, fp16 out)
    hgemm<false, true, false, true><<<dim3(DFFN / 128, NTOK / 128), 256>>>(
        h2_16, w16 + W16_WFC, b_fc, nullptr, ff16, NTOK, DFFN, DD);
    // 10. FFN down + residual (NN, fp32 out) -> out
    hgemm<false, false, true, false><<<dim3(DD / 128, NTOK / 128), 256>>>(
        ff16, w16 + W16_WPROJ, b_proj, x2, out, NTOK, DD, DFFN);
}